// round 4
// baseline (speedup 1.0000x reference)
#include <cuda_runtime.h>
#include <cuda_bf16.h>
#include <math.h>
#include <stdint.h>

// ---------------- problem constants ----------------
#define B_   4
#define S1_  768
#define S2_  64
#define S_   832
#define D0_  2048
#define F0_  16384
#define D1_  1024
#define F1_  4096
#define H_   8
#define HD_  256
#define EPS_ 1e-6f
#define MASK_VAL_ -1000000000.0f

// ---------------- scratch (device globals; no allocation allowed) ----------------
__device__ float g_h0[B_*S1_*D0_];
__device__ float g_h1[B_*S2_*D1_];
__device__ float g_mod_in[B_*2*D1_];
__device__ float g_mod_post[B_*2*D1_];
__device__ float g_q[(size_t)B_*S_*H_*HD_];
__device__ float g_k[B_*S_*HD_];
__device__ float g_v[B_*S_*HD_];
__device__ float g_scores[(size_t)B_*H_*S_*S_];
__device__ float g_att[(size_t)B_*S_*H_*HD_];
__device__ float g_r0[B_*S1_*D0_];
__device__ float g_gu0[(size_t)B_*S1_*F0_];
__device__ float g_r1[B_*S2_*D1_];
__device__ float g_y1[B_*S2_*D1_];
__device__ float g_gu1[B_*S2_*F1_];
__device__ int   g_pos[B_*S_];
__device__ int   g_cs[B_*S_];

// split-bf16 operands (activations A' = [hi|hi|lo], weights B' = [hi|lo|hi] along K)
__device__ __nv_bfloat16 g_h03 [(size_t)3072*3*2048];
__device__ __nv_bfloat16 g_att3[(size_t)3072*3*2048];
__device__ __nv_bfloat16 g_y03 [(size_t)3072*3*2048];
__device__ __nv_bfloat16 g_gu03[(size_t)3072*3*16384];
__device__ __nv_bfloat16 g_wq03[(size_t)2048*3*2048];
__device__ __nv_bfloat16 g_wo03[(size_t)2048*3*2048];
__device__ __nv_bfloat16 g_wg03[(size_t)16384*3*2048];
__device__ __nv_bfloat16 g_wu03[(size_t)16384*3*2048];
__device__ __nv_bfloat16 g_wd03[(size_t)2048*3*16384];

// ---------------- small helpers ----------------
__device__ __forceinline__ float gelu_tanh(float x) {
    float x3 = x * x * x;
    return 0.5f * x * (1.0f + tanhf(0.79788456080286535588f * (x + 0.044715f * x3)));
}

__device__ __forceinline__ uint32_t smem_u32(const void* p) {
    uint32_t a;
    asm("{ .reg .u64 t; cvta.to.shared.u64 t, %1; cvt.u32.u64 %0, t; }" : "=r"(a) : "l"(p));
    return a;
}

#define CP_ASYNC16(sm, gm) \
    asm volatile("cp.async.cg.shared.global [%0], [%1], 16;" :: "r"(sm), "l"(gm))
#define CP_COMMIT() asm volatile("cp.async.commit_group;")
#define CP_WAIT(n)  asm volatile("cp.async.wait_group %0;" :: "n"(n))

__device__ __forceinline__ void ldsm_x4(uint32_t* r, uint32_t addr) {
    asm volatile("ldmatrix.sync.aligned.m8n8.x4.shared.b16 {%0,%1,%2,%3}, [%4];"
                 : "=r"(r[0]), "=r"(r[1]), "=r"(r[2]), "=r"(r[3]) : "r"(addr));
}
__device__ __forceinline__ void mma_bf16(float* c, const uint32_t* a, uint32_t b0, uint32_t b1) {
    asm volatile("mma.sync.aligned.m16n8k16.row.col.f32.bf16.bf16.f32 "
                 "{%0,%1,%2,%3}, {%4,%5,%6,%7}, {%8,%9}, {%0,%1,%2,%3};"
                 : "+f"(c[0]), "+f"(c[1]), "+f"(c[2]), "+f"(c[3])
                 : "r"(a[0]), "r"(a[1]), "r"(a[2]), "r"(a[3]), "r"(b0), "r"(b1));
}

// swizzled chunk address within a [rows x 64bf16] tile: 8 x 16B chunks per row, chunk^(row&7)
__device__ __forceinline__ uint32_t sw_addr(uint32_t base, int row, int chunk) {
    return base + (uint32_t)(((row << 3) + (chunk ^ (row & 7))) << 4);
}

// ---------------- epilogue modes ----------------
#define EPI_NONE       0
#define EPI_SCORES     1
#define EPI_RES        2
#define EPI_RES_GATE   3
#define EPI_GELUMUL    4
#define EPI_GELUMUL_SP 5   // v = gelu(aux)*v, write bf16 triple [hi|hi|lo] to C3 (no fp32 store)

// ---------------- tensor-core split-bf16 GEMM: C[M,N] = A'[M,Kp] * B't[N,Kp]^T ----------------
// 128x256 CTA tile, 8 warps (2x4), warp tile 64x64, BK=64, 3-stage cp.async pipeline.
struct TcP {
    const __nv_bfloat16* A;   // [M, Kp] row-major
    const __nv_bfloat16* Bt;  // [N, Kp] row-major (B^T)
    float* C;
    __nv_bfloat16* C3;        // triple output (EPI_GELUMUL_SP)
    const float* aux;         // logical [M, N] row-major
    int M, N, Kp;
    int epi;
    int rpb, obatch, ldc;     // out row = (r/rpb)*obatch + r%rpb
    long zsA, zsB, zsC, zsAux; int zdiv;   // batching (z over grid.z)
};

#define TSTAGE_BYTES 49152       // 16KB A + 32KB B
#define TSMEM (3 * TSTAGE_BYTES) // 147456

__global__ __launch_bounds__(256, 1) void tc_gemm_kernel(TcP p) {
    extern __shared__ char dsm[];
    uint32_t sbase = smem_u32(dsm);

    int tid  = threadIdx.x;
    int lane = tid & 31;
    int wid  = tid >> 5;
    int wm = wid >> 2;          // 0..1
    int wn = wid & 3;           // 0..3

    int m0 = blockIdx.y * 128;
    int n0 = blockIdx.x * 256;
    int z  = blockIdx.z;

    const __nv_bfloat16* Ab = p.A  + (size_t)z * p.zsA;
    const __nv_bfloat16* Bb = p.Bt + (size_t)(z / p.zdiv) * p.zsB;
    float* Cz = p.C + (size_t)z * p.zsC;
    const float* auxz = p.aux + (size_t)z * p.zsAux;

    int kc = tid & 7;
    int rb = tid >> 3;          // 0..31

    float acc[4][8][4];
    #pragma unroll
    for (int i = 0; i < 4; i++)
        #pragma unroll
        for (int j = 0; j < 8; j++)
            #pragma unroll
            for (int e = 0; e < 4; e++) acc[i][j][e] = 0.f;

    int nIter = p.Kp >> 6;

    auto issue = [&](int it) {
        int st = it % 3;
        uint32_t sa = sbase + st * TSTAGE_BYTES;
        uint32_t sb = sa + 16384;
        int k0 = it << 6;
        #pragma unroll
        for (int i = 0; i < 4; i++) {
            int row = rb + i * 32;
            int grow = m0 + row; if (grow >= p.M) grow = p.M - 1;
            CP_ASYNC16(sw_addr(sa, row, kc), Ab + (size_t)grow * p.Kp + k0 + kc * 8);
        }
        #pragma unroll
        for (int i = 0; i < 8; i++) {
            int row = rb + i * 32;
            int grow = n0 + row; if (grow >= p.N) grow = p.N - 1;
            CP_ASYNC16(sw_addr(sb, row, kc), Bb + (size_t)grow * p.Kp + k0 + kc * 8);
        }
        CP_COMMIT();
    };

    issue(0);
    if (nIter > 1) issue(1);

    int grp = lane >> 3;
    int lr  = lane & 7;

    for (int it = 0; it < nIter; it++) {
        if (it == nIter - 1) { CP_WAIT(0); } else { CP_WAIT(1); }
        __syncthreads();

        int st = it % 3;
        uint32_t sa = sbase + st * TSTAGE_BYTES;
        uint32_t sb = sa + 16384;

        #pragma unroll
        for (int kb = 0; kb < 4; kb++) {
            int chA = 2 * kb + (grp >> 1);
            uint32_t a[4][4];
            #pragma unroll
            for (int mi = 0; mi < 4; mi++)
                ldsm_x4(a[mi], sw_addr(sa, wm * 64 + mi * 16 + (grp & 1) * 8 + lr, chA));
            uint32_t bb[4][4];
            #pragma unroll
            for (int ni = 0; ni < 4; ni++)
                ldsm_x4(bb[ni], sw_addr(sb, wn * 64 + ni * 16 + (grp & 1) * 8 + lr, chA));
            #pragma unroll
            for (int mi = 0; mi < 4; mi++)
                #pragma unroll
                for (int nt = 0; nt < 8; nt++)
                    mma_bf16(acc[mi][nt], a[mi], bb[nt >> 1][nt & 1], bb[nt >> 1][(nt & 1) + 2]);
        }
        if (it + 2 < nIter) issue(it + 2);
    }

    // ---- epilogue (direct stores) ----
    int qrow = lane >> 2;
    int qcol = (lane & 3) * 2;
    #pragma unroll
    for (int mi = 0; mi < 4; mi++) {
        #pragma unroll
        for (int half = 0; half < 2; half++) {
            int r = m0 + wm * 64 + mi * 16 + half * 8 + qrow;
            if (r >= p.M) continue;
            int orow = (r / p.rpb) * p.obatch + (r % p.rpb);
            #pragma unroll
            for (int nt = 0; nt < 8; nt++) {
                int col = n0 + wn * 64 + nt * 8 + qcol;
                if (col >= p.N) continue;
                float v0 = acc[mi][nt][half * 2 + 0];
                float v1 = acc[mi][nt][half * 2 + 1];
                if (p.epi == EPI_RES) {
                    float2 ax = *(const float2*)&auxz[(size_t)r * p.N + col];
                    v0 += ax.x; v1 += ax.y;
                } else if (p.epi == EPI_GELUMUL) {
                    float2 ax = *(const float2*)&auxz[(size_t)r * p.N + col];
                    v0 = gelu_tanh(ax.x) * v0;
                    v1 = gelu_tanh(ax.y) * v1;
                } else if (p.epi == EPI_GELUMUL_SP) {
                    float2 ax = *(const float2*)&auxz[(size_t)r * p.N + col];
                    v0 = gelu_tanh(ax.x) * v0;
                    v1 = gelu_tanh(ax.y) * v1;
                    __nv_bfloat16 h0 = __float2bfloat16(v0);
                    __nv_bfloat16 h1 = __float2bfloat16(v1);
                    __nv_bfloat162 hh; hh.x = h0; hh.y = h1;
                    __nv_bfloat162 ll;
                    ll.x = __float2bfloat16(v0 - __bfloat162float(h0));
                    ll.y = __float2bfloat16(v1 - __bfloat162float(h1));
                    size_t base = (size_t)orow * 3 * p.N;
                    *(__nv_bfloat162*)&p.C3[base + col]             = hh;
                    *(__nv_bfloat162*)&p.C3[base + p.N + col]       = hh;
                    *(__nv_bfloat162*)&p.C3[base + 2 * p.N + col]   = ll;
                    continue;
                }
                *(float2*)&Cz[(size_t)orow * p.ldc + col] = make_float2(v0, v1);
            }
        }
    }
}

// ---------------- split conversion kernels ----------------
// activations: out[r, 0..K)=hi, [K..2K)=hi, [2K..3K)=lo ; in row = (r/rpb)*ibatch + r%rpb
__global__ void split_act_kernel(const float* __restrict__ in, __nv_bfloat16* __restrict__ out,
                                 int M, int K, int rpb, int ibatch) {
    size_t idx = blockIdx.x * (size_t)blockDim.x + threadIdx.x;
    size_t total = (size_t)M * K;
    if (idx >= total) return;
    int r = (int)(idx / K), k = (int)(idx % K);
    int ir = (r / rpb) * ibatch + (r % rpb);
    float v = in[(size_t)ir * K + k];
    __nv_bfloat16 hi = __float2bfloat16(v);
    __nv_bfloat16 lo = __float2bfloat16(v - __bfloat162float(hi));
    __nv_bfloat16* o = out + (size_t)r * 3 * K;
    o[k] = hi; o[K + k] = hi; o[2 * K + k] = lo;
}

// weights W[K,N] -> out[N, 3K]: [0..K)=hi, [K..2K)=lo, [2K..3K)=hi (transposed)
__global__ void tsplit_kernel(const float* __restrict__ W, __nv_bfloat16* __restrict__ out,
                              int K, int N) {
    __shared__ float t[32][33];
    int k0 = blockIdx.y * 32, n0 = blockIdx.x * 32;
    int tx = threadIdx.x, ty = threadIdx.y;   // 32 x 8
    #pragma unroll
    for (int i = 0; i < 4; i++)
        t[ty + i * 8][tx] = W[(size_t)(k0 + ty + i * 8) * N + n0 + tx];
    __syncthreads();
    #pragma unroll
    for (int i = 0; i < 4; i++) {
        int n = n0 + ty + i * 8;
        int k = k0 + tx;
        float v = t[tx][ty + i * 8];
        __nv_bfloat16 hi = __float2bfloat16(v);
        __nv_bfloat16 lo = __float2bfloat16(v - __bfloat162float(hi));
        __nv_bfloat16* o = out + (size_t)n * 3 * K;
        o[k] = hi; o[K + k] = lo; o[2 * K + k] = hi;
    }
}

// ---------------- legacy FFMA batched SGEMM (small ops / attention) ----------------
struct GemmP {
    const float* A; const float* B; float* C;
    int M, N, K, lda, ldb, ldc;
    long sA1, sA2, sB1, sB2, sC1, sC2;
    int zdiv;
    int transB;
    int epi;
    const float* aux; long sAux;
    const float* gvec; int gvecStride;
    const int* cs; const int* pad; int maskStride;
    float scale;
};

#define BM 128
#define BN 128
#define BK 8
#define TM 8
#define TN 8

__global__ __launch_bounds__(256) void gemm_kernel(GemmP p) {
    __shared__ float As[BK][BM];
    __shared__ float Bs[BK][BN];

    int z  = blockIdx.z;
    int zb = z / p.zdiv;
    int zr = z % p.zdiv;

    const float* A = p.A + (long)zb * p.sA1 + (long)zr * p.sA2;
    const float* Bm = p.B + (long)zb * p.sB1 + (long)zr * p.sB2;
    float* C = p.C + (long)zb * p.sC1 + (long)zr * p.sC2;

    int rowBase = blockIdx.y * BM;
    int colBase = blockIdx.x * BN;
    int tid = threadIdx.x;
    int tx = tid % 16;
    int ty = tid / 16;

    float acc[TM][TN];
    #pragma unroll
    for (int i = 0; i < TM; i++)
        #pragma unroll
        for (int j = 0; j < TN; j++) acc[i][j] = 0.0f;

    int aRow = tid >> 1;
    int aCol = (tid & 1) * 4;
    int bRow = tid >> 5;
    int bCol = (tid & 31) * 4;

    for (int k0 = 0; k0 < p.K; k0 += BK) {
        {
            int gr = rowBase + aRow;
            float4 av = make_float4(0.f, 0.f, 0.f, 0.f);
            if (gr < p.M)
                av = *(const float4*)&A[(long)gr * p.lda + k0 + aCol];
            As[aCol + 0][aRow] = av.x;
            As[aCol + 1][aRow] = av.y;
            As[aCol + 2][aRow] = av.z;
            As[aCol + 3][aRow] = av.w;
        }
        if (!p.transB) {
            int gk = k0 + bRow;
            int gc = colBase + bCol;
            if (gc + 3 < p.N) {
                float4 bv = *(const float4*)&Bm[(long)gk * p.ldb + gc];
                Bs[bRow][bCol + 0] = bv.x;
                Bs[bRow][bCol + 1] = bv.y;
                Bs[bRow][bCol + 2] = bv.z;
                Bs[bRow][bCol + 3] = bv.w;
            } else {
                #pragma unroll
                for (int i = 0; i < 4; i++)
                    Bs[bRow][bCol + i] = (gc + i < p.N) ? Bm[(long)gk * p.ldb + gc + i] : 0.f;
            }
        } else {
            int n  = tid >> 1;
            int kk = (tid & 1) * 4;
            int gn = colBase + n;
            float4 bv = make_float4(0.f, 0.f, 0.f, 0.f);
            if (gn < p.N)
                bv = *(const float4*)&Bm[(long)gn * p.ldb + k0 + kk];
            Bs[kk + 0][n] = bv.x;
            Bs[kk + 1][n] = bv.y;
            Bs[kk + 2][n] = bv.z;
            Bs[kk + 3][n] = bv.w;
        }
        __syncthreads();

        #pragma unroll
        for (int k = 0; k < BK; k++) {
            float a[TM], b[TN];
            float4 a0 = *(const float4*)&As[k][ty * TM];
            float4 a1 = *(const float4*)&As[k][ty * TM + 4];
            a[0]=a0.x; a[1]=a0.y; a[2]=a0.z; a[3]=a0.w;
            a[4]=a1.x; a[5]=a1.y; a[6]=a1.z; a[7]=a1.w;
            float4 b0 = *(const float4*)&Bs[k][tx * TN];
            float4 b1 = *(const float4*)&Bs[k][tx * TN + 4];
            b[0]=b0.x; b[1]=b0.y; b[2]=b0.z; b[3]=b0.w;
            b[4]=b1.x; b[5]=b1.y; b[6]=b1.z; b[7]=b1.w;
            #pragma unroll
            for (int i = 0; i < TM; i++)
                #pragma unroll
                for (int j = 0; j < TN; j++)
                    acc[i][j] += a[i] * b[j];
        }
        __syncthreads();
    }

    const int* csb  = p.cs  ? p.cs  + (long)zb * p.maskStride : nullptr;
    const int* padb = p.pad ? p.pad + (long)zb * p.maskStride : nullptr;
    long auxOff = (long)zb * p.sAux;

    #pragma unroll
    for (int i = 0; i < TM; i++) {
        int row = rowBase + ty * TM + i;
        if (row >= p.M) continue;
        #pragma unroll
        for (int j = 0; j < TN; j++) {
            int col = colBase + tx * TN + j;
            if (col >= p.N) continue;
            long idx = (long)row * p.ldc + col;
            float v = acc[i][j];
            if (p.epi == EPI_SCORES) {
                bool ok = (csb[col] <= csb[row]) && (padb[row] != 0) && (padb[col] != 0);
                v = ok ? v * p.scale : MASK_VAL_;
            } else if (p.epi == EPI_RES) {
                v += p.aux[auxOff + idx];
            } else if (p.epi == EPI_RES_GATE) {
                v = p.aux[auxOff + idx] + p.gvec[(long)zb * p.gvecStride + col] * v;
            } else if (p.epi == EPI_GELUMUL) {
                v = gelu_tanh(p.aux[auxOff + idx]) * v;
            }
            C[idx] = v;
        }
    }
}

// ---------------- mod GEMV ----------------
__global__ void mod_kernel(const float* __restrict__ cond, const float* __restrict__ W,
                           const float* __restrict__ bias, float* __restrict__ out,
                           int D, int N) {
    int j = blockIdx.x * blockDim.x + threadIdx.x;
    int b = blockIdx.y;
    if (j >= N) return;
    float s = bias[j];
    const float* c = cond + (long)b * D;
    for (int k = 0; k < D; k++)
        s += c[k] * W[(long)k * N + j];
    out[(long)b * N + j] = s;
}

// ---------------- prefix scans ----------------
__global__ void scan_kernel(const int* __restrict__ pad, const int* __restrict__ att,
                            int* __restrict__ pos, int* __restrict__ cs) {
    int b = threadIdx.x;
    if (b >= B_) return;
    int cp = 0, ca = 0;
    for (int s = 0; s < S_; s++) {
        cp += pad[b * S_ + s];
        ca += att[b * S_ + s];
        pos[b * S_ + s] = cp - 1;
        cs[b * S_ + s] = ca;
    }
}

// ---------------- RMSNorm (optionally writes fp32 out and/or bf16 triple) ----------------
__global__ void rmsnorm_kernel(const float* __restrict__ x, float* __restrict__ outF,
                               __nv_bfloat16* __restrict__ out3,
                               const float* __restrict__ w, int wStride,
                               int D, int rowsPerBatch) {
    long row = blockIdx.x;
    int b = (int)(row / rowsPerBatch);
    const float* xp = x + row * (long)D;
    float ss = 0.f;
    for (int i = threadIdx.x; i < D; i += blockDim.x) {
        float v = xp[i];
        ss += v * v;
    }
    __shared__ float red[256];
    red[threadIdx.x] = ss;
    __syncthreads();
    for (int s = 128; s > 0; s >>= 1) {
        if (threadIdx.x < s) red[threadIdx.x] += red[threadIdx.x + s];
        __syncthreads();
    }
    float r = rsqrtf(red[0] / (float)D + EPS_);
    const float* wp = w + (long)b * wStride;
    float* opF = outF ? outF + row * (long)D : nullptr;
    __nv_bfloat16* op3 = out3 ? out3 + row * (long)(3 * D) : nullptr;
    for (int i = threadIdx.x; i < D; i += blockDim.x) {
        float v = xp[i] * r * (1.0f + wp[i]);
        if (opF) opF[i] = v;
        if (op3) {
            __nv_bfloat16 hi = __float2bfloat16(v);
            __nv_bfloat16 lo = __float2bfloat16(v - __bfloat162float(hi));
            op3[i] = hi; op3[D + i] = hi; op3[2 * D + i] = lo;
        }
    }
}

// ---------------- RoPE ----------------
__global__ void rope_kernel(float* __restrict__ X, const int* __restrict__ pos, int nH, long total) {
    long idx = blockIdx.x * (long)blockDim.x + threadIdx.x;
    if (idx >= total) return;
    int i = (int)(idx & 127);
    long t = idx >> 7;
    int h = (int)(t % nH); t /= nH;
    int s = (int)(t % S_);
    int b = (int)(t / S_);
    float p = (float)pos[b * S_ + s];
    float inv = expf(-((float)i / 128.0f) * 9.210340371976184f);
    float f = p * inv;
    float c = cosf(f), sn = sinf(f);
    float* base = X + ((long)(b * S_ + s) * nH + h) * (long)HD_;
    float x1 = base[i];
    float x2 = base[i + 128];
    base[i]       = x1 * c - x2 * sn;
    base[i + 128] = x2 * c + x1 * sn;
}

// ---------------- row softmax ----------------
__global__ void softmax_kernel(float* __restrict__ scores) {
    float* p = scores + (long)blockIdx.x * S_;
    __shared__ float red[256];
    int tid = threadIdx.x;

    float m = -3.4e38f;
    for (int i = tid; i < S_; i += 256) m = fmaxf(m, p[i]);
    red[tid] = m;
    __syncthreads();
    for (int s = 128; s > 0; s >>= 1) {
        if (tid < s) red[tid] = fmaxf(red[tid], red[tid + s]);
        __syncthreads();
    }
    m = red[0];
    __syncthreads();

    float sum = 0.f;
    for (int i = tid; i < S_; i += 256) {
        float e = expf(p[i] - m);
        p[i] = e;
        sum += e;
    }
    red[tid] = sum;
    __syncthreads();
    for (int s = 128; s > 0; s >>= 1) {
        if (tid < s) red[tid] += red[tid + s];
        __syncthreads();
    }
    float inv = 1.0f / red[0];
    for (int i = tid; i < S_; i += 256) p[i] *= inv;
}

// ---------------- host helpers ----------------
static void launch_gemm(const float* A, const float* Bm, float* C,
                        int M, int N, int K, int lda, int ldb, int ldc,
                        int batches, long sA1, long sA2, long sB1, long sB2,
                        long sC1, long sC2, int zdiv, bool transB, int epi,
                        const float* aux = nullptr, long sAux = 0,
                        const float* gvec = nullptr, int gvecStride = 0,
                        const int* cs = nullptr, const int* pad = nullptr,
                        int maskStride = 0, float scale = 1.0f) {
    GemmP p;
    p.A = A; p.B = Bm; p.C = C;
    p.M = M; p.N = N; p.K = K; p.lda = lda; p.ldb = ldb; p.ldc = ldc;
    p.sA1 = sA1; p.sA2 = sA2; p.sB1 = sB1; p.sB2 = sB2; p.sC1 = sC1; p.sC2 = sC2;
    p.zdiv = zdiv; p.transB = transB ? 1 : 0; p.epi = epi;
    p.aux = aux; p.sAux = sAux; p.gvec = gvec; p.gvecStride = gvecStride;
    p.cs = cs; p.pad = pad; p.maskStride = maskStride; p.scale = scale;
    dim3 grid((N + BN - 1) / BN, (M + BM - 1) / BM, batches);
    gemm_kernel<<<grid, 256>>>(p);
}

static void launch_tc(const __nv_bfloat16* A, const __nv_bfloat16* Bt, float* C,
                      int M, int N, int Kp, int epi, const float* aux,
                      int rpb, int obatch, int ldc,
                      __nv_bfloat16* C3 = nullptr) {
    cudaFuncSetAttribute(tc_gemm_kernel, cudaFuncAttributeMaxDynamicSharedMemorySize, TSMEM);
    TcP p;
    p.A = A; p.Bt = Bt; p.C = C; p.C3 = C3; p.aux = aux;
    p.M = M; p.N = N; p.Kp = Kp; p.epi = epi;
    p.rpb = rpb; p.obatch = obatch; p.ldc = ldc;
    p.zsA = 0; p.zsB = 0; p.zsC = 0; p.zsAux = 0; p.zdiv = 1;
    dim3 grid((N + 255) / 256, (M + 127) / 128, 1);
    tc_gemm_kernel<<<grid, 256, TSMEM>>>(p);
}

static void launch_split(const float* in, __nv_bfloat16* out, int M, int K, int rpb, int ibatch) {
    size_t total = (size_t)M * K;
    split_act_kernel<<<(unsigned)((total + 255) / 256), 256>>>(in, out, M, K, rpb, ibatch);
}

static void launch_tsplit(const float* W, __nv_bfloat16* out, int K, int N) {
    dim3 grid(N / 32, K / 32);
    tsplit_kernel<<<grid, dim3(32, 8)>>>(W, out, K, N);
}

extern "C" void kernel_launch(void* const* d_in, const int* in_sizes, int n_in,
                              void* d_out, int out_size) {
    const float* x0         = (const float*)d_in[0];
    const float* x1         = (const float*)d_in[1];
    const float* cond1      = (const float*)d_in[2];
    const float* w_q0       = (const float*)d_in[3];
    const float* w_k0       = (const float*)d_in[4];
    const float* w_v0       = (const float*)d_in[5];
    const float* w_o0       = (const float*)d_in[6];
    const float* norm1_w0   = (const float*)d_in[7];
    const float* norm2_w0   = (const float*)d_in[8];
    const float* w_gate0    = (const float*)d_in[9];
    const float* w_up0      = (const float*)d_in[10];
    const float* w_down0    = (const float*)d_in[11];
    const float* w_q1       = (const float*)d_in[12];
    const float* w_k1       = (const float*)d_in[13];
    const float* w_v1       = (const float*)d_in[14];
    const float* w_o1       = (const float*)d_in[15];
    const float* ada_in_w1  = (const float*)d_in[16];
    const float* ada_in_b1  = (const float*)d_in[17];
    const float* ada_post_w1= (const float*)d_in[18];
    const float* ada_post_b1= (const float*)d_in[19];
    const float* w_gate1    = (const float*)d_in[20];
    const float* w_up1      = (const float*)d_in[21];
    const float* w_down1    = (const float*)d_in[22];
    const int*   pad_masks  = (const int*)d_in[23];
    const int*   att_masks  = (const int*)d_in[24];

    float* out0 = (float*)d_out;
    float* out1 = out0 + (size_t)B_ * S1_ * D0_;

    float *h0, *h1, *modin, *modpost, *q, *k, *v, *scores, *att, *r0, *gu0, *r1, *y1, *gu1;
    int *pos, *cs;
    __nv_bfloat16 *h03, *att3, *y03, *gu03, *wq03, *wo03, *wg03, *wu03, *wd03;
    cudaGetSymbolAddress((void**)&h0, g_h0);
    cudaGetSymbolAddress((void**)&h1, g_h1);
    cudaGetSymbolAddress((void**)&modin, g_mod_in);
    cudaGetSymbolAddress((void**)&modpost, g_mod_post);
    cudaGetSymbolAddress((void**)&q, g_q);
    cudaGetSymbolAddress((void**)&k, g_k);
    cudaGetSymbolAddress((void**)&v, g_v);
    cudaGetSymbolAddress((void**)&scores, g_scores);
    cudaGetSymbolAddress((void**)&att, g_att);
    cudaGetSymbolAddress((void**)&r0, g_r0);
    cudaGetSymbolAddress((void**)&gu0, g_gu0);
    cudaGetSymbolAddress((void**)&r1, g_r1);
    cudaGetSymbolAddress((void**)&y1, g_y1);
    cudaGetSymbolAddress((void**)&gu1, g_gu1);
    cudaGetSymbolAddress((void**)&pos, g_pos);
    cudaGetSymbolAddress((void**)&cs, g_cs);
    cudaGetSymbolAddress((void**)&h03, g_h03);
    cudaGetSymbolAddress((void**)&att3, g_att3);
    cudaGetSymbolAddress((void**)&y03, g_y03);
    cudaGetSymbolAddress((void**)&gu03, g_gu03);
    cudaGetSymbolAddress((void**)&wq03, g_wq03);
    cudaGetSymbolAddress((void**)&wo03, g_wo03);
    cudaGetSymbolAddress((void**)&wg03, g_wg03);
    cudaGetSymbolAddress((void**)&wu03, g_wu03);
    cudaGetSymbolAddress((void**)&wd03, g_wd03);

    const int M0 = B_ * S1_;   // 3072

    // weight prep (split + transpose to [N, 3K])
    launch_tsplit(w_q0,    wq03, D0_, H_ * HD_);
    launch_tsplit(w_o0,    wo03, H_ * HD_, D0_);
    launch_tsplit(w_gate0, wg03, D0_, F0_);
    launch_tsplit(w_up0,   wu03, D0_, F0_);
    launch_tsplit(w_down0, wd03, F0_, D0_);

    // 1) adaLN modulation
    {
        dim3 mg((2 * D1_ + 255) / 256, B_);
        mod_kernel<<<mg, 256>>>(cond1, ada_in_w1,  ada_in_b1,  modin,   D1_, 2 * D1_);
        mod_kernel<<<mg, 256>>>(cond1, ada_post_w1, ada_post_b1, modpost, D1_, 2 * D1_);
    }

    // 2) scans
    scan_kernel<<<1, 32>>>(pad_masks, att_masks, pos, cs);

    // 3) input norms (h0 fp32 for k/v FFMA + h03 triple for TC)
    rmsnorm_kernel<<<B_ * S1_, 256>>>(x0, h0, h03, norm1_w0, 0, D0_, S1_);
    rmsnorm_kernel<<<B_ * S2_, 256>>>(x1, h1, nullptr, modin, 2 * D1_, D1_, S2_);

    // 4) QKV: q0 via TC (row remap into S=832 buffer), rest FFMA
    launch_tc(h03, wq03, q, M0, H_ * HD_, 3 * D0_, EPI_NONE, nullptr, S1_, S_ * H_ * HD_ / (H_ * HD_) * (H_ * HD_) == 0 ? S_ : S_, H_ * HD_);
    // NOTE: obatch semantics: orow = (r/rpb)*obatch + r%rpb ; for q0: rpb=S1_, obatch=S_
    launch_gemm(h0, w_k0, k, S1_, HD_, D0_, D0_, HD_, HD_,
                B_, (long)S1_*D0_, 0, 0, 0, (long)S_*HD_, 0, 1, false, EPI_NONE);
    launch_gemm(h0, w_v0, v, S1_, HD_, D0_, D0_, HD_, HD_,
                B_, (long)S1_*D0_, 0, 0, 0, (long)S_*HD_, 0, 1, false, EPI_NONE);
    launch_gemm(h1, w_q1, q + (long)S1_*H_*HD_, S2_, H_*HD_, D1_, D1_, H_*HD_, H_*HD_,
                B_, (long)S2_*D1_, 0, 0, 0, (long)S_*H_*HD_, 0, 1, false, EPI_NONE);
    launch_gemm(h1, w_k1, k + (long)S1_*HD_, S2_, HD_, D1_, D1_, HD_, HD_,
                B_, (long)S2_*D1_, 0, 0, 0, (long)S_*HD_, 0, 1, false, EPI_NONE);
    launch_gemm(h1, w_v1, v + (long)S1_*HD_, S2_, HD_, D1_, D1_, HD_, HD_,
                B_, (long)S2_*D1_, 0, 0, 0, (long)S_*HD_, 0, 1, false, EPI_NONE);

    // 5) RoPE
    {
        long nq = (long)B_ * S_ * H_ * 128;
        rope_kernel<<<(unsigned)((nq + 255) / 256), 256>>>(q, pos, H_, nq);
        long nk = (long)B_ * S_ * 1 * 128;
        rope_kernel<<<(unsigned)((nk + 255) / 256), 256>>>(k, pos, 1, nk);
    }

    // 6) scores, 7) softmax, 8) att (FFMA path)
    launch_gemm(q, k, scores, S_, S_, HD_, H_*HD_, HD_, S_,
                B_ * H_,
                (long)S_*H_*HD_, HD_,
                (long)S_*HD_, 0,
                (long)H_*S_*S_, (long)S_*S_,
                H_, true, EPI_SCORES,
                nullptr, 0, nullptr, 0, cs, pad_masks, S_, 0.0625f);
    softmax_kernel<<<B_ * H_ * S_, 256>>>(scores);
    launch_gemm(scores, v, att, S_, HD_, S_, S_, HD_, H_*HD_,
                B_ * H_,
                (long)H_*S_*S_, (long)S_*S_,
                (long)S_*HD_, 0,
                (long)S_*H_*HD_, HD_,
                H_, false, EPI_NONE);

    // 9) output projections
    launch_split(att, att3, M0, H_ * HD_, S1_, S_);   // gather first 768 rows of each batch
    launch_tc(att3, wo03, r0, M0, D0_, 3 * H_ * HD_, EPI_RES, x0, M0, 0, D0_);
    launch_gemm(att + (long)S1_*H_*HD_, w_o1, r1, S2_, D1_, H_*HD_, H_*HD_, D1_, D1_,
                B_, (long)S_*H_*HD_, 0, 0, 0, (long)S2_*D1_, 0, 1, false,
                EPI_RES_GATE, x1, (long)S2_*D1_, modin + D1_, 2 * D1_);

    // 10) post norms (y03 triple directly for TC; y1 fp32 for FFMA)
    rmsnorm_kernel<<<B_ * S1_, 256>>>(r0, nullptr, y03, norm2_w0, 0, D0_, S1_);
    rmsnorm_kernel<<<B_ * S2_, 256>>>(r1, y1, nullptr, modpost, 2 * D1_, D1_, S2_);

    // 11) MLP stream 0 (tensor cores; up epilogue writes gu03 triple directly)
    launch_tc(y03, wg03, gu0, M0, F0_, 3 * D0_, EPI_NONE, nullptr, M0, 0, F0_);
    launch_tc(y03, wu03, nullptr, M0, F0_, 3 * D0_, EPI_GELUMUL_SP, gu0, M0, 0, F0_, gu03);
    launch_tc(gu03, wd03, out0, M0, D0_, 3 * F0_, EPI_RES, r0, M0, 0, D0_);

    // 12) MLP stream 1 (FFMA)
    launch_gemm(y1, w_gate1, gu1, S2_, F1_, D1_, D1_, F1_, F1_,
                B_, (long)S2_*D1_, 0, 0, 0, (long)S2_*F1_, 0, 1, false, EPI_NONE);
    launch_gemm(y1, w_up1, gu1, S2_, F1_, D1_, D1_, F1_, F1_,
                B_, (long)S2_*D1_, 0, 0, 0, (long)S2_*F1_, 0, 1, false,
                EPI_GELUMUL, gu1, (long)S2_*F1_);
    launch_gemm(gu1, w_down1, out1, S2_, D1_, F1_, F1_, D1_, D1_,
                B_, (long)S2_*F1_, 0, 0, 0, (long)S2_*D1_, 0, 1, false,
                EPI_RES_GATE, r1, (long)S2_*D1_, modpost + D1_, 2 * D1_);
}

// round 5
// speedup vs baseline: 1.1118x; 1.1118x over previous
#include <cuda_runtime.h>
#include <cuda_bf16.h>
#include <math.h>
#include <stdint.h>

// ---------------- problem constants ----------------
#define B_   4
#define S1_  768
#define S2_  64
#define S_   832
#define D0_  2048
#define F0_  16384
#define D1_  1024
#define F1_  4096
#define H_   8
#define HD_  256
#define EPS_ 1e-6f
#define MASK_VAL_ -1000000000.0f

// ---------------- scratch (device globals; no allocation allowed) ----------------
__device__ float g_h0[B_*S1_*D0_];
__device__ float g_h1[B_*S2_*D1_];
__device__ float g_mod_in[B_*2*D1_];
__device__ float g_mod_post[B_*2*D1_];
__device__ float g_q[(size_t)B_*S_*H_*HD_];
__device__ float g_k[B_*S_*HD_];
__device__ float g_v[B_*S_*HD_];
__device__ float g_scores[(size_t)B_*H_*S_*S_];
__device__ float g_att[(size_t)B_*S_*H_*HD_];
__device__ float g_r0[B_*S1_*D0_];
__device__ float g_gu0[(size_t)B_*S1_*F0_];
__device__ float g_r1[B_*S2_*D1_];
__device__ float g_y1[B_*S2_*D1_];
__device__ float g_gu1[B_*S2_*F1_];
__device__ int   g_pos[B_*S_];
__device__ int   g_cs[B_*S_];

// split-bf16 operands (activations A' = [hi|hi|lo], weights B' = [hi|lo|hi] along K)
__device__ __nv_bfloat16 g_h03 [(size_t)3072*3*2048];
__device__ __nv_bfloat16 g_att3[(size_t)3072*3*2048];
__device__ __nv_bfloat16 g_y03 [(size_t)3072*3*2048];
__device__ __nv_bfloat16 g_gu03[(size_t)3072*3*16384];
__device__ __nv_bfloat16 g_wq03[(size_t)2048*3*2048];
__device__ __nv_bfloat16 g_wo03[(size_t)2048*3*2048];
__device__ __nv_bfloat16 g_wg03[(size_t)16384*3*2048];
__device__ __nv_bfloat16 g_wu03[(size_t)16384*3*2048];
__device__ __nv_bfloat16 g_wd03[(size_t)2048*3*16384];

// ---------------- small helpers ----------------
__device__ __forceinline__ float gelu_tanh(float x) {
    float x3 = x * x * x;
    return 0.5f * x * (1.0f + tanhf(0.79788456080286535588f * (x + 0.044715f * x3)));
}

__device__ __forceinline__ uint32_t smem_u32(const void* p) {
    uint32_t a;
    asm("{ .reg .u64 t; cvta.to.shared.u64 t, %1; cvt.u32.u64 %0, t; }" : "=r"(a) : "l"(p));
    return a;
}

#define CP_ASYNC16(sm, gm) \
    asm volatile("cp.async.cg.shared.global [%0], [%1], 16;" :: "r"(sm), "l"(gm))
#define CP_COMMIT() asm volatile("cp.async.commit_group;")
#define CP_WAIT(n)  asm volatile("cp.async.wait_group %0;" :: "n"(n))

__device__ __forceinline__ void ldsm_x4(uint32_t* r, uint32_t addr) {
    asm volatile("ldmatrix.sync.aligned.m8n8.x4.shared.b16 {%0,%1,%2,%3}, [%4];"
                 : "=r"(r[0]), "=r"(r[1]), "=r"(r[2]), "=r"(r[3]) : "r"(addr));
}
__device__ __forceinline__ void mma_bf16(float* c, const uint32_t* a, uint32_t b0, uint32_t b1) {
    asm volatile("mma.sync.aligned.m16n8k16.row.col.f32.bf16.bf16.f32 "
                 "{%0,%1,%2,%3}, {%4,%5,%6,%7}, {%8,%9}, {%0,%1,%2,%3};"
                 : "+f"(c[0]), "+f"(c[1]), "+f"(c[2]), "+f"(c[3])
                 : "r"(a[0]), "r"(a[1]), "r"(a[2]), "r"(a[3]), "r"(b0), "r"(b1));
}

// swizzled chunk address within a [rows x 64bf16] tile: 8 x 16B chunks per row, chunk^(row&7)
__device__ __forceinline__ uint32_t sw_addr(uint32_t base, int row, int chunk) {
    return base + (uint32_t)(((row << 3) + (chunk ^ (row & 7))) << 4);
}

// ---------------- epilogue modes ----------------
#define EPI_NONE       0
#define EPI_SCORES     1
#define EPI_RES        2
#define EPI_RES_GATE   3
#define EPI_GELUMUL    4
#define EPI_GELUMUL_SP 5   // v = gelu(aux)*v, write bf16 triple [hi|hi|lo] to C3 (no fp32 store)

// ---------------- tensor-core split-bf16 GEMM: C[M,N] = A'[M,Kp] * B't[N,Kp]^T ----------------
// 128x128 CTA tile, 8 warps (2x4), warp tile 64x32, BK=64, 3-stage cp.async, 96KB smem (2 CTA/SM)
struct TcP {
    const __nv_bfloat16* A;   // [M, Kp] row-major
    const __nv_bfloat16* Bt;  // [N, Kp] row-major (B^T)
    float* C;
    __nv_bfloat16* C3;        // triple output (EPI_GELUMUL_SP)
    const float* aux;         // logical [M, N] row-major
    int M, N, Kp;
    int epi;
    int rpb, obatch, ldc;     // out row = (r/rpb)*obatch + r%rpb
};

#define TC_STAGES 3
#define TC_STAGE_BYTES 32768     // 16KB A + 16KB B
#define TC_SMEM (TC_STAGES * TC_STAGE_BYTES)

__global__ __launch_bounds__(256) void tc_gemm_kernel(TcP p) {
    extern __shared__ char dsm[];
    uint32_t sbase = smem_u32(dsm);

    int tid  = threadIdx.x;
    int wid  = tid >> 5;
    int lane = tid & 31;
    int wm = wid >> 2;          // 0..1 -> row offset wm*64
    int wn = wid & 3;           // 0..3 -> col offset wn*32

    int m0 = blockIdx.y * 128;
    int n0 = blockIdx.x * 128;

    int kc   = tid & 7;
    int rb   = tid >> 3;        // 0..31
    const __nv_bfloat16* gA = p.A  + (size_t)(m0) * p.Kp + kc * 8;
    const __nv_bfloat16* gB = p.Bt + (size_t)(n0) * p.Kp + kc * 8;

    float acc[4][4][4];
    #pragma unroll
    for (int i = 0; i < 4; i++)
        #pragma unroll
        for (int j = 0; j < 4; j++)
            #pragma unroll
            for (int e = 0; e < 4; e++) acc[i][j][e] = 0.f;

    int nIter = p.Kp >> 6;

    auto issue = [&](int it) {
        int st = it % TC_STAGES;
        uint32_t sa = sbase + st * TC_STAGE_BYTES;
        uint32_t sb = sa + 16384;
        int k0 = it << 6;
        #pragma unroll
        for (int i = 0; i < 4; i++) {
            int row = rb + i * 32;
            CP_ASYNC16(sw_addr(sa, row, kc), gA + (size_t)row * p.Kp + k0);
            CP_ASYNC16(sw_addr(sb, row, kc), gB + (size_t)row * p.Kp + k0);
        }
        CP_COMMIT();
    };

    #pragma unroll
    for (int s = 0; s < TC_STAGES - 1; s++) issue(s);

    int grp = lane >> 3;     // 0..3
    int lr  = lane & 7;

    for (int it = 0; it < nIter; it++) {
        if (it + TC_STAGES - 1 < nIter) {
            issue(it + TC_STAGES - 1);
            CP_WAIT(TC_STAGES - 2);
        } else {
            CP_WAIT(0);
        }
        __syncthreads();

        int st = it % TC_STAGES;
        uint32_t sa = sbase + st * TC_STAGE_BYTES;
        uint32_t sb = sa + 16384;

        #pragma unroll
        for (int kb = 0; kb < 4; kb++) {
            int chA = 2 * kb + (grp >> 1);
            uint32_t a[4][4];
            #pragma unroll
            for (int mi = 0; mi < 4; mi++) {
                int row = wm * 64 + mi * 16 + (grp & 1) * 8 + lr;
                ldsm_x4(a[mi], sw_addr(sa, row, chA));
            }
            uint32_t bf[2][4];
            #pragma unroll
            for (int bi = 0; bi < 2; bi++) {
                int row = wn * 32 + bi * 16 + (grp & 1) * 8 + lr;
                ldsm_x4(bf[bi], sw_addr(sb, row, chA));
            }
            #pragma unroll
            for (int mi = 0; mi < 4; mi++)
                #pragma unroll
                for (int ni = 0; ni < 4; ni++) {
                    int bi = ni >> 1, wh = ni & 1;
                    mma_bf16(acc[mi][ni], a[mi], bf[bi][wh], bf[bi][wh + 2]);
                }
        }
        __syncthreads();
    }

    // ---- epilogue ----
    int qrow = lane >> 2;        // 0..7
    int qcol = (lane & 3) * 2;
    #pragma unroll
    for (int mi = 0; mi < 4; mi++) {
        #pragma unroll
        for (int half = 0; half < 2; half++) {
            int r = m0 + wm * 64 + mi * 16 + half * 8 + qrow;
            int orow = (r / p.rpb) * p.obatch + (r % p.rpb);
            #pragma unroll
            for (int ni = 0; ni < 4; ni++) {
                int col = n0 + wn * 32 + ni * 8 + qcol;
                float v0 = acc[mi][ni][half * 2 + 0];
                float v1 = acc[mi][ni][half * 2 + 1];
                if (p.epi == EPI_RES) {
                    float2 ax = *(const float2*)&p.aux[(size_t)r * p.N + col];
                    v0 += ax.x; v1 += ax.y;
                } else if (p.epi == EPI_GELUMUL) {
                    float2 ax = *(const float2*)&p.aux[(size_t)r * p.N + col];
                    v0 = gelu_tanh(ax.x) * v0;
                    v1 = gelu_tanh(ax.y) * v1;
                } else if (p.epi == EPI_GELUMUL_SP) {
                    float2 ax = *(const float2*)&p.aux[(size_t)r * p.N + col];
                    v0 = gelu_tanh(ax.x) * v0;
                    v1 = gelu_tanh(ax.y) * v1;
                    __nv_bfloat16 h0 = __float2bfloat16(v0);
                    __nv_bfloat16 h1 = __float2bfloat16(v1);
                    __nv_bfloat162 hh; hh.x = h0; hh.y = h1;
                    __nv_bfloat162 ll;
                    ll.x = __float2bfloat16(v0 - __bfloat162float(h0));
                    ll.y = __float2bfloat16(v1 - __bfloat162float(h1));
                    size_t base = (size_t)orow * 3 * p.N;
                    *(__nv_bfloat162*)&p.C3[base + col]           = hh;
                    *(__nv_bfloat162*)&p.C3[base + p.N + col]     = hh;
                    *(__nv_bfloat162*)&p.C3[base + 2 * p.N + col] = ll;
                    continue;
                }
                *(float2*)&p.C[(size_t)orow * p.ldc + col] = make_float2(v0, v1);
            }
        }
    }
}

// ---------------- split conversion kernels ----------------
// activations: out[r, 0..K)=hi, [K..2K)=hi, [2K..3K)=lo ; in row = (r/rpb)*ibatch + r%rpb
__global__ void split_act_kernel(const float* __restrict__ in, __nv_bfloat16* __restrict__ out,
                                 int M, int K, int rpb, int ibatch) {
    size_t idx = blockIdx.x * (size_t)blockDim.x + threadIdx.x;
    size_t total = (size_t)M * K;
    if (idx >= total) return;
    int r = (int)(idx / K), k = (int)(idx % K);
    int ir = (r / rpb) * ibatch + (r % rpb);
    float v = in[(size_t)ir * K + k];
    __nv_bfloat16 hi = __float2bfloat16(v);
    __nv_bfloat16 lo = __float2bfloat16(v - __bfloat162float(hi));
    __nv_bfloat16* o = out + (size_t)r * 3 * K;
    o[k] = hi; o[K + k] = hi; o[2 * K + k] = lo;
}

// weights W[K,N] -> out[N, 3K]: [0..K)=hi, [K..2K)=lo, [2K..3K)=hi (transposed)
__global__ void tsplit_kernel(const float* __restrict__ W, __nv_bfloat16* __restrict__ out,
                              int K, int N) {
    __shared__ float t[32][33];
    int k0 = blockIdx.y * 32, n0 = blockIdx.x * 32;
    int tx = threadIdx.x, ty = threadIdx.y;   // 32 x 8
    #pragma unroll
    for (int i = 0; i < 4; i++)
        t[ty + i * 8][tx] = W[(size_t)(k0 + ty + i * 8) * N + n0 + tx];
    __syncthreads();
    #pragma unroll
    for (int i = 0; i < 4; i++) {
        int n = n0 + ty + i * 8;
        int k = k0 + tx;
        float v = t[tx][ty + i * 8];
        __nv_bfloat16 hi = __float2bfloat16(v);
        __nv_bfloat16 lo = __float2bfloat16(v - __bfloat162float(hi));
        __nv_bfloat16* o = out + (size_t)n * 3 * K;
        o[k] = hi; o[K + k] = lo; o[2 * K + k] = hi;
    }
}

// ---------------- legacy FFMA batched SGEMM (small ops / attention) ----------------
struct GemmP {
    const float* A; const float* B; float* C;
    int M, N, K, lda, ldb, ldc;
    long sA1, sA2, sB1, sB2, sC1, sC2;
    int zdiv;
    int transB;
    int epi;
    const float* aux; long sAux;
    const float* gvec; int gvecStride;
    const int* cs; const int* pad; int maskStride;
    float scale;
};

#define BM 128
#define BN 128
#define BK 8
#define TM 8
#define TN 8

__global__ __launch_bounds__(256) void gemm_kernel(GemmP p) {
    __shared__ float As[BK][BM];
    __shared__ float Bs[BK][BN];

    int z  = blockIdx.z;
    int zb = z / p.zdiv;
    int zr = z % p.zdiv;

    const float* A = p.A + (long)zb * p.sA1 + (long)zr * p.sA2;
    const float* Bm = p.B + (long)zb * p.sB1 + (long)zr * p.sB2;
    float* C = p.C + (long)zb * p.sC1 + (long)zr * p.sC2;

    int rowBase = blockIdx.y * BM;
    int colBase = blockIdx.x * BN;
    int tid = threadIdx.x;
    int tx = tid % 16;
    int ty = tid / 16;

    float acc[TM][TN];
    #pragma unroll
    for (int i = 0; i < TM; i++)
        #pragma unroll
        for (int j = 0; j < TN; j++) acc[i][j] = 0.0f;

    int aRow = tid >> 1;
    int aCol = (tid & 1) * 4;
    int bRow = tid >> 5;
    int bCol = (tid & 31) * 4;

    for (int k0 = 0; k0 < p.K; k0 += BK) {
        {
            int gr = rowBase + aRow;
            float4 av = make_float4(0.f, 0.f, 0.f, 0.f);
            if (gr < p.M)
                av = *(const float4*)&A[(long)gr * p.lda + k0 + aCol];
            As[aCol + 0][aRow] = av.x;
            As[aCol + 1][aRow] = av.y;
            As[aCol + 2][aRow] = av.z;
            As[aCol + 3][aRow] = av.w;
        }
        if (!p.transB) {
            int gk = k0 + bRow;
            int gc = colBase + bCol;
            if (gc + 3 < p.N) {
                float4 bv = *(const float4*)&Bm[(long)gk * p.ldb + gc];
                Bs[bRow][bCol + 0] = bv.x;
                Bs[bRow][bCol + 1] = bv.y;
                Bs[bRow][bCol + 2] = bv.z;
                Bs[bRow][bCol + 3] = bv.w;
            } else {
                #pragma unroll
                for (int i = 0; i < 4; i++)
                    Bs[bRow][bCol + i] = (gc + i < p.N) ? Bm[(long)gk * p.ldb + gc + i] : 0.f;
            }
        } else {
            int n  = tid >> 1;
            int kk = (tid & 1) * 4;
            int gn = colBase + n;
            float4 bv = make_float4(0.f, 0.f, 0.f, 0.f);
            if (gn < p.N)
                bv = *(const float4*)&Bm[(long)gn * p.ldb + k0 + kk];
            Bs[kk + 0][n] = bv.x;
            Bs[kk + 1][n] = bv.y;
            Bs[kk + 2][n] = bv.z;
            Bs[kk + 3][n] = bv.w;
        }
        __syncthreads();

        #pragma unroll
        for (int k = 0; k < BK; k++) {
            float a[TM], b[TN];
            float4 a0 = *(const float4*)&As[k][ty * TM];
            float4 a1 = *(const float4*)&As[k][ty * TM + 4];
            a[0]=a0.x; a[1]=a0.y; a[2]=a0.z; a[3]=a0.w;
            a[4]=a1.x; a[5]=a1.y; a[6]=a1.z; a[7]=a1.w;
            float4 b0 = *(const float4*)&Bs[k][tx * TN];
            float4 b1 = *(const float4*)&Bs[k][tx * TN + 4];
            b[0]=b0.x; b[1]=b0.y; b[2]=b0.z; b[3]=b0.w;
            b[4]=b1.x; b[5]=b1.y; b[6]=b1.z; b[7]=b1.w;
            #pragma unroll
            for (int i = 0; i < TM; i++)
                #pragma unroll
                for (int j = 0; j < TN; j++)
                    acc[i][j] += a[i] * b[j];
        }
        __syncthreads();
    }

    const int* csb  = p.cs  ? p.cs  + (long)zb * p.maskStride : nullptr;
    const int* padb = p.pad ? p.pad + (long)zb * p.maskStride : nullptr;
    long auxOff = (long)zb * p.sAux;

    #pragma unroll
    for (int i = 0; i < TM; i++) {
        int row = rowBase + ty * TM + i;
        if (row >= p.M) continue;
        #pragma unroll
        for (int j = 0; j < TN; j++) {
            int col = colBase + tx * TN + j;
            if (col >= p.N) continue;
            long idx = (long)row * p.ldc + col;
            float v = acc[i][j];
            if (p.epi == EPI_SCORES) {
                bool ok = (csb[col] <= csb[row]) && (padb[row] != 0) && (padb[col] != 0);
                v = ok ? v * p.scale : MASK_VAL_;
            } else if (p.epi == EPI_RES) {
                v += p.aux[auxOff + idx];
            } else if (p.epi == EPI_RES_GATE) {
                v = p.aux[auxOff + idx] + p.gvec[(long)zb * p.gvecStride + col] * v;
            } else if (p.epi == EPI_GELUMUL) {
                v = gelu_tanh(p.aux[auxOff + idx]) * v;
            }
            C[idx] = v;
        }
    }
}

// ---------------- mod GEMV ----------------
__global__ void mod_kernel(const float* __restrict__ cond, const float* __restrict__ W,
                           const float* __restrict__ bias, float* __restrict__ out,
                           int D, int N) {
    int j = blockIdx.x * blockDim.x + threadIdx.x;
    int b = blockIdx.y;
    if (j >= N) return;
    float s = bias[j];
    const float* c = cond + (long)b * D;
    for (int k = 0; k < D; k++)
        s += c[k] * W[(long)k * N + j];
    out[(long)b * N + j] = s;
}

// ---------------- prefix scans ----------------
__global__ void scan_kernel(const int* __restrict__ pad, const int* __restrict__ att,
                            int* __restrict__ pos, int* __restrict__ cs) {
    int b = threadIdx.x;
    if (b >= B_) return;
    int cp = 0, ca = 0;
    for (int s = 0; s < S_; s++) {
        cp += pad[b * S_ + s];
        ca += att[b * S_ + s];
        pos[b * S_ + s] = cp - 1;
        cs[b * S_ + s] = ca;
    }
}

// ---------------- RMSNorm (optionally writes fp32 out and/or bf16 triple) ----------------
__global__ void rmsnorm_kernel(const float* __restrict__ x, float* __restrict__ outF,
                               __nv_bfloat16* __restrict__ out3,
                               const float* __restrict__ w, int wStride,
                               int D, int rowsPerBatch) {
    long row = blockIdx.x;
    int b = (int)(row / rowsPerBatch);
    const float* xp = x + row * (long)D;
    float ss = 0.f;
    for (int i = threadIdx.x; i < D; i += blockDim.x) {
        float v = xp[i];
        ss += v * v;
    }
    __shared__ float red[256];
    red[threadIdx.x] = ss;
    __syncthreads();
    for (int s = 128; s > 0; s >>= 1) {
        if (threadIdx.x < s) red[threadIdx.x] += red[threadIdx.x + s];
        __syncthreads();
    }
    float r = rsqrtf(red[0] / (float)D + EPS_);
    const float* wp = w + (long)b * wStride;
    float* opF = outF ? outF + row * (long)D : nullptr;
    __nv_bfloat16* op3 = out3 ? out3 + row * (long)(3 * D) : nullptr;
    for (int i = threadIdx.x; i < D; i += blockDim.x) {
        float v = xp[i] * r * (1.0f + wp[i]);
        if (opF) opF[i] = v;
        if (op3) {
            __nv_bfloat16 hi = __float2bfloat16(v);
            __nv_bfloat16 lo = __float2bfloat16(v - __bfloat162float(hi));
            op3[i] = hi; op3[D + i] = hi; op3[2 * D + i] = lo;
        }
    }
}

// ---------------- RoPE ----------------
__global__ void rope_kernel(float* __restrict__ X, const int* __restrict__ pos, int nH, long total) {
    long idx = blockIdx.x * (long)blockDim.x + threadIdx.x;
    if (idx >= total) return;
    int i = (int)(idx & 127);
    long t = idx >> 7;
    int h = (int)(t % nH); t /= nH;
    int s = (int)(t % S_);
    int b = (int)(t / S_);
    float p = (float)pos[b * S_ + s];
    float inv = expf(-((float)i / 128.0f) * 9.210340371976184f);
    float f = p * inv;
    float c = cosf(f), sn = sinf(f);
    float* base = X + ((long)(b * S_ + s) * nH + h) * (long)HD_;
    float x1 = base[i];
    float x2 = base[i + 128];
    base[i]       = x1 * c - x2 * sn;
    base[i + 128] = x2 * c + x1 * sn;
}

// ---------------- row softmax ----------------
__global__ void softmax_kernel(float* __restrict__ scores) {
    float* p = scores + (long)blockIdx.x * S_;
    __shared__ float red[256];
    int tid = threadIdx.x;

    float m = -3.4e38f;
    for (int i = tid; i < S_; i += 256) m = fmaxf(m, p[i]);
    red[tid] = m;
    __syncthreads();
    for (int s = 128; s > 0; s >>= 1) {
        if (tid < s) red[tid] = fmaxf(red[tid], red[tid + s]);
        __syncthreads();
    }
    m = red[0];
    __syncthreads();

    float sum = 0.f;
    for (int i = tid; i < S_; i += 256) {
        float e = expf(p[i] - m);
        p[i] = e;
        sum += e;
    }
    red[tid] = sum;
    __syncthreads();
    for (int s = 128; s > 0; s >>= 1) {
        if (tid < s) red[tid] += red[tid + s];
        __syncthreads();
    }
    float inv = 1.0f / red[0];
    for (int i = tid; i < S_; i += 256) p[i] *= inv;
}

// ---------------- host helpers ----------------
static void launch_gemm(const float* A, const float* Bm, float* C,
                        int M, int N, int K, int lda, int ldb, int ldc,
                        int batches, long sA1, long sA2, long sB1, long sB2,
                        long sC1, long sC2, int zdiv, bool transB, int epi,
                        const float* aux = nullptr, long sAux = 0,
                        const float* gvec = nullptr, int gvecStride = 0,
                        const int* cs = nullptr, const int* pad = nullptr,
                        int maskStride = 0, float scale = 1.0f) {
    GemmP p;
    p.A = A; p.B = Bm; p.C = C;
    p.M = M; p.N = N; p.K = K; p.lda = lda; p.ldb = ldb; p.ldc = ldc;
    p.sA1 = sA1; p.sA2 = sA2; p.sB1 = sB1; p.sB2 = sB2; p.sC1 = sC1; p.sC2 = sC2;
    p.zdiv = zdiv; p.transB = transB ? 1 : 0; p.epi = epi;
    p.aux = aux; p.sAux = sAux; p.gvec = gvec; p.gvecStride = gvecStride;
    p.cs = cs; p.pad = pad; p.maskStride = maskStride; p.scale = scale;
    dim3 grid((N + BN - 1) / BN, (M + BM - 1) / BM, batches);
    gemm_kernel<<<grid, 256>>>(p);
}

static void launch_tc(const __nv_bfloat16* A, const __nv_bfloat16* Bt, float* C,
                      int M, int N, int Kp, int epi, const float* aux,
                      int rpb, int obatch, int ldc,
                      __nv_bfloat16* C3 = nullptr) {
    cudaFuncSetAttribute(tc_gemm_kernel, cudaFuncAttributeMaxDynamicSharedMemorySize, TC_SMEM);
    TcP p;
    p.A = A; p.Bt = Bt; p.C = C; p.C3 = C3; p.aux = aux;
    p.M = M; p.N = N; p.Kp = Kp; p.epi = epi;
    p.rpb = rpb; p.obatch = obatch; p.ldc = ldc;
    dim3 grid(N / 128, M / 128);
    tc_gemm_kernel<<<grid, 256, TC_SMEM>>>(p);
}

static void launch_split(const float* in, __nv_bfloat16* out, int M, int K, int rpb, int ibatch) {
    size_t total = (size_t)M * K;
    split_act_kernel<<<(unsigned)((total + 255) / 256), 256>>>(in, out, M, K, rpb, ibatch);
}

static void launch_tsplit(const float* W, __nv_bfloat16* out, int K, int N) {
    dim3 grid(N / 32, K / 32);
    tsplit_kernel<<<grid, dim3(32, 8)>>>(W, out, K, N);
}

extern "C" void kernel_launch(void* const* d_in, const int* in_sizes, int n_in,
                              void* d_out, int out_size) {
    const float* x0         = (const float*)d_in[0];
    const float* x1         = (const float*)d_in[1];
    const float* cond1      = (const float*)d_in[2];
    const float* w_q0       = (const float*)d_in[3];
    const float* w_k0       = (const float*)d_in[4];
    const float* w_v0       = (const float*)d_in[5];
    const float* w_o0       = (const float*)d_in[6];
    const float* norm1_w0   = (const float*)d_in[7];
    const float* norm2_w0   = (const float*)d_in[8];
    const float* w_gate0    = (const float*)d_in[9];
    const float* w_up0      = (const float*)d_in[10];
    const float* w_down0    = (const float*)d_in[11];
    const float* w_q1       = (const float*)d_in[12];
    const float* w_k1       = (const float*)d_in[13];
    const float* w_v1       = (const float*)d_in[14];
    const float* w_o1       = (const float*)d_in[15];
    const float* ada_in_w1  = (const float*)d_in[16];
    const float* ada_in_b1  = (const float*)d_in[17];
    const float* ada_post_w1= (const float*)d_in[18];
    const float* ada_post_b1= (const float*)d_in[19];
    const float* w_gate1    = (const float*)d_in[20];
    const float* w_up1      = (const float*)d_in[21];
    const float* w_down1    = (const float*)d_in[22];
    const int*   pad_masks  = (const int*)d_in[23];
    const int*   att_masks  = (const int*)d_in[24];

    float* out0 = (float*)d_out;
    float* out1 = out0 + (size_t)B_ * S1_ * D0_;

    float *h0, *h1, *modin, *modpost, *q, *k, *v, *scores, *att, *r0, *gu0, *r1, *y1, *gu1;
    int *pos, *cs;
    __nv_bfloat16 *h03, *att3, *y03, *gu03, *wq03, *wo03, *wg03, *wu03, *wd03;
    cudaGetSymbolAddress((void**)&h0, g_h0);
    cudaGetSymbolAddress((void**)&h1, g_h1);
    cudaGetSymbolAddress((void**)&modin, g_mod_in);
    cudaGetSymbolAddress((void**)&modpost, g_mod_post);
    cudaGetSymbolAddress((void**)&q, g_q);
    cudaGetSymbolAddress((void**)&k, g_k);
    cudaGetSymbolAddress((void**)&v, g_v);
    cudaGetSymbolAddress((void**)&scores, g_scores);
    cudaGetSymbolAddress((void**)&att, g_att);
    cudaGetSymbolAddress((void**)&r0, g_r0);
    cudaGetSymbolAddress((void**)&gu0, g_gu0);
    cudaGetSymbolAddress((void**)&r1, g_r1);
    cudaGetSymbolAddress((void**)&y1, g_y1);
    cudaGetSymbolAddress((void**)&gu1, g_gu1);
    cudaGetSymbolAddress((void**)&pos, g_pos);
    cudaGetSymbolAddress((void**)&cs, g_cs);
    cudaGetSymbolAddress((void**)&h03, g_h03);
    cudaGetSymbolAddress((void**)&att3, g_att3);
    cudaGetSymbolAddress((void**)&y03, g_y03);
    cudaGetSymbolAddress((void**)&gu03, g_gu03);
    cudaGetSymbolAddress((void**)&wq03, g_wq03);
    cudaGetSymbolAddress((void**)&wo03, g_wo03);
    cudaGetSymbolAddress((void**)&wg03, g_wg03);
    cudaGetSymbolAddress((void**)&wu03, g_wu03);
    cudaGetSymbolAddress((void**)&wd03, g_wd03);

    const int M0 = B_ * S1_;   // 3072

    // weight prep (split + transpose to [N, 3K])
    launch_tsplit(w_q0,    wq03, D0_, H_ * HD_);
    launch_tsplit(w_o0,    wo03, H_ * HD_, D0_);
    launch_tsplit(w_gate0, wg03, D0_, F0_);
    launch_tsplit(w_up0,   wu03, D0_, F0_);
    launch_tsplit(w_down0, wd03, F0_, D0_);

    // 1) adaLN modulation
    {
        dim3 mg((2 * D1_ + 255) / 256, B_);
        mod_kernel<<<mg, 256>>>(cond1, ada_in_w1,  ada_in_b1,  modin,   D1_, 2 * D1_);
        mod_kernel<<<mg, 256>>>(cond1, ada_post_w1, ada_post_b1, modpost, D1_, 2 * D1_);
    }

    // 2) scans
    scan_kernel<<<1, 32>>>(pad_masks, att_masks, pos, cs);

    // 3) input norms (h0 fp32 for k/v FFMA + h03 triple for TC)
    rmsnorm_kernel<<<B_ * S1_, 256>>>(x0, h0, h03, norm1_w0, 0, D0_, S1_);
    rmsnorm_kernel<<<B_ * S2_, 256>>>(x1, h1, nullptr, modin, 2 * D1_, D1_, S2_);

    // 4) QKV: q0 via TC (row remap into S=832 buffer), rest FFMA
    launch_tc(h03, wq03, q, M0, H_ * HD_, 3 * D0_, EPI_NONE, nullptr, S1_, S_, H_ * HD_);
    launch_gemm(h0, w_k0, k, S1_, HD_, D0_, D0_, HD_, HD_,
                B_, (long)S1_*D0_, 0, 0, 0, (long)S_*HD_, 0, 1, false, EPI_NONE);
    launch_gemm(h0, w_v0, v, S1_, HD_, D0_, D0_, HD_, HD_,
                B_, (long)S1_*D0_, 0, 0, 0, (long)S_*HD_, 0, 1, false, EPI_NONE);
    launch_gemm(h1, w_q1, q + (long)S1_*H_*HD_, S2_, H_*HD_, D1_, D1_, H_*HD_, H_*HD_,
                B_, (long)S2_*D1_, 0, 0, 0, (long)S_*H_*HD_, 0, 1, false, EPI_NONE);
    launch_gemm(h1, w_k1, k + (long)S1_*HD_, S2_, HD_, D1_, D1_, HD_, HD_,
                B_, (long)S2_*D1_, 0, 0, 0, (long)S_*HD_, 0, 1, false, EPI_NONE);
    launch_gemm(h1, w_v1, v + (long)S1_*HD_, S2_, HD_, D1_, D1_, HD_, HD_,
                B_, (long)S2_*D1_, 0, 0, 0, (long)S_*HD_, 0, 1, false, EPI_NONE);

    // 5) RoPE
    {
        long nq = (long)B_ * S_ * H_ * 128;
        rope_kernel<<<(unsigned)((nq + 255) / 256), 256>>>(q, pos, H_, nq);
        long nk = (long)B_ * S_ * 1 * 128;
        rope_kernel<<<(unsigned)((nk + 255) / 256), 256>>>(k, pos, 1, nk);
    }

    // 6) scores, 7) softmax, 8) att (FFMA path)
    launch_gemm(q, k, scores, S_, S_, HD_, H_*HD_, HD_, S_,
                B_ * H_,
                (long)S_*H_*HD_, HD_,
                (long)S_*HD_, 0,
                (long)H_*S_*S_, (long)S_*S_,
                H_, true, EPI_SCORES,
                nullptr, 0, nullptr, 0, cs, pad_masks, S_, 0.0625f);
    softmax_kernel<<<B_ * H_ * S_, 256>>>(scores);
    launch_gemm(scores, v, att, S_, HD_, S_, S_, HD_, H_*HD_,
                B_ * H_,
                (long)H_*S_*S_, (long)S_*S_,
                (long)S_*HD_, 0,
                (long)S_*H_*HD_, HD_,
                H_, false, EPI_NONE);

    // 9) output projections
    launch_split(att, att3, M0, H_ * HD_, S1_, S_);   // gather first 768 rows of each batch
    launch_tc(att3, wo03, r0, M0, D0_, 3 * H_ * HD_, EPI_RES, x0, M0, 0, D0_);
    launch_gemm(att + (long)S1_*H_*HD_, w_o1, r1, S2_, D1_, H_*HD_, H_*HD_, D1_, D1_,
                B_, (long)S_*H_*HD_, 0, 0, 0, (long)S2_*D1_, 0, 1, false,
                EPI_RES_GATE, x1, (long)S2_*D1_, modin + D1_, 2 * D1_);

    // 10) post norms (y03 triple directly for TC; y1 fp32 for FFMA)
    rmsnorm_kernel<<<B_ * S1_, 256>>>(r0, nullptr, y03, norm2_w0, 0, D0_, S1_);
    rmsnorm_kernel<<<B_ * S2_, 256>>>(r1, y1, nullptr, modpost, 2 * D1_, D1_, S2_);

    // 11) MLP stream 0 (tensor cores; up epilogue writes gu03 triple directly)
    launch_tc(y03, wg03, gu0, M0, F0_, 3 * D0_, EPI_NONE, nullptr, M0, 0, F0_);
    launch_tc(y03, wu03, nullptr, M0, F0_, 3 * D0_, EPI_GELUMUL_SP, gu0, M0, 0, F0_, gu03);
    launch_tc(gu03, wd03, out0, M0, D0_, 3 * F0_, EPI_RES, r0, M0, 0, D0_);

    // 12) MLP stream 1 (FFMA)
    launch_gemm(y1, w_gate1, gu1, S2_, F1_, D1_, D1_, F1_, F1_,
                B_, (long)S2_*D1_, 0, 0, 0, (long)S2_*F1_, 0, 1, false, EPI_NONE);
    launch_gemm(y1, w_up1, gu1, S2_, F1_, D1_, D1_, F1_, F1_,
                B_, (long)S2_*D1_, 0, 0, 0, (long)S2_*F1_, 0, 1, false,
                EPI_GELUMUL, gu1, (long)S2_*F1_);
    launch_gemm(gu1, w_down1, out1, S2_, D1_, F1_, F1_, D1_, D1_,
                B_, (long)S2_*F1_, 0, 0, 0, (long)S2_*D1_, 0, 1, false,
                EPI_RES_GATE, r1, (long)S2_*D1_, modpost + D1_, 2 * D1_);
}

// round 6
// speedup vs baseline: 1.5007x; 1.3498x over previous
#include <cuda_runtime.h>
#include <cuda_bf16.h>
#include <math.h>
#include <stdint.h>

// ---------------- problem constants ----------------
#define B_   4
#define S1_  768
#define S2_  64
#define S_   832
#define D0_  2048
#define F0_  16384
#define D1_  1024
#define F1_  4096
#define H_   8
#define HD_  256
#define EPS_ 1e-6f
#define MASK_VAL_ -1000000000.0f

// ---------------- scratch (device globals) ----------------
__device__ float g_mod_in[B_*2*D1_];
__device__ float g_mod_post[B_*2*D1_];
__device__ float g_q[(size_t)B_*S_*H_*HD_];
__device__ float g_k[B_*S_*HD_];
__device__ float g_v[B_*S_*HD_];
__device__ float g_scores[(size_t)B_*H_*S_*S_];
__device__ float g_att[(size_t)B_*S_*H_*HD_];
__device__ float g_r0[B_*S1_*D0_];
__device__ float g_gu0[(size_t)B_*S1_*F0_];
__device__ float g_r1[B_*S2_*D1_];
__device__ float g_gu1[B_*S2_*F1_];
__device__ int   g_pos[B_*S_];
__device__ int   g_cs[B_*S_];

// split-bf16 operands: activations [hi|hi|lo], weights/B-side [hi|lo|hi] along K
__device__ __nv_bfloat16 g_h03 [(size_t)3072*3*2048];
__device__ __nv_bfloat16 g_h13 [(size_t)256*3*1024];
__device__ __nv_bfloat16 g_att3[(size_t)3072*3*2048];
__device__ __nv_bfloat16 g_att13[(size_t)256*3*2048];
__device__ __nv_bfloat16 g_y03 [(size_t)3072*3*2048];
__device__ __nv_bfloat16 g_y13 [(size_t)256*3*1024];
__device__ __nv_bfloat16 g_gu03[(size_t)3072*3*16384];
__device__ __nv_bfloat16 g_gu13[(size_t)256*3*4096];
__device__ __nv_bfloat16 g_q3 [(size_t)B_*H_*S_*3*HD_];
__device__ __nv_bfloat16 g_k3 [(size_t)B_*S_*3*HD_];
__device__ __nv_bfloat16 g_vt3[(size_t)B_*HD_*3*S_];
__device__ __nv_bfloat16 g_p3 [(size_t)B_*H_*S_*3*S_];
// weights
__device__ __nv_bfloat16 g_wq03[(size_t)2048*3*2048];
__device__ __nv_bfloat16 g_wk03[(size_t)256*3*2048];
__device__ __nv_bfloat16 g_wv03[(size_t)256*3*2048];
__device__ __nv_bfloat16 g_wo03[(size_t)2048*3*2048];
__device__ __nv_bfloat16 g_wg03[(size_t)16384*3*2048];
__device__ __nv_bfloat16 g_wu03[(size_t)16384*3*2048];
__device__ __nv_bfloat16 g_wd03[(size_t)2048*3*16384];
__device__ __nv_bfloat16 g_wq13[(size_t)2048*3*1024];
__device__ __nv_bfloat16 g_wk13[(size_t)256*3*1024];
__device__ __nv_bfloat16 g_wv13[(size_t)256*3*1024];
__device__ __nv_bfloat16 g_wo13[(size_t)1024*3*2048];
__device__ __nv_bfloat16 g_wg13[(size_t)4096*3*1024];
__device__ __nv_bfloat16 g_wu13[(size_t)4096*3*1024];
__device__ __nv_bfloat16 g_wd13[(size_t)1024*3*4096];

// ---------------- helpers ----------------
__device__ __forceinline__ float gelu_tanh(float x) {
    float x3 = x * x * x;
    return 0.5f * x * (1.0f + tanhf(0.79788456080286535588f * (x + 0.044715f * x3)));
}
__device__ __forceinline__ uint32_t smem_u32(const void* p) {
    uint32_t a;
    asm("{ .reg .u64 t; cvta.to.shared.u64 t, %1; cvt.u32.u64 %0, t; }" : "=r"(a) : "l"(p));
    return a;
}
#define CP_ASYNC16(sm, gm) \
    asm volatile("cp.async.cg.shared.global [%0], [%1], 16;" :: "r"(sm), "l"(gm))
#define CP_COMMIT() asm volatile("cp.async.commit_group;")
#define CP_WAIT(n)  asm volatile("cp.async.wait_group %0;" :: "n"(n))

__device__ __forceinline__ void ldsm_x4(uint32_t* r, uint32_t addr) {
    asm volatile("ldmatrix.sync.aligned.m8n8.x4.shared.b16 {%0,%1,%2,%3}, [%4];"
                 : "=r"(r[0]), "=r"(r[1]), "=r"(r[2]), "=r"(r[3]) : "r"(addr));
}
__device__ __forceinline__ void mma_bf16(float* c, const uint32_t* a, uint32_t b0, uint32_t b1) {
    asm volatile("mma.sync.aligned.m16n8k16.row.col.f32.bf16.bf16.f32 "
                 "{%0,%1,%2,%3}, {%4,%5,%6,%7}, {%8,%9}, {%0,%1,%2,%3};"
                 : "+f"(c[0]), "+f"(c[1]), "+f"(c[2]), "+f"(c[3])
                 : "r"(a[0]), "r"(a[1]), "r"(a[2]), "r"(a[3]), "r"(b0), "r"(b1));
}
__device__ __forceinline__ uint32_t sw_addr(uint32_t base, int row, int chunk) {
    return base + (uint32_t)(((row << 3) + (chunk ^ (row & 7))) << 4);
}

// ---------------- epilogue modes ----------------
#define EPI_NONE       0
#define EPI_SCORES     1
#define EPI_RES        2
#define EPI_RES_GATE   3
#define EPI_GELUMUL_SP 5

// ---------------- TC split-bf16 GEMM ----------------
// 128x128 CTA tile, 8 warps, warp 64x32, BK=64, 3-stage cp.async, 96KB smem (2 CTA/SM)
struct TcP {
    const __nv_bfloat16* A;   // [M, Kp] (z-batched)
    const __nv_bfloat16* Bt;  // [N, Kp] (z-batched)
    float* C;
    __nv_bfloat16* C3;
    const float* aux;         // [M, N] row-major (non-batched uses)
    const float* gvec; int gstride, gdiv;
    const int *cs, *pad; int maskStride; float scale;
    int M, N, Kp, epi;
    int rpb, obatch, ldc;     // out row = (r/rpb)*obatch + r%rpb
    size_t zA1, zA2, zB1, zB2, zC1, zC2; int zdiv;
};

#define TC_STAGES 3
#define TC_STAGE_BYTES 32768
#define TC_SMEM (TC_STAGES * TC_STAGE_BYTES)

__global__ __launch_bounds__(256) void tc_gemm_kernel(TcP p) {
    extern __shared__ char dsm[];
    uint32_t sbase = smem_u32(dsm);

    int tid  = threadIdx.x;
    int wid  = tid >> 5;
    int lane = tid & 31;
    int wm = wid >> 2;
    int wn = wid & 3;

    int m0 = blockIdx.y * 128;
    int n0 = blockIdx.x * 128;
    int z  = blockIdx.z;
    int zb = z / p.zdiv;
    int zr = z - zb * p.zdiv;

    const __nv_bfloat16* Ab = p.A  + (size_t)zb * p.zA1 + (size_t)zr * p.zA2;
    const __nv_bfloat16* Bb = p.Bt + (size_t)zb * p.zB1 + (size_t)zr * p.zB2;
    float* Cz = p.C + (size_t)zb * p.zC1 + (size_t)zr * p.zC2;

    int kc = tid & 7;
    int rb = tid >> 3;

    float acc[4][4][4];
    #pragma unroll
    for (int i = 0; i < 4; i++)
        #pragma unroll
        for (int j = 0; j < 4; j++)
            #pragma unroll
            for (int e = 0; e < 4; e++) acc[i][j][e] = 0.f;

    int nIter = p.Kp >> 6;

    auto issue = [&](int it) {
        int st = it % TC_STAGES;
        uint32_t sa = sbase + st * TC_STAGE_BYTES;
        uint32_t sb = sa + 16384;
        int k0 = it << 6;
        #pragma unroll
        for (int i = 0; i < 4; i++) {
            int row = rb + i * 32;
            int ra = m0 + row; if (ra > p.M - 1) ra = p.M - 1;
            CP_ASYNC16(sw_addr(sa, row, kc), Ab + (size_t)ra * p.Kp + k0 + kc * 8);
            int rn = n0 + row; if (rn > p.N - 1) rn = p.N - 1;
            CP_ASYNC16(sw_addr(sb, row, kc), Bb + (size_t)rn * p.Kp + k0 + kc * 8);
        }
        CP_COMMIT();
    };

    #pragma unroll
    for (int s = 0; s < TC_STAGES - 1; s++) issue(s);

    int grp = lane >> 3;
    int lr  = lane & 7;

    for (int it = 0; it < nIter; it++) {
        if (it + TC_STAGES - 1 < nIter) {
            issue(it + TC_STAGES - 1);
            CP_WAIT(TC_STAGES - 2);
        } else {
            CP_WAIT(0);
        }
        __syncthreads();

        int st = it % TC_STAGES;
        uint32_t sa = sbase + st * TC_STAGE_BYTES;
        uint32_t sb = sa + 16384;

        #pragma unroll
        for (int kb = 0; kb < 4; kb++) {
            int chA = 2 * kb + (grp >> 1);
            uint32_t a[4][4];
            #pragma unroll
            for (int mi = 0; mi < 4; mi++) {
                int row = wm * 64 + mi * 16 + (grp & 1) * 8 + lr;
                ldsm_x4(a[mi], sw_addr(sa, row, chA));
            }
            uint32_t bf[2][4];
            #pragma unroll
            for (int bi = 0; bi < 2; bi++) {
                int row = wn * 32 + bi * 16 + (grp & 1) * 8 + lr;
                ldsm_x4(bf[bi], sw_addr(sb, row, chA));
            }
            #pragma unroll
            for (int mi = 0; mi < 4; mi++)
                #pragma unroll
                for (int ni = 0; ni < 4; ni++) {
                    int bi = ni >> 1, wh = ni & 1;
                    mma_bf16(acc[mi][ni], a[mi], bf[bi][wh], bf[bi][wh + 2]);
                }
        }
        __syncthreads();
    }

    // ---- epilogue ----
    const int* csb  = p.cs  ? p.cs  + (size_t)zb * p.maskStride : nullptr;
    const int* padb = p.pad ? p.pad + (size_t)zb * p.maskStride : nullptr;
    int qrow = lane >> 2;
    int qcol = (lane & 3) * 2;
    #pragma unroll
    for (int mi = 0; mi < 4; mi++) {
        #pragma unroll
        for (int half = 0; half < 2; half++) {
            int r = m0 + wm * 64 + mi * 16 + half * 8 + qrow;
            if (r >= p.M) continue;
            int orow = (r / p.rpb) * p.obatch + (r % p.rpb);
            #pragma unroll
            for (int ni = 0; ni < 4; ni++) {
                int col = n0 + wn * 32 + ni * 8 + qcol;
                if (col >= p.N) continue;
                float v0 = acc[mi][ni][half * 2 + 0];
                float v1 = acc[mi][ni][half * 2 + 1];
                if (p.epi == EPI_SCORES) {
                    int csr = csb[r];
                    bool okr = padb[r] != 0;
                    bool ok0 = (csb[col] <= csr) && okr && (padb[col] != 0);
                    bool ok1 = (csb[col + 1] <= csr) && okr && (padb[col + 1] != 0);
                    v0 = ok0 ? v0 * p.scale : MASK_VAL_;
                    v1 = ok1 ? v1 * p.scale : MASK_VAL_;
                } else if (p.epi == EPI_RES) {
                    float2 ax = *(const float2*)&p.aux[(size_t)r * p.N + col];
                    v0 += ax.x; v1 += ax.y;
                } else if (p.epi == EPI_RES_GATE) {
                    float2 ax = *(const float2*)&p.aux[(size_t)r * p.N + col];
                    float2 gx = *(const float2*)&p.gvec[(size_t)(r / p.gdiv) * p.gstride + col];
                    v0 = ax.x + gx.x * v0;
                    v1 = ax.y + gx.y * v1;
                } else if (p.epi == EPI_GELUMUL_SP) {
                    float2 ax = *(const float2*)&p.aux[(size_t)r * p.N + col];
                    v0 = gelu_tanh(ax.x) * v0;
                    v1 = gelu_tanh(ax.y) * v1;
                    __nv_bfloat16 h0 = __float2bfloat16(v0);
                    __nv_bfloat16 h1 = __float2bfloat16(v1);
                    __nv_bfloat162 hh; hh.x = h0; hh.y = h1;
                    __nv_bfloat162 ll;
                    ll.x = __float2bfloat16(v0 - __bfloat162float(h0));
                    ll.y = __float2bfloat16(v1 - __bfloat162float(h1));
                    size_t base = (size_t)orow * 3 * p.N;
                    *(__nv_bfloat162*)&p.C3[base + col]           = hh;
                    *(__nv_bfloat162*)&p.C3[base + p.N + col]     = hh;
                    *(__nv_bfloat162*)&p.C3[base + 2 * p.N + col] = ll;
                    continue;
                }
                *(float2*)&Cz[(size_t)orow * p.ldc + col] = make_float2(v0, v1);
            }
        }
    }
}

// ---------------- split kernels ----------------
// act triple [hi|hi|lo]; in row = (r/rpb)*ibatch + r%rpb
__global__ void split_act_kernel(const float* __restrict__ in, __nv_bfloat16* __restrict__ out,
                                 int M, int K, int rpb, int ibatch) {
    size_t idx = blockIdx.x * (size_t)blockDim.x + threadIdx.x;
    if (idx >= (size_t)M * K) return;
    int r = (int)(idx / K), k = (int)(idx % K);
    int ir = (r / rpb) * ibatch + (r % rpb);
    float v = in[(size_t)ir * K + k];
    __nv_bfloat16 hi = __float2bfloat16(v);
    __nv_bfloat16 lo = __float2bfloat16(v - __bfloat162float(hi));
    __nv_bfloat16* o = out + (size_t)r * 3 * K;
    o[k] = hi; o[K + k] = hi; o[2 * K + k] = lo;
}

// W[K,N] -> out[N,3K] [hi|lo|hi], transposed; batched via grid.z
__global__ void tsplit_kernel(const float* __restrict__ W, __nv_bfloat16* __restrict__ out,
                              int K, int N, size_t inZ, size_t outZ) {
    W   += blockIdx.z * inZ;
    out += blockIdx.z * outZ;
    __shared__ float t[32][33];
    int k0 = blockIdx.y * 32, n0 = blockIdx.x * 32;
    int tx = threadIdx.x, ty = threadIdx.y;
    #pragma unroll
    for (int i = 0; i < 4; i++)
        t[ty + i * 8][tx] = W[(size_t)(k0 + ty + i * 8) * N + n0 + tx];
    __syncthreads();
    #pragma unroll
    for (int i = 0; i < 4; i++) {
        int n = n0 + ty + i * 8;
        int k = k0 + tx;
        float v = t[tx][ty + i * 8];
        __nv_bfloat16 hi = __float2bfloat16(v);
        __nv_bfloat16 lo = __float2bfloat16(v - __bfloat162float(hi));
        __nv_bfloat16* o = out + (size_t)n * 3 * K;
        o[k] = hi; o[K + k] = lo; o[2 * K + k] = hi;
    }
}

// RoPE + split for Q: q[B,S,H,HD] -> q3[B,H,S,3*HD] act-style
__global__ void rope_qsplit_kernel(const float* __restrict__ q, const int* __restrict__ pos,
                                   __nv_bfloat16* __restrict__ out) {
    long idx = blockIdx.x * (long)blockDim.x + threadIdx.x;
    if (idx >= (long)B_ * H_ * S_ * 128) return;
    int i = (int)(idx & 127);
    long t = idx >> 7;
    int s = (int)(t % S_); t /= S_;
    int h = (int)(t % H_);
    int b = (int)(t / H_);
    const float* base = q + ((size_t)(b * S_ + s) * H_ + h) * HD_;
    float x1 = base[i], x2 = base[i + 128];
    float f = (float)pos[b * S_ + s] * expf(-((float)i / 128.0f) * 9.210340371976184f);
    float sn, c; sincosf(f, &sn, &c);
    float o1 = x1 * c - x2 * sn;
    float o2 = x2 * c + x1 * sn;
    __nv_bfloat16 h1 = __float2bfloat16(o1), h2 = __float2bfloat16(o2);
    __nv_bfloat16 l1 = __float2bfloat16(o1 - __bfloat162float(h1));
    __nv_bfloat16 l2 = __float2bfloat16(o2 - __bfloat162float(h2));
    __nv_bfloat16* ob = out + ((size_t)(b * H_ + h) * S_ + s) * (3 * HD_);
    ob[i] = h1;        ob[i + 128] = h2;
    ob[256 + i] = h1;  ob[256 + i + 128] = h2;
    ob[512 + i] = l1;  ob[512 + i + 128] = l2;
}

// RoPE + split for K: k[B,S,HD] -> k3[B,S,3*HD] weight-style [hi|lo|hi]
__global__ void rope_ksplit_kernel(const float* __restrict__ k, const int* __restrict__ pos,
                                   __nv_bfloat16* __restrict__ out) {
    long idx = blockIdx.x * (long)blockDim.x + threadIdx.x;
    if (idx >= (long)B_ * S_ * 128) return;
    int i = (int)(idx & 127);
    long t = idx >> 7;
    int s = (int)(t % S_);
    int b = (int)(t / S_);
    const float* base = k + (size_t)(b * S_ + s) * HD_;
    float x1 = base[i], x2 = base[i + 128];
    float f = (float)pos[b * S_ + s] * expf(-((float)i / 128.0f) * 9.210340371976184f);
    float sn, c; sincosf(f, &sn, &c);
    float o1 = x1 * c - x2 * sn;
    float o2 = x2 * c + x1 * sn;
    __nv_bfloat16 h1 = __float2bfloat16(o1), h2 = __float2bfloat16(o2);
    __nv_bfloat16 l1 = __float2bfloat16(o1 - __bfloat162float(h1));
    __nv_bfloat16 l2 = __float2bfloat16(o2 - __bfloat162float(h2));
    __nv_bfloat16* ob = out + (size_t)(b * S_ + s) * (3 * HD_);
    ob[i] = h1;        ob[i + 128] = h2;
    ob[256 + i] = l1;  ob[256 + i + 128] = l2;
    ob[512 + i] = h1;  ob[512 + i + 128] = h2;
}

// ---------------- mod GEMV ----------------
__global__ void mod_kernel(const float* __restrict__ cond, const float* __restrict__ W,
                           const float* __restrict__ bias, float* __restrict__ out,
                           int D, int N) {
    int j = blockIdx.x * blockDim.x + threadIdx.x;
    int b = blockIdx.y;
    if (j >= N) return;
    float s = bias[j];
    const float* c = cond + (size_t)b * D;
    for (int kk = 0; kk < D; kk++)
        s += c[kk] * W[(size_t)kk * N + j];
    out[(size_t)b * N + j] = s;
}

// ---------------- prefix scans ----------------
__global__ void scan_kernel(const int* __restrict__ pad, const int* __restrict__ att,
                            int* __restrict__ pos, int* __restrict__ cs) {
    int b = threadIdx.x;
    if (b >= B_) return;
    int cp = 0, ca = 0;
    for (int s = 0; s < S_; s++) {
        cp += pad[b * S_ + s];
        ca += att[b * S_ + s];
        pos[b * S_ + s] = cp - 1;
        cs[b * S_ + s] = ca;
    }
}

// ---------------- RMSNorm -> bf16 triple ----------------
__global__ void rmsnorm_kernel(const float* __restrict__ x, __nv_bfloat16* __restrict__ out3,
                               const float* __restrict__ w, int wStride,
                               int D, int rowsPerBatch) {
    long row = blockIdx.x;
    int b = (int)(row / rowsPerBatch);
    const float* xp = x + row * (long)D;
    float ss = 0.f;
    for (int i = threadIdx.x; i < D; i += blockDim.x) {
        float v = xp[i];
        ss += v * v;
    }
    __shared__ float red[256];
    red[threadIdx.x] = ss;
    __syncthreads();
    for (int s = 128; s > 0; s >>= 1) {
        if (threadIdx.x < s) red[threadIdx.x] += red[threadIdx.x + s];
        __syncthreads();
    }
    float r = rsqrtf(red[0] / (float)D + EPS_);
    const float* wp = w + (size_t)b * wStride;
    __nv_bfloat16* op3 = out3 + row * (long)(3 * D);
    for (int i = threadIdx.x; i < D; i += blockDim.x) {
        float v = xp[i] * r * (1.0f + wp[i]);
        __nv_bfloat16 hi = __float2bfloat16(v);
        __nv_bfloat16 lo = __float2bfloat16(v - __bfloat162float(hi));
        op3[i] = hi; op3[D + i] = hi; op3[2 * D + i] = lo;
    }
}

// ---------------- row softmax ----------------
__global__ void softmax_kernel(float* __restrict__ scores) {
    float* p = scores + (size_t)blockIdx.x * S_;
    __shared__ float red[256];
    int tid = threadIdx.x;
    float m = -3.4e38f;
    for (int i = tid; i < S_; i += 256) m = fmaxf(m, p[i]);
    red[tid] = m;
    __syncthreads();
    for (int s = 128; s > 0; s >>= 1) {
        if (tid < s) red[tid] = fmaxf(red[tid], red[tid + s]);
        __syncthreads();
    }
    m = red[0];
    __syncthreads();
    float sum = 0.f;
    for (int i = tid; i < S_; i += 256) {
        float e = expf(p[i] - m);
        p[i] = e;
        sum += e;
    }
    red[tid] = sum;
    __syncthreads();
    for (int s = 128; s > 0; s >>= 1) {
        if (tid < s) red[tid] += red[tid + s];
        __syncthreads();
    }
    float inv = 1.0f / red[0];
    for (int i = tid; i < S_; i += 256) p[i] *= inv;
}

// ---------------- host helpers ----------------
static void launch_tc(const __nv_bfloat16* A, const __nv_bfloat16* Bt, float* C,
                      int M, int N, int Kp, int epi,
                      const float* aux = nullptr,
                      int rpb = 0, int obatch = 0, int ldc = 0,
                      __nv_bfloat16* C3 = nullptr,
                      int zcount = 1, int zdiv = 1,
                      size_t zA1 = 0, size_t zA2 = 0, size_t zB1 = 0, size_t zB2 = 0,
                      size_t zC1 = 0, size_t zC2 = 0,
                      const int* cs = nullptr, const int* pad = nullptr,
                      int maskStride = 0, float scale = 1.0f,
                      const float* gvec = nullptr, int gstride = 0, int gdiv = 1) {
    cudaFuncSetAttribute(tc_gemm_kernel, cudaFuncAttributeMaxDynamicSharedMemorySize, TC_SMEM);
    TcP p;
    p.A = A; p.Bt = Bt; p.C = C; p.C3 = C3; p.aux = aux;
    p.gvec = gvec; p.gstride = gstride; p.gdiv = gdiv;
    p.cs = cs; p.pad = pad; p.maskStride = maskStride; p.scale = scale;
    p.M = M; p.N = N; p.Kp = Kp; p.epi = epi;
    p.rpb = rpb ? rpb : M; p.obatch = obatch; p.ldc = ldc ? ldc : N;
    p.zA1 = zA1; p.zA2 = zA2; p.zB1 = zB1; p.zB2 = zB2; p.zC1 = zC1; p.zC2 = zC2;
    p.zdiv = zdiv;
    dim3 grid((N + 127) / 128, (M + 127) / 128, zcount);
    tc_gemm_kernel<<<grid, 256, TC_SMEM>>>(p);
}

static void launch_split(const float* in, __nv_bfloat16* out, int M, int K, int rpb, int ibatch) {
    size_t total = (size_t)M * K;
    split_act_kernel<<<(unsigned)((total + 255) / 256), 256>>>(in, out, M, K, rpb, ibatch);
}

static void launch_tsplit(const float* W, __nv_bfloat16* out, int K, int N,
                          int z = 1, size_t inZ = 0, size_t outZ = 0) {
    dim3 grid(N / 32, K / 32, z);
    tsplit_kernel<<<grid, dim3(32, 8)>>>(W, out, K, N, inZ, outZ);
}

extern "C" void kernel_launch(void* const* d_in, const int* in_sizes, int n_in,
                              void* d_out, int out_size) {
    const float* x0         = (const float*)d_in[0];
    const float* x1         = (const float*)d_in[1];
    const float* cond1      = (const float*)d_in[2];
    const float* w_q0       = (const float*)d_in[3];
    const float* w_k0       = (const float*)d_in[4];
    const float* w_v0       = (const float*)d_in[5];
    const float* w_o0       = (const float*)d_in[6];
    const float* norm1_w0   = (const float*)d_in[7];
    const float* norm2_w0   = (const float*)d_in[8];
    const float* w_gate0    = (const float*)d_in[9];
    const float* w_up0      = (const float*)d_in[10];
    const float* w_down0    = (const float*)d_in[11];
    const float* w_q1       = (const float*)d_in[12];
    const float* w_k1       = (const float*)d_in[13];
    const float* w_v1       = (const float*)d_in[14];
    const float* w_o1       = (const float*)d_in[15];
    const float* ada_in_w1  = (const float*)d_in[16];
    const float* ada_in_b1  = (const float*)d_in[17];
    const float* ada_post_w1= (const float*)d_in[18];
    const float* ada_post_b1= (const float*)d_in[19];
    const float* w_gate1    = (const float*)d_in[20];
    const float* w_up1      = (const float*)d_in[21];
    const float* w_down1    = (const float*)d_in[22];
    const int*   pad_masks  = (const int*)d_in[23];
    const int*   att_masks  = (const int*)d_in[24];

    float* out0 = (float*)d_out;
    float* out1 = out0 + (size_t)B_ * S1_ * D0_;

    float *modin, *modpost, *q, *k, *v, *scores, *att, *r0, *gu0, *r1, *gu1;
    int *pos, *cs;
    __nv_bfloat16 *h03, *h13, *att3, *att13, *y03, *y13, *gu03, *gu13;
    __nv_bfloat16 *q3, *k3, *vt3, *p3;
    __nv_bfloat16 *wq03, *wk03, *wv03, *wo03, *wg03, *wu03, *wd03;
    __nv_bfloat16 *wq13, *wk13, *wv13, *wo13, *wg13, *wu13, *wd13;
    cudaGetSymbolAddress((void**)&modin, g_mod_in);
    cudaGetSymbolAddress((void**)&modpost, g_mod_post);
    cudaGetSymbolAddress((void**)&q, g_q);
    cudaGetSymbolAddress((void**)&k, g_k);
    cudaGetSymbolAddress((void**)&v, g_v);
    cudaGetSymbolAddress((void**)&scores, g_scores);
    cudaGetSymbolAddress((void**)&att, g_att);
    cudaGetSymbolAddress((void**)&r0, g_r0);
    cudaGetSymbolAddress((void**)&gu0, g_gu0);
    cudaGetSymbolAddress((void**)&r1, g_r1);
    cudaGetSymbolAddress((void**)&gu1, g_gu1);
    cudaGetSymbolAddress((void**)&pos, g_pos);
    cudaGetSymbolAddress((void**)&cs, g_cs);
    cudaGetSymbolAddress((void**)&h03, g_h03);
    cudaGetSymbolAddress((void**)&h13, g_h13);
    cudaGetSymbolAddress((void**)&att3, g_att3);
    cudaGetSymbolAddress((void**)&att13, g_att13);
    cudaGetSymbolAddress((void**)&y03, g_y03);
    cudaGetSymbolAddress((void**)&y13, g_y13);
    cudaGetSymbolAddress((void**)&gu03, g_gu03);
    cudaGetSymbolAddress((void**)&gu13, g_gu13);
    cudaGetSymbolAddress((void**)&q3, g_q3);
    cudaGetSymbolAddress((void**)&k3, g_k3);
    cudaGetSymbolAddress((void**)&vt3, g_vt3);
    cudaGetSymbolAddress((void**)&p3, g_p3);
    cudaGetSymbolAddress((void**)&wq03, g_wq03);
    cudaGetSymbolAddress((void**)&wk03, g_wk03);
    cudaGetSymbolAddress((void**)&wv03, g_wv03);
    cudaGetSymbolAddress((void**)&wo03, g_wo03);
    cudaGetSymbolAddress((void**)&wg03, g_wg03);
    cudaGetSymbolAddress((void**)&wu03, g_wu03);
    cudaGetSymbolAddress((void**)&wd03, g_wd03);
    cudaGetSymbolAddress((void**)&wq13, g_wq13);
    cudaGetSymbolAddress((void**)&wk13, g_wk13);
    cudaGetSymbolAddress((void**)&wv13, g_wv13);
    cudaGetSymbolAddress((void**)&wo13, g_wo13);
    cudaGetSymbolAddress((void**)&wg13, g_wg13);
    cudaGetSymbolAddress((void**)&wu13, g_wu13);
    cudaGetSymbolAddress((void**)&wd13, g_wd13);

    const int M0 = B_ * S1_;   // 3072
    const int M1 = B_ * S2_;   // 256

    // ---- weight prep ----
    launch_tsplit(w_q0,    wq03, D0_, H_ * HD_);
    launch_tsplit(w_k0,    wk03, D0_, HD_);
    launch_tsplit(w_v0,    wv03, D0_, HD_);
    launch_tsplit(w_o0,    wo03, H_ * HD_, D0_);
    launch_tsplit(w_gate0, wg03, D0_, F0_);
    launch_tsplit(w_up0,   wu03, D0_, F0_);
    launch_tsplit(w_down0, wd03, F0_, D0_);
    launch_tsplit(w_q1,    wq13, D1_, H_ * HD_);
    launch_tsplit(w_k1,    wk13, D1_, HD_);
    launch_tsplit(w_v1,    wv13, D1_, HD_);
    launch_tsplit(w_o1,    wo13, H_ * HD_, D1_);
    launch_tsplit(w_gate1, wg13, D1_, F1_);
    launch_tsplit(w_up1,   wu13, D1_, F1_);
    launch_tsplit(w_down1, wd13, F1_, D1_);

    // ---- adaLN modulation + scans ----
    {
        dim3 mg((2 * D1_ + 255) / 256, B_);
        mod_kernel<<<mg, 256>>>(cond1, ada_in_w1,   ada_in_b1,   modin,   D1_, 2 * D1_);
        mod_kernel<<<mg, 256>>>(cond1, ada_post_w1, ada_post_b1, modpost, D1_, 2 * D1_);
    }
    scan_kernel<<<1, 32>>>(pad_masks, att_masks, pos, cs);

    // ---- input norms (bf16 triples) ----
    rmsnorm_kernel<<<M0, 256>>>(x0, h03, norm1_w0, 0, D0_, S1_);
    rmsnorm_kernel<<<M1, 256>>>(x1, h13, modin, 2 * D1_, D1_, S2_);

    // ---- QKV projections (all TC; outputs fp32 with row remap into S=832 layout) ----
    launch_tc(h03, wq03, q, M0, H_ * HD_, 3 * D0_, EPI_NONE, nullptr, S1_, S_, H_ * HD_);
    launch_tc(h03, wk03, k, M0, HD_, 3 * D0_, EPI_NONE, nullptr, S1_, S_, HD_);
    launch_tc(h03, wv03, v, M0, HD_, 3 * D0_, EPI_NONE, nullptr, S1_, S_, HD_);
    launch_tc(h13, wq13, q + (size_t)S1_ * H_ * HD_, M1, H_ * HD_, 3 * D1_, EPI_NONE,
              nullptr, S2_, S_, H_ * HD_);
    launch_tc(h13, wk13, k + (size_t)S1_ * HD_, M1, HD_, 3 * D1_, EPI_NONE,
              nullptr, S2_, S_, HD_);
    launch_tc(h13, wv13, v + (size_t)S1_ * HD_, M1, HD_, 3 * D1_, EPI_NONE,
              nullptr, S2_, S_, HD_);

    // ---- RoPE + attention operand splits ----
    {
        long nq = (long)B_ * H_ * S_ * 128;
        rope_qsplit_kernel<<<(unsigned)((nq + 255) / 256), 256>>>(q, pos, q3);
        long nk = (long)B_ * S_ * 128;
        rope_ksplit_kernel<<<(unsigned)((nk + 255) / 256), 256>>>(k, pos, k3);
        launch_tsplit(v, vt3, S_, HD_, B_, (size_t)S_ * HD_, (size_t)HD_ * 3 * S_);
    }

    // ---- scores = Q K^T * scale, masked (batched z = B*H) ----
    launch_tc(q3, k3, scores, S_, S_, 3 * HD_, EPI_SCORES,
              nullptr, S_, 0, S_, nullptr,
              B_ * H_, H_,
              (size_t)H_ * S_ * 3 * HD_, (size_t)S_ * 3 * HD_,
              (size_t)S_ * 3 * HD_, 0,
              (size_t)H_ * S_ * S_, (size_t)S_ * S_,
              cs, pad_masks, S_, 0.0625f);

    softmax_kernel<<<B_ * H_ * S_, 256>>>(scores);

    // ---- PV (batched) ----
    launch_split(scores, p3, B_ * H_ * S_, S_, B_ * H_ * S_, 0);
    launch_tc(p3, vt3, att, S_, HD_, 3 * S_, EPI_NONE,
              nullptr, S_, 0, H_ * HD_, nullptr,
              B_ * H_, H_,
              (size_t)H_ * S_ * 3 * S_, (size_t)S_ * 3 * S_,
              (size_t)HD_ * 3 * S_, 0,
              (size_t)S_ * H_ * HD_, (size_t)HD_);

    // ---- output projections ----
    launch_split(att, att3, M0, H_ * HD_, S1_, S_);
    launch_split(att + (size_t)S1_ * H_ * HD_, att13, M1, H_ * HD_, S2_, S_);
    launch_tc(att3, wo03, r0, M0, D0_, 3 * H_ * HD_, EPI_RES, x0);
    launch_tc(att13, wo13, r1, M1, D1_, 3 * H_ * HD_, EPI_RES_GATE, x1,
              0, 0, 0, nullptr, 1, 1, 0, 0, 0, 0, 0, 0,
              nullptr, nullptr, 0, 1.0f, modin + D1_, 2 * D1_, S2_);

    // ---- post norms ----
    rmsnorm_kernel<<<M0, 256>>>(r0, y03, norm2_w0, 0, D0_, S1_);
    rmsnorm_kernel<<<M1, 256>>>(r1, y13, modpost, 2 * D1_, D1_, S2_);

    // ---- MLP stream 0 ----
    launch_tc(y03, wg03, gu0, M0, F0_, 3 * D0_, EPI_NONE);
    launch_tc(y03, wu03, gu0, M0, F0_, 3 * D0_, EPI_GELUMUL_SP, gu0, 0, 0, 0, gu03);
    launch_tc(gu03, wd03, out0, M0, D0_, 3 * F0_, EPI_RES, r0);

    // ---- MLP stream 1 ----
    launch_tc(y13, wg13, gu1, M1, F1_, 3 * D1_, EPI_NONE);
    launch_tc(y13, wu13, gu1, M1, F1_, 3 * D1_, EPI_GELUMUL_SP, gu1, 0, 0, 0, gu13);
    launch_tc(gu13, wd13, out1, M1, D1_, 3 * F1_, EPI_RES_GATE, r1,
              0, 0, 0, nullptr, 1, 1, 0, 0, 0, 0, 0, 0,
              nullptr, nullptr, 0, 1.0f, modpost + D1_, 2 * D1_, S2_);
}

// round 7
// speedup vs baseline: 2.1268x; 1.4172x over previous
#include <cuda_runtime.h>
#include <cuda_bf16.h>
#include <math.h>
#include <stdint.h>

// ---------------- problem constants ----------------
#define B_   4
#define S1_  768
#define S2_  64
#define S_   832
#define D0_  2048
#define F0_  16384
#define D1_  1024
#define F1_  4096
#define H_   8
#define HD_  256
#define EPS_ 1e-6f
#define MASK_VAL_ -1000000000.0f

// ---------------- scratch (device globals) ----------------
__device__ float g_mod_in[B_*2*D1_];
__device__ float g_mod_post[B_*2*D1_];
__device__ float g_hc0[(size_t)B_*S1_*D0_];     // tf32-rounded norm1 out
__device__ float g_hc1[B_*S2_*D1_];
__device__ float g_q[(size_t)B_*S_*H_*HD_];
__device__ float g_k[B_*S_*HD_];
__device__ float g_v[B_*S_*HD_];
__device__ float g_qr[(size_t)B_*H_*S_*HD_];    // rope'd + tf32
__device__ float g_kr[B_*S_*HD_];               // rope'd + tf32
__device__ float g_vt[B_*HD_*S_];               // transposed + tf32
__device__ float g_scores[(size_t)B_*H_*S_*S_];
__device__ float g_att[(size_t)B_*S_*H_*HD_];   // tf32 (PV epilogue cvt)
__device__ float g_r0[B_*S1_*D0_];
__device__ float g_r1[B_*S2_*D1_];
__device__ float g_yc0[(size_t)B_*S1_*D0_];     // tf32 norm2 out
__device__ float g_yc1[B_*S2_*D1_];
__device__ float g_gu0[(size_t)B_*S1_*F0_];
__device__ float g_gu1[B_*S2_*F1_];
__device__ int   g_pos[B_*S_];
__device__ int   g_cs[B_*S_];
// transposed tf32 weights [N, K]
__device__ float g_wq0t[(size_t)2048*2048];
__device__ float g_wk0t[(size_t)256*2048];
__device__ float g_wv0t[(size_t)256*2048];
__device__ float g_wo0t[(size_t)2048*2048];
__device__ float g_wg0t[(size_t)16384*2048];
__device__ float g_wu0t[(size_t)16384*2048];
__device__ float g_wd0t[(size_t)2048*16384];
__device__ float g_wq1t[(size_t)2048*1024];
__device__ float g_wk1t[(size_t)256*1024];
__device__ float g_wv1t[(size_t)256*1024];
__device__ float g_wo1t[(size_t)1024*2048];
__device__ float g_wg1t[(size_t)4096*1024];
__device__ float g_wu1t[(size_t)4096*1024];
__device__ float g_wd1t[(size_t)1024*4096];

// ---------------- helpers ----------------
__device__ __forceinline__ float gelu_tanh(float x) {
    float x3 = x * x * x;
    return 0.5f * x * (1.0f + tanhf(0.79788456080286535588f * (x + 0.044715f * x3)));
}
__device__ __forceinline__ float to_tf32(float x) {
    float r;
    asm("cvt.rna.tf32.f32 %0, %1;" : "=f"(r) : "f"(x));
    return r;
}
__device__ __forceinline__ uint32_t smem_u32(const void* p) {
    uint32_t a;
    asm("{ .reg .u64 t; cvta.to.shared.u64 t, %1; cvt.u32.u64 %0, t; }" : "=r"(a) : "l"(p));
    return a;
}
#define CP_ASYNC16(sm, gm) \
    asm volatile("cp.async.cg.shared.global [%0], [%1], 16;" :: "r"(sm), "l"(gm))
#define CP_COMMIT() asm volatile("cp.async.commit_group;")
#define CP_WAIT(n)  asm volatile("cp.async.wait_group %0;" :: "n"(n))

__device__ __forceinline__ void ldsm_x4(uint32_t* r, uint32_t addr) {
    asm volatile("ldmatrix.sync.aligned.m8n8.x4.shared.b16 {%0,%1,%2,%3}, [%4];"
                 : "=r"(r[0]), "=r"(r[1]), "=r"(r[2]), "=r"(r[3]) : "r"(addr));
}
__device__ __forceinline__ void mma_tf32(float* c, const uint32_t* a, uint32_t b0, uint32_t b1) {
    asm volatile("mma.sync.aligned.m16n8k8.row.col.f32.tf32.tf32.f32 "
                 "{%0,%1,%2,%3}, {%4,%5,%6,%7}, {%8,%9}, {%0,%1,%2,%3};"
                 : "+f"(c[0]), "+f"(c[1]), "+f"(c[2]), "+f"(c[3])
                 : "r"(a[0]), "r"(a[1]), "r"(a[2]), "r"(a[3]), "r"(b0), "r"(b1));
}
// swizzled chunk address within a [rows x 32 float] tile: 8 x 16B chunks/row, chunk^(row&7)
__device__ __forceinline__ uint32_t sw_addr(uint32_t base, int row, int chunk) {
    return base + (uint32_t)(((row << 3) + (chunk ^ (row & 7))) << 4);
}

// ---------------- epilogue modes ----------------
#define EPI_NONE        0
#define EPI_SCORES      1
#define EPI_RES         2
#define EPI_RES_GATE    3
#define EPI_CVT         4   // store tf32-rounded
#define EPI_GELUMUL_CVT 5   // v = tf32(gelu(aux)*v) (aux may alias C)

// ---------------- TC tf32 GEMM: C[M,N] = A[M,Kp] * Bt[N,Kp]^T ----------------
// 128x128 CTA tile, 8 warps (2x4), warp 64x32, BK=32 floats, 3-stage cp.async, 96KB (2 CTA/SM)
struct TcP {
    const float* A; const float* Bt; float* C;
    const float* aux; const float* gvec;
    const int *cs, *pad;
    size_t zA1, zA2, zB1, zB2, zC1, zC2, zAux, zGv;
    int zdiv;
    int gstride, gdiv;
    int maskStride; float scale;
    int M, N, Kp, epi;
    int rpb, obatch, ldc;
};

#define TC_STAGES 3
#define TC_STAGE_BYTES 32768    // 16KB A + 16KB B
#define TC_SMEM (TC_STAGES * TC_STAGE_BYTES)

__global__ __launch_bounds__(256) void tc_gemm_kernel(TcP p) {
    extern __shared__ char dsm[];
    uint32_t sbase = smem_u32(dsm);

    int tid  = threadIdx.x;
    int wid  = tid >> 5;
    int lane = tid & 31;
    int wm = wid >> 2;
    int wn = wid & 3;

    int m0 = blockIdx.y * 128;
    int n0 = blockIdx.x * 128;
    int z  = blockIdx.z;
    int zb = z / p.zdiv;
    int zr = z - zb * p.zdiv;

    const float* Ab = p.A  + (size_t)zb * p.zA1 + (size_t)zr * p.zA2;
    const float* Bb = p.Bt + (size_t)zb * p.zB1 + (size_t)zr * p.zB2;
    float* Cz = p.C + (size_t)zb * p.zC1 + (size_t)zr * p.zC2;

    int kc = tid & 7;
    int rb = tid >> 3;

    float acc[4][4][4];
    #pragma unroll
    for (int i = 0; i < 4; i++)
        #pragma unroll
        for (int j = 0; j < 4; j++)
            #pragma unroll
            for (int e = 0; e < 4; e++) acc[i][j][e] = 0.f;

    int nIter = p.Kp >> 5;

    auto issue = [&](int it) {
        int st = it % TC_STAGES;
        uint32_t sa = sbase + st * TC_STAGE_BYTES;
        uint32_t sb = sa + 16384;
        int k0 = it << 5;
        #pragma unroll
        for (int i = 0; i < 4; i++) {
            int row = rb + i * 32;
            int ra = m0 + row; if (ra > p.M - 1) ra = p.M - 1;
            CP_ASYNC16(sw_addr(sa, row, kc), Ab + (size_t)ra * p.Kp + k0 + kc * 4);
            int rn = n0 + row; if (rn > p.N - 1) rn = p.N - 1;
            CP_ASYNC16(sw_addr(sb, row, kc), Bb + (size_t)rn * p.Kp + k0 + kc * 4);
        }
        CP_COMMIT();
    };

    #pragma unroll
    for (int s = 0; s < TC_STAGES - 1; s++) issue(s);

    int grp = lane >> 3;
    int lr  = lane & 7;

    for (int it = 0; it < nIter; it++) {
        if (it + TC_STAGES - 1 < nIter) {
            issue(it + TC_STAGES - 1);
            CP_WAIT(TC_STAGES - 2);
        } else {
            CP_WAIT(0);
        }
        __syncthreads();

        int st = it % TC_STAGES;
        uint32_t sa = sbase + st * TC_STAGE_BYTES;
        uint32_t sb = sa + 16384;

        #pragma unroll
        for (int kb = 0; kb < 4; kb++) {
            int chA = 2 * kb + (grp >> 1);
            uint32_t a[4][4];
            #pragma unroll
            for (int mi = 0; mi < 4; mi++) {
                int row = wm * 64 + mi * 16 + (grp & 1) * 8 + lr;
                ldsm_x4(a[mi], sw_addr(sa, row, chA));
            }
            uint32_t bf[2][4];
            #pragma unroll
            for (int bi = 0; bi < 2; bi++) {
                int row = wn * 32 + bi * 16 + (grp & 1) * 8 + lr;
                ldsm_x4(bf[bi], sw_addr(sb, row, chA));
            }
            #pragma unroll
            for (int mi = 0; mi < 4; mi++)
                #pragma unroll
                for (int ni = 0; ni < 4; ni++) {
                    int bi = ni >> 1, wh = ni & 1;
                    mma_tf32(acc[mi][ni], a[mi], bf[bi][wh], bf[bi][wh + 2]);
                }
        }
        __syncthreads();
    }

    // ---- epilogue ----
    const int* csb  = p.cs  ? p.cs  + (size_t)zb * p.maskStride : nullptr;
    const int* padb = p.pad ? p.pad + (size_t)zb * p.maskStride : nullptr;
    const float* auxz = p.aux ? p.aux + (size_t)zb * p.zAux : nullptr;
    const float* gvz  = p.gvec ? p.gvec + (size_t)zb * p.zGv : nullptr;
    int qrow = lane >> 2;
    int qcol = (lane & 3) * 2;
    #pragma unroll
    for (int mi = 0; mi < 4; mi++) {
        #pragma unroll
        for (int half = 0; half < 2; half++) {
            int r = m0 + wm * 64 + mi * 16 + half * 8 + qrow;
            if (r >= p.M) continue;
            int orow = (r / p.rpb) * p.obatch + (r % p.rpb);
            #pragma unroll
            for (int ni = 0; ni < 4; ni++) {
                int col = n0 + wn * 32 + ni * 8 + qcol;
                if (col >= p.N) continue;
                float v0 = acc[mi][ni][half * 2 + 0];
                float v1 = acc[mi][ni][half * 2 + 1];
                if (p.epi == EPI_SCORES) {
                    int csr = csb[r];
                    bool okr = padb[r] != 0;
                    bool ok0 = (csb[col] <= csr) && okr && (padb[col] != 0);
                    bool ok1 = (csb[col + 1] <= csr) && okr && (padb[col + 1] != 0);
                    v0 = ok0 ? v0 * p.scale : MASK_VAL_;
                    v1 = ok1 ? v1 * p.scale : MASK_VAL_;
                } else if (p.epi == EPI_RES) {
                    float2 ax = *(const float2*)&auxz[(size_t)r * p.N + col];
                    v0 += ax.x; v1 += ax.y;
                } else if (p.epi == EPI_RES_GATE) {
                    float2 ax = *(const float2*)&auxz[(size_t)r * p.N + col];
                    float2 gx = *(const float2*)&gvz[(size_t)(r / p.gdiv) * p.gstride + col];
                    v0 = ax.x + gx.x * v0;
                    v1 = ax.y + gx.y * v1;
                } else if (p.epi == EPI_CVT) {
                    v0 = to_tf32(v0); v1 = to_tf32(v1);
                } else if (p.epi == EPI_GELUMUL_CVT) {
                    float2 ax = *(const float2*)&auxz[(size_t)r * p.N + col];
                    v0 = to_tf32(gelu_tanh(ax.x) * v0);
                    v1 = to_tf32(gelu_tanh(ax.y) * v1);
                }
                *(float2*)&Cz[(size_t)orow * p.ldc + col] = make_float2(v0, v1);
            }
        }
    }
}

// ---------------- weight/V transpose with tf32 rounding ----------------
// out[n*K + k] = tf32(W[k*N + n]); batched via grid.z
__global__ void wtrans_kernel(const float* __restrict__ W, float* __restrict__ out,
                              int K, int N, size_t inZ, size_t outZ) {
    W   += blockIdx.z * inZ;
    out += blockIdx.z * outZ;
    __shared__ float t[32][33];
    int k0 = blockIdx.y * 32, n0 = blockIdx.x * 32;
    int tx = threadIdx.x, ty = threadIdx.y;   // 32 x 8
    #pragma unroll
    for (int i = 0; i < 4; i++)
        t[ty + i * 8][tx] = W[(size_t)(k0 + ty + i * 8) * N + n0 + tx];
    __syncthreads();
    #pragma unroll
    for (int i = 0; i < 4; i++) {
        int n = n0 + ty + i * 8;
        int k = k0 + tx;
        out[(size_t)n * K + k] = to_tf32(t[tx][ty + i * 8]);
    }
}

// RoPE + tf32 for Q: q[B,S,H,HD] -> qr[B,H,S,HD]
__global__ void rope_q_kernel(const float* __restrict__ q, const int* __restrict__ pos,
                              float* __restrict__ out) {
    long idx = blockIdx.x * (long)blockDim.x + threadIdx.x;
    if (idx >= (long)B_ * H_ * S_ * 128) return;
    int i = (int)(idx & 127);
    long t = idx >> 7;
    int s = (int)(t % S_); t /= S_;
    int h = (int)(t % H_);
    int b = (int)(t / H_);
    const float* base = q + ((size_t)(b * S_ + s) * H_ + h) * HD_;
    float x1 = base[i], x2 = base[i + 128];
    float f = (float)pos[b * S_ + s] * expf(-((float)i / 128.0f) * 9.210340371976184f);
    float sn, c; sincosf(f, &sn, &c);
    float* ob = out + ((size_t)(b * H_ + h) * S_ + s) * HD_;
    ob[i]       = to_tf32(x1 * c - x2 * sn);
    ob[i + 128] = to_tf32(x2 * c + x1 * sn);
}

// RoPE + tf32 for K (in k layout [B,S,HD])
__global__ void rope_k_kernel(const float* __restrict__ k, const int* __restrict__ pos,
                              float* __restrict__ out) {
    long idx = blockIdx.x * (long)blockDim.x + threadIdx.x;
    if (idx >= (long)B_ * S_ * 128) return;
    int i = (int)(idx & 127);
    long t = idx >> 7;
    int s = (int)(t % S_);
    int b = (int)(t / S_);
    const float* base = k + (size_t)(b * S_ + s) * HD_;
    float x1 = base[i], x2 = base[i + 128];
    float f = (float)pos[b * S_ + s] * expf(-((float)i / 128.0f) * 9.210340371976184f);
    float sn, c; sincosf(f, &sn, &c);
    float* ob = out + (size_t)(b * S_ + s) * HD_;
    ob[i]       = to_tf32(x1 * c - x2 * sn);
    ob[i + 128] = to_tf32(x2 * c + x1 * sn);
}

// ---------------- mod GEMV ----------------
__global__ void mod_kernel(const float* __restrict__ cond, const float* __restrict__ W,
                           const float* __restrict__ bias, float* __restrict__ out,
                           int D, int N) {
    int j = blockIdx.x * blockDim.x + threadIdx.x;
    int b = blockIdx.y;
    if (j >= N) return;
    float s = bias[j];
    const float* c = cond + (size_t)b * D;
    for (int kk = 0; kk < D; kk++)
        s += c[kk] * W[(size_t)kk * N + j];
    out[(size_t)b * N + j] = s;
}

// ---------------- prefix scans ----------------
__global__ void scan_kernel(const int* __restrict__ pad, const int* __restrict__ att,
                            int* __restrict__ pos, int* __restrict__ cs) {
    int b = threadIdx.x;
    if (b >= B_) return;
    int cp = 0, ca = 0;
    for (int s = 0; s < S_; s++) {
        cp += pad[b * S_ + s];
        ca += att[b * S_ + s];
        pos[b * S_ + s] = cp - 1;
        cs[b * S_ + s] = ca;
    }
}

// ---------------- RMSNorm -> tf32-rounded fp32 ----------------
__global__ void rmsnorm_kernel(const float* __restrict__ x, float* __restrict__ out,
                               const float* __restrict__ w, int wStride,
                               int D, int rowsPerBatch) {
    long row = blockIdx.x;
    int b = (int)(row / rowsPerBatch);
    const float* xp = x + row * (long)D;
    float ss = 0.f;
    for (int i = threadIdx.x; i < D; i += blockDim.x) {
        float v = xp[i];
        ss += v * v;
    }
    __shared__ float red[256];
    red[threadIdx.x] = ss;
    __syncthreads();
    for (int s = 128; s > 0; s >>= 1) {
        if (threadIdx.x < s) red[threadIdx.x] += red[threadIdx.x + s];
        __syncthreads();
    }
    float r = rsqrtf(red[0] / (float)D + EPS_);
    const float* wp = w + (size_t)b * wStride;
    float* op = out + row * (long)D;
    for (int i = threadIdx.x; i < D; i += blockDim.x)
        op[i] = to_tf32(xp[i] * r * (1.0f + wp[i]));
}

// ---------------- row softmax (writes tf32-rounded probs) ----------------
__global__ void softmax_kernel(float* __restrict__ scores) {
    float* p = scores + (size_t)blockIdx.x * S_;
    __shared__ float red[256];
    int tid = threadIdx.x;
    float m = -3.4e38f;
    for (int i = tid; i < S_; i += 256) m = fmaxf(m, p[i]);
    red[tid] = m;
    __syncthreads();
    for (int s = 128; s > 0; s >>= 1) {
        if (tid < s) red[tid] = fmaxf(red[tid], red[tid + s]);
        __syncthreads();
    }
    m = red[0];
    __syncthreads();
    float sum = 0.f;
    for (int i = tid; i < S_; i += 256) {
        float e = expf(p[i] - m);
        p[i] = e;
        sum += e;
    }
    red[tid] = sum;
    __syncthreads();
    for (int s = 128; s > 0; s >>= 1) {
        if (tid < s) red[tid] += red[tid + s];
        __syncthreads();
    }
    float inv = 1.0f / red[0];
    for (int i = tid; i < S_; i += 256) p[i] = to_tf32(p[i] * inv);
}

// ---------------- host helper ----------------
struct TcArgs {
    const float* A; const float* Bt; float* C;
    int M, N, Kp, epi;
    const float* aux = nullptr;
    int rpb = 0, obatch = 0, ldc = 0;
    int zcount = 1, zdiv = 1;
    size_t zA1 = 0, zA2 = 0, zB1 = 0, zB2 = 0, zC1 = 0, zC2 = 0, zAux = 0, zGv = 0;
    const int* cs = nullptr; const int* pad = nullptr;
    int maskStride = 0; float scale = 1.0f;
    const float* gvec = nullptr; int gstride = 0, gdiv = 1;
};

static void launch_tc(const TcArgs& a) {
    cudaFuncSetAttribute(tc_gemm_kernel, cudaFuncAttributeMaxDynamicSharedMemorySize, TC_SMEM);
    TcP p;
    p.A = a.A; p.Bt = a.Bt; p.C = a.C; p.aux = a.aux; p.gvec = a.gvec;
    p.cs = a.cs; p.pad = a.pad;
    p.zA1 = a.zA1; p.zA2 = a.zA2; p.zB1 = a.zB1; p.zB2 = a.zB2;
    p.zC1 = a.zC1; p.zC2 = a.zC2; p.zAux = a.zAux; p.zGv = a.zGv;
    p.zdiv = a.zdiv; p.gstride = a.gstride; p.gdiv = a.gdiv;
    p.maskStride = a.maskStride; p.scale = a.scale;
    p.M = a.M; p.N = a.N; p.Kp = a.Kp; p.epi = a.epi;
    p.rpb = a.rpb ? a.rpb : a.M; p.obatch = a.obatch; p.ldc = a.ldc ? a.ldc : a.N;
    dim3 grid((a.N + 127) / 128, (a.M + 127) / 128, a.zcount);
    tc_gemm_kernel<<<grid, 256, TC_SMEM>>>(p);
}

static void launch_wtrans(const float* W, float* out, int K, int N,
                          int z = 1, size_t inZ = 0, size_t outZ = 0) {
    dim3 grid(N / 32, K / 32, z);
    wtrans_kernel<<<grid, dim3(32, 8)>>>(W, out, K, N, inZ, outZ);
}

extern "C" void kernel_launch(void* const* d_in, const int* in_sizes, int n_in,
                              void* d_out, int out_size) {
    const float* x0         = (const float*)d_in[0];
    const float* x1         = (const float*)d_in[1];
    const float* cond1      = (const float*)d_in[2];
    const float* w_q0       = (const float*)d_in[3];
    const float* w_k0       = (const float*)d_in[4];
    const float* w_v0       = (const float*)d_in[5];
    const float* w_o0       = (const float*)d_in[6];
    const float* norm1_w0   = (const float*)d_in[7];
    const float* norm2_w0   = (const float*)d_in[8];
    const float* w_gate0    = (const float*)d_in[9];
    const float* w_up0      = (const float*)d_in[10];
    const float* w_down0    = (const float*)d_in[11];
    const float* w_q1       = (const float*)d_in[12];
    const float* w_k1       = (const float*)d_in[13];
    const float* w_v1       = (const float*)d_in[14];
    const float* w_o1       = (const float*)d_in[15];
    const float* ada_in_w1  = (const float*)d_in[16];
    const float* ada_in_b1  = (const float*)d_in[17];
    const float* ada_post_w1= (const float*)d_in[18];
    const float* ada_post_b1= (const float*)d_in[19];
    const float* w_gate1    = (const float*)d_in[20];
    const float* w_up1      = (const float*)d_in[21];
    const float* w_down1    = (const float*)d_in[22];
    const int*   pad_masks  = (const int*)d_in[23];
    const int*   att_masks  = (const int*)d_in[24];

    float* out0 = (float*)d_out;
    float* out1 = out0 + (size_t)B_ * S1_ * D0_;

    float *modin, *modpost, *hc0, *hc1, *q, *k, *v, *qr, *kr, *vt, *scores, *att;
    float *r0, *r1, *yc0, *yc1, *gu0, *gu1;
    int *pos, *cs;
    float *wq0t, *wk0t, *wv0t, *wo0t, *wg0t, *wu0t, *wd0t;
    float *wq1t, *wk1t, *wv1t, *wo1t, *wg1t, *wu1t, *wd1t;
    cudaGetSymbolAddress((void**)&modin, g_mod_in);
    cudaGetSymbolAddress((void**)&modpost, g_mod_post);
    cudaGetSymbolAddress((void**)&hc0, g_hc0);
    cudaGetSymbolAddress((void**)&hc1, g_hc1);
    cudaGetSymbolAddress((void**)&q, g_q);
    cudaGetSymbolAddress((void**)&k, g_k);
    cudaGetSymbolAddress((void**)&v, g_v);
    cudaGetSymbolAddress((void**)&qr, g_qr);
    cudaGetSymbolAddress((void**)&kr, g_kr);
    cudaGetSymbolAddress((void**)&vt, g_vt);
    cudaGetSymbolAddress((void**)&scores, g_scores);
    cudaGetSymbolAddress((void**)&att, g_att);
    cudaGetSymbolAddress((void**)&r0, g_r0);
    cudaGetSymbolAddress((void**)&r1, g_r1);
    cudaGetSymbolAddress((void**)&yc0, g_yc0);
    cudaGetSymbolAddress((void**)&yc1, g_yc1);
    cudaGetSymbolAddress((void**)&gu0, g_gu0);
    cudaGetSymbolAddress((void**)&gu1, g_gu1);
    cudaGetSymbolAddress((void**)&pos, g_pos);
    cudaGetSymbolAddress((void**)&cs, g_cs);
    cudaGetSymbolAddress((void**)&wq0t, g_wq0t);
    cudaGetSymbolAddress((void**)&wk0t, g_wk0t);
    cudaGetSymbolAddress((void**)&wv0t, g_wv0t);
    cudaGetSymbolAddress((void**)&wo0t, g_wo0t);
    cudaGetSymbolAddress((void**)&wg0t, g_wg0t);
    cudaGetSymbolAddress((void**)&wu0t, g_wu0t);
    cudaGetSymbolAddress((void**)&wd0t, g_wd0t);
    cudaGetSymbolAddress((void**)&wq1t, g_wq1t);
    cudaGetSymbolAddress((void**)&wk1t, g_wk1t);
    cudaGetSymbolAddress((void**)&wv1t, g_wv1t);
    cudaGetSymbolAddress((void**)&wo1t, g_wo1t);
    cudaGetSymbolAddress((void**)&wg1t, g_wg1t);
    cudaGetSymbolAddress((void**)&wu1t, g_wu1t);
    cudaGetSymbolAddress((void**)&wd1t, g_wd1t);

    const int M0 = B_ * S1_;   // 3072
    const int M1 = B_ * S2_;   // 256

    // ---- weight prep (transpose + tf32 round) ----
    launch_wtrans(w_q0,    wq0t, D0_, H_ * HD_);
    launch_wtrans(w_k0,    wk0t, D0_, HD_);
    launch_wtrans(w_v0,    wv0t, D0_, HD_);
    launch_wtrans(w_o0,    wo0t, H_ * HD_, D0_);
    launch_wtrans(w_gate0, wg0t, D0_, F0_);
    launch_wtrans(w_up0,   wu0t, D0_, F0_);
    launch_wtrans(w_down0, wd0t, F0_, D0_);
    launch_wtrans(w_q1,    wq1t, D1_, H_ * HD_);
    launch_wtrans(w_k1,    wk1t, D1_, HD_);
    launch_wtrans(w_v1,    wv1t, D1_, HD_);
    launch_wtrans(w_o1,    wo1t, H_ * HD_, D1_);
    launch_wtrans(w_gate1, wg1t, D1_, F1_);
    launch_wtrans(w_up1,   wu1t, D1_, F1_);
    launch_wtrans(w_down1, wd1t, F1_, D1_);

    // ---- adaLN modulation + scans ----
    {
        dim3 mg((2 * D1_ + 255) / 256, B_);
        mod_kernel<<<mg, 256>>>(cond1, ada_in_w1,   ada_in_b1,   modin,   D1_, 2 * D1_);
        mod_kernel<<<mg, 256>>>(cond1, ada_post_w1, ada_post_b1, modpost, D1_, 2 * D1_);
    }
    scan_kernel<<<1, 32>>>(pad_masks, att_masks, pos, cs);

    // ---- input norms (tf32-rounded fp32) ----
    rmsnorm_kernel<<<M0, 256>>>(x0, hc0, norm1_w0, 0, D0_, S1_);
    rmsnorm_kernel<<<M1, 256>>>(x1, hc1, modin, 2 * D1_, D1_, S2_);

    // ---- QKV projections (row remap into S=832 layout) ----
    { TcArgs a{hc0, wq0t, q, M0, H_ * HD_, D0_, EPI_NONE};
      a.rpb = S1_; a.obatch = S_; a.ldc = H_ * HD_; launch_tc(a); }
    { TcArgs a{hc0, wk0t, k, M0, HD_, D0_, EPI_NONE};
      a.rpb = S1_; a.obatch = S_; a.ldc = HD_; launch_tc(a); }
    { TcArgs a{hc0, wv0t, v, M0, HD_, D0_, EPI_NONE};
      a.rpb = S1_; a.obatch = S_; a.ldc = HD_; launch_tc(a); }
    { TcArgs a{hc1, wq1t, q + (size_t)S1_ * H_ * HD_, M1, H_ * HD_, D1_, EPI_NONE};
      a.rpb = S2_; a.obatch = S_; a.ldc = H_ * HD_; launch_tc(a); }
    { TcArgs a{hc1, wk1t, k + (size_t)S1_ * HD_, M1, HD_, D1_, EPI_NONE};
      a.rpb = S2_; a.obatch = S_; a.ldc = HD_; launch_tc(a); }
    { TcArgs a{hc1, wv1t, v + (size_t)S1_ * HD_, M1, HD_, D1_, EPI_NONE};
      a.rpb = S2_; a.obatch = S_; a.ldc = HD_; launch_tc(a); }

    // ---- RoPE (+tf32) and V transpose ----
    {
        long nq = (long)B_ * H_ * S_ * 128;
        rope_q_kernel<<<(unsigned)((nq + 255) / 256), 256>>>(q, pos, qr);
        long nk = (long)B_ * S_ * 128;
        rope_k_kernel<<<(unsigned)((nk + 255) / 256), 256>>>(k, pos, kr);
        launch_wtrans(v, vt, S_, HD_, B_, (size_t)S_ * HD_, (size_t)HD_ * S_);
    }

    // ---- scores = Q K^T * scale, masked (z = B*H) ----
    { TcArgs a{qr, kr, scores, S_, S_, HD_, EPI_SCORES};
      a.zcount = B_ * H_; a.zdiv = H_;
      a.zA1 = (size_t)H_ * S_ * HD_; a.zA2 = (size_t)S_ * HD_;
      a.zB1 = (size_t)S_ * HD_;
      a.zC1 = (size_t)H_ * S_ * S_; a.zC2 = (size_t)S_ * S_;
      a.cs = cs; a.pad = pad_masks; a.maskStride = S_; a.scale = 0.0625f;
      launch_tc(a); }

    softmax_kernel<<<B_ * H_ * S_, 256>>>(scores);

    // ---- PV (z = B*H) -> att [B,S,H*HD], tf32-rounded ----
    { TcArgs a{scores, vt, att, S_, HD_, S_, EPI_CVT};
      a.ldc = H_ * HD_;
      a.zcount = B_ * H_; a.zdiv = H_;
      a.zA1 = (size_t)H_ * S_ * S_; a.zA2 = (size_t)S_ * S_;
      a.zB1 = (size_t)HD_ * S_;
      a.zC1 = (size_t)S_ * H_ * HD_; a.zC2 = (size_t)HD_;
      launch_tc(a); }

    // ---- output projections (z = B; skips the 832-row layout) ----
    { TcArgs a{att, wo0t, r0, S1_, D0_, H_ * HD_, EPI_RES};
      a.aux = x0;
      a.zcount = B_;
      a.zA1 = (size_t)S_ * H_ * HD_; a.zC1 = (size_t)S1_ * D0_; a.zAux = (size_t)S1_ * D0_;
      launch_tc(a); }
    { TcArgs a{att + (size_t)S1_ * H_ * HD_, wo1t, r1, S2_, D1_, H_ * HD_, EPI_RES_GATE};
      a.aux = x1;
      a.zcount = B_;
      a.zA1 = (size_t)S_ * H_ * HD_; a.zC1 = (size_t)S2_ * D1_; a.zAux = (size_t)S2_ * D1_;
      a.gvec = modin + D1_; a.zGv = (size_t)2 * D1_; a.gdiv = S2_; a.gstride = 0;
      launch_tc(a); }

    // ---- post norms ----
    rmsnorm_kernel<<<M0, 256>>>(r0, yc0, norm2_w0, 0, D0_, S1_);
    rmsnorm_kernel<<<M1, 256>>>(r1, yc1, modpost, 2 * D1_, D1_, S2_);

    // ---- MLP stream 0 ----
    { TcArgs a{yc0, wg0t, gu0, M0, F0_, D0_, EPI_NONE}; launch_tc(a); }
    { TcArgs a{yc0, wu0t, gu0, M0, F0_, D0_, EPI_GELUMUL_CVT}; a.aux = gu0; launch_tc(a); }
    { TcArgs a{gu0, wd0t, out0, M0, D0_, F0_, EPI_RES}; a.aux = r0; launch_tc(a); }

    // ---- MLP stream 1 ----
    { TcArgs a{yc1, wg1t, gu1, M1, F1_, D1_, EPI_NONE}; launch_tc(a); }
    { TcArgs a{yc1, wu1t, gu1, M1, F1_, D1_, EPI_GELUMUL_CVT}; a.aux = gu1; launch_tc(a); }
    { TcArgs a{gu1, wd1t, out1, M1, D1_, F1_, EPI_RES_GATE};
      a.aux = r1;
      a.gvec = modpost + D1_; a.gstride = 2 * D1_; a.gdiv = S2_;
      launch_tc(a); }
}

// round 8
// speedup vs baseline: 3.6998x; 1.7396x over previous
#include <cuda_runtime.h>
#include <cuda_fp16.h>
#include <math.h>
#include <stdint.h>

// ---------------- problem constants ----------------
#define B_   4
#define S1_  768
#define S2_  64
#define S_   832
#define D0_  2048
#define F0_  16384
#define D1_  1024
#define F1_  4096
#define H_   8
#define HD_  256
#define EPS_ 1e-6f
#define MASK_VAL_ -1000000000.0f

// ---------------- scratch (device globals) ----------------
__device__ float g_mod_in[B_*2*D1_];
__device__ float g_mod_post[B_*2*D1_];
__device__ float g_q[(size_t)B_*S_*H_*HD_];
__device__ float g_k[B_*S_*HD_];
__device__ float g_v[B_*S_*HD_];
__device__ float g_scores[(size_t)B_*H_*S_*S_];
__device__ float g_r0[B_*S1_*D0_];
__device__ float g_r1[B_*S2_*D1_];
__device__ float g_gu0[(size_t)B_*S1_*F0_];
__device__ float g_gu1[B_*S2_*F1_];
__device__ int   g_pos[B_*S_];
__device__ int   g_cs[B_*S_];
// fp16 operands
__device__ __half g_hc0[(size_t)B_*S1_*D0_];
__device__ __half g_hc1[B_*S2_*D1_];
__device__ __half g_qr[(size_t)B_*H_*S_*HD_];
__device__ __half g_kr[B_*S_*HD_];
__device__ __half g_vt[B_*HD_*S_];
__device__ __half g_ph[(size_t)B_*H_*S_*S_];
__device__ __half g_atth[(size_t)B_*S_*H_*HD_];
__device__ __half g_yc0[(size_t)B_*S1_*D0_];
__device__ __half g_yc1[B_*S2_*D1_];
__device__ __half g_gu0h[(size_t)B_*S1_*F0_];
__device__ __half g_gu1h[B_*S2_*F1_];
// transposed fp16 weights [N, K]
__device__ __half g_wq0t[(size_t)2048*2048];
__device__ __half g_wk0t[(size_t)256*2048];
__device__ __half g_wv0t[(size_t)256*2048];
__device__ __half g_wo0t[(size_t)2048*2048];
__device__ __half g_wg0t[(size_t)16384*2048];
__device__ __half g_wu0t[(size_t)16384*2048];
__device__ __half g_wd0t[(size_t)2048*16384];
__device__ __half g_wq1t[(size_t)2048*1024];
__device__ __half g_wk1t[(size_t)256*1024];
__device__ __half g_wv1t[(size_t)256*1024];
__device__ __half g_wo1t[(size_t)1024*2048];
__device__ __half g_wg1t[(size_t)4096*1024];
__device__ __half g_wu1t[(size_t)4096*1024];
__device__ __half g_wd1t[(size_t)1024*4096];

// ---------------- helpers ----------------
__device__ __forceinline__ float gelu_tanh(float x) {
    float x3 = x * x * x;
    return 0.5f * x * (1.0f + tanhf(0.79788456080286535588f * (x + 0.044715f * x3)));
}
__device__ __forceinline__ uint32_t smem_u32(const void* p) {
    uint32_t a;
    asm("{ .reg .u64 t; cvta.to.shared.u64 t, %1; cvt.u32.u64 %0, t; }" : "=r"(a) : "l"(p));
    return a;
}
#define CP_ASYNC16(sm, gm) \
    asm volatile("cp.async.cg.shared.global [%0], [%1], 16;" :: "r"(sm), "l"(gm))
#define CP_COMMIT() asm volatile("cp.async.commit_group;")
#define CP_WAIT(n)  asm volatile("cp.async.wait_group %0;" :: "n"(n))

__device__ __forceinline__ void ldsm_x4(uint32_t* r, uint32_t addr) {
    asm volatile("ldmatrix.sync.aligned.m8n8.x4.shared.b16 {%0,%1,%2,%3}, [%4];"
                 : "=r"(r[0]), "=r"(r[1]), "=r"(r[2]), "=r"(r[3]) : "r"(addr));
}
__device__ __forceinline__ void mma_f16(float* c, const uint32_t* a, uint32_t b0, uint32_t b1) {
    asm volatile("mma.sync.aligned.m16n8k16.row.col.f32.f16.f16.f32 "
                 "{%0,%1,%2,%3}, {%4,%5,%6,%7}, {%8,%9}, {%0,%1,%2,%3};"
                 : "+f"(c[0]), "+f"(c[1]), "+f"(c[2]), "+f"(c[3])
                 : "r"(a[0]), "r"(a[1]), "r"(a[2]), "r"(a[3]), "r"(b0), "r"(b1));
}
// swizzled chunk address within a [rows x 64 half] tile: 8 x 16B chunks/row, chunk^(row&7)
__device__ __forceinline__ uint32_t sw_addr(uint32_t base, int row, int chunk) {
    return base + (uint32_t)(((row << 3) + (chunk ^ (row & 7))) << 4);
}

// ---------------- epilogue modes ----------------
#define EPI_NONE       0   // fp32 C
#define EPI_SCORES     1   // fp32 C, mask+scale
#define EPI_RES        2   // fp32 C = aux + v
#define EPI_RES_GATE   3   // fp32 C = aux + gvec*v
#define EPI_H          4   // half Ch = v
#define EPI_GELUMUL_H  5   // half Ch = gelu(aux)*v

// ---------------- TC fp16 GEMM: C[M,N] = A[M,Kp] * Bt[N,Kp]^T ----------------
// 128x128 CTA tile, 8 warps (2x4), warp 64x32, BK=64 halves, 3-stage cp.async, 96KB (2 CTA/SM)
struct TcP {
    const __half* A; const __half* Bt;
    float* C; __half* Ch;
    const float* aux; const float* gvec;
    const int *cs, *pad;
    size_t zA1, zA2, zB1, zB2, zC1, zC2, zAux, zGv;
    int zdiv;
    int gstride, gdiv;
    int maskStride; float scale;
    int M, N, Kp, epi;
    int rpb, obatch, ldc;
};

#define TC_STAGES 3
#define TC_STAGE_BYTES 32768    // 16KB A + 16KB B
#define TC_SMEM (TC_STAGES * TC_STAGE_BYTES)

__global__ __launch_bounds__(256) void tc_gemm_kernel(TcP p) {
    extern __shared__ char dsm[];
    uint32_t sbase = smem_u32(dsm);

    int tid  = threadIdx.x;
    int wid  = tid >> 5;
    int lane = tid & 31;
    int wm = wid >> 2;
    int wn = wid & 3;

    int m0 = blockIdx.y * 128;
    int n0 = blockIdx.x * 128;
    int z  = blockIdx.z;
    int zb = z / p.zdiv;
    int zr = z - zb * p.zdiv;

    const __half* Ab = p.A  + (size_t)zb * p.zA1 + (size_t)zr * p.zA2;
    const __half* Bb = p.Bt + (size_t)zb * p.zB1 + (size_t)zr * p.zB2;

    int kc = tid & 7;
    int rb = tid >> 3;

    float acc[4][4][4];
    #pragma unroll
    for (int i = 0; i < 4; i++)
        #pragma unroll
        for (int j = 0; j < 4; j++)
            #pragma unroll
            for (int e = 0; e < 4; e++) acc[i][j][e] = 0.f;

    int nIter = p.Kp >> 6;

    auto issue = [&](int it) {
        int st = it % TC_STAGES;
        uint32_t sa = sbase + st * TC_STAGE_BYTES;
        uint32_t sb = sa + 16384;
        int k0 = it << 6;
        #pragma unroll
        for (int i = 0; i < 4; i++) {
            int row = rb + i * 32;
            int ra = m0 + row; if (ra > p.M - 1) ra = p.M - 1;
            CP_ASYNC16(sw_addr(sa, row, kc), Ab + (size_t)ra * p.Kp + k0 + kc * 8);
            int rn = n0 + row; if (rn > p.N - 1) rn = p.N - 1;
            CP_ASYNC16(sw_addr(sb, row, kc), Bb + (size_t)rn * p.Kp + k0 + kc * 8);
        }
        CP_COMMIT();
    };

    #pragma unroll
    for (int s = 0; s < TC_STAGES - 1; s++) issue(s);

    int grp = lane >> 3;
    int lr  = lane & 7;

    for (int it = 0; it < nIter; it++) {
        if (it + TC_STAGES - 1 < nIter) {
            issue(it + TC_STAGES - 1);
            CP_WAIT(TC_STAGES - 2);
        } else {
            CP_WAIT(0);
        }
        __syncthreads();

        int st = it % TC_STAGES;
        uint32_t sa = sbase + st * TC_STAGE_BYTES;
        uint32_t sb = sa + 16384;

        #pragma unroll
        for (int kb = 0; kb < 4; kb++) {
            int chA = 2 * kb + (grp >> 1);
            uint32_t a[4][4];
            #pragma unroll
            for (int mi = 0; mi < 4; mi++) {
                int row = wm * 64 + mi * 16 + (grp & 1) * 8 + lr;
                ldsm_x4(a[mi], sw_addr(sa, row, chA));
            }
            uint32_t bf[2][4];
            #pragma unroll
            for (int bi = 0; bi < 2; bi++) {
                int row = wn * 32 + bi * 16 + (grp & 1) * 8 + lr;
                ldsm_x4(bf[bi], sw_addr(sb, row, chA));
            }
            #pragma unroll
            for (int mi = 0; mi < 4; mi++)
                #pragma unroll
                for (int ni = 0; ni < 4; ni++) {
                    int bi = ni >> 1, wh = ni & 1;
                    mma_f16(acc[mi][ni], a[mi], bf[bi][wh], bf[bi][wh + 2]);
                }
        }
        __syncthreads();
    }

    // ---- epilogue ----
    const int* csb  = p.cs  ? p.cs  + (size_t)zb * p.maskStride : nullptr;
    const int* padb = p.pad ? p.pad + (size_t)zb * p.maskStride : nullptr;
    const float* auxz = p.aux ? p.aux + (size_t)zb * p.zAux : nullptr;
    const float* gvz  = p.gvec ? p.gvec + (size_t)zb * p.zGv : nullptr;
    float* Cz = p.C + (size_t)zb * p.zC1 + (size_t)zr * p.zC2;
    __half* Chz = p.Ch + (size_t)zb * p.zC1 + (size_t)zr * p.zC2;
    int qrow = lane >> 2;
    int qcol = (lane & 3) * 2;
    #pragma unroll
    for (int mi = 0; mi < 4; mi++) {
        #pragma unroll
        for (int half_ = 0; half_ < 2; half_++) {
            int r = m0 + wm * 64 + mi * 16 + half_ * 8 + qrow;
            if (r >= p.M) continue;
            int orow = (r / p.rpb) * p.obatch + (r % p.rpb);
            #pragma unroll
            for (int ni = 0; ni < 4; ni++) {
                int col = n0 + wn * 32 + ni * 8 + qcol;
                if (col >= p.N) continue;
                float v0 = acc[mi][ni][half_ * 2 + 0];
                float v1 = acc[mi][ni][half_ * 2 + 1];
                if (p.epi == EPI_H) {
                    __half2 hv; hv.x = __float2half(v0); hv.y = __float2half(v1);
                    *(__half2*)&Chz[(size_t)orow * p.ldc + col] = hv;
                    continue;
                } else if (p.epi == EPI_GELUMUL_H) {
                    float2 ax = *(const float2*)&auxz[(size_t)r * p.N + col];
                    __half2 hv;
                    hv.x = __float2half(gelu_tanh(ax.x) * v0);
                    hv.y = __float2half(gelu_tanh(ax.y) * v1);
                    *(__half2*)&Chz[(size_t)orow * p.ldc + col] = hv;
                    continue;
                } else if (p.epi == EPI_SCORES) {
                    int csr = csb[r];
                    bool okr = padb[r] != 0;
                    bool ok0 = (csb[col] <= csr) && okr && (padb[col] != 0);
                    bool ok1 = (csb[col + 1] <= csr) && okr && (padb[col + 1] != 0);
                    v0 = ok0 ? v0 * p.scale : MASK_VAL_;
                    v1 = ok1 ? v1 * p.scale : MASK_VAL_;
                } else if (p.epi == EPI_RES) {
                    float2 ax = *(const float2*)&auxz[(size_t)r * p.N + col];
                    v0 += ax.x; v1 += ax.y;
                } else if (p.epi == EPI_RES_GATE) {
                    float2 ax = *(const float2*)&auxz[(size_t)r * p.N + col];
                    float2 gx = *(const float2*)&gvz[(size_t)(r / p.gdiv) * p.gstride + col];
                    v0 = ax.x + gx.x * v0;
                    v1 = ax.y + gx.y * v1;
                }
                *(float2*)&Cz[(size_t)orow * p.ldc + col] = make_float2(v0, v1);
            }
        }
    }
}

// ---------------- transpose fp32 -> fp16: out[n*K+k] = W[k*N+n]; batched via z ----------------
__global__ void wtrans_kernel(const float* __restrict__ W, __half* __restrict__ out,
                              int K, int N, size_t inZ, size_t outZ) {
    W   += blockIdx.z * inZ;
    out += blockIdx.z * outZ;
    __shared__ float t[32][33];
    int k0 = blockIdx.y * 32, n0 = blockIdx.x * 32;
    int tx = threadIdx.x, ty = threadIdx.y;   // 32 x 8
    #pragma unroll
    for (int i = 0; i < 4; i++)
        t[ty + i * 8][tx] = W[(size_t)(k0 + ty + i * 8) * N + n0 + tx];
    __syncthreads();
    #pragma unroll
    for (int i = 0; i < 4; i++) {
        int n = n0 + ty + i * 8;
        int k = k0 + tx;
        out[(size_t)n * K + k] = __float2half(t[tx][ty + i * 8]);
    }
}

// RoPE -> fp16 for Q: q[B,S,H,HD] -> qr[B,H,S,HD]
__global__ void rope_q_kernel(const float* __restrict__ q, const int* __restrict__ pos,
                              __half* __restrict__ out) {
    long idx = blockIdx.x * (long)blockDim.x + threadIdx.x;
    if (idx >= (long)B_ * H_ * S_ * 128) return;
    int i = (int)(idx & 127);
    long t = idx >> 7;
    int s = (int)(t % S_); t /= S_;
    int h = (int)(t % H_);
    int b = (int)(t / H_);
    const float* base = q + ((size_t)(b * S_ + s) * H_ + h) * HD_;
    float x1 = base[i], x2 = base[i + 128];
    float f = (float)pos[b * S_ + s] * expf(-((float)i / 128.0f) * 9.210340371976184f);
    float sn, c; sincosf(f, &sn, &c);
    __half* ob = out + ((size_t)(b * H_ + h) * S_ + s) * HD_;
    ob[i]       = __float2half(x1 * c - x2 * sn);
    ob[i + 128] = __float2half(x2 * c + x1 * sn);
}

// RoPE -> fp16 for K
__global__ void rope_k_kernel(const float* __restrict__ k, const int* __restrict__ pos,
                              __half* __restrict__ out) {
    long idx = blockIdx.x * (long)blockDim.x + threadIdx.x;
    if (idx >= (long)B_ * S_ * 128) return;
    int i = (int)(idx & 127);
    long t = idx >> 7;
    int s = (int)(t % S_);
    int b = (int)(t / S_);
    const float* base = k + (size_t)(b * S_ + s) * HD_;
    float x1 = base[i], x2 = base[i + 128];
    float f = (float)pos[b * S_ + s] * expf(-((float)i / 128.0f) * 9.210340371976184f);
    float sn, c; sincosf(f, &sn, &c);
    __half* ob = out + (size_t)(b * S_ + s) * HD_;
    ob[i]       = __float2half(x1 * c - x2 * sn);
    ob[i + 128] = __float2half(x2 * c + x1 * sn);
}

// ---------------- mod GEMV ----------------
__global__ void mod_kernel(const float* __restrict__ cond, const float* __restrict__ W,
                           const float* __restrict__ bias, float* __restrict__ out,
                           int D, int N) {
    int j = blockIdx.x * blockDim.x + threadIdx.x;
    int b = blockIdx.y;
    if (j >= N) return;
    float s = bias[j];
    const float* c = cond + (size_t)b * D;
    for (int kk = 0; kk < D; kk++)
        s += c[kk] * W[(size_t)kk * N + j];
    out[(size_t)b * N + j] = s;
}

// ---------------- prefix scans ----------------
__global__ void scan_kernel(const int* __restrict__ pad, const int* __restrict__ att,
                            int* __restrict__ pos, int* __restrict__ cs) {
    int b = threadIdx.x;
    if (b >= B_) return;
    int cp = 0, ca = 0;
    for (int s = 0; s < S_; s++) {
        cp += pad[b * S_ + s];
        ca += att[b * S_ + s];
        pos[b * S_ + s] = cp - 1;
        cs[b * S_ + s] = ca;
    }
}

// ---------------- RMSNorm -> fp16 ----------------
__global__ void rmsnorm_kernel(const float* __restrict__ x, __half* __restrict__ out,
                               const float* __restrict__ w, int wStride,
                               int D, int rowsPerBatch) {
    long row = blockIdx.x;
    int b = (int)(row / rowsPerBatch);
    const float* xp = x + row * (long)D;
    float ss = 0.f;
    for (int i = threadIdx.x; i < D; i += blockDim.x) {
        float v = xp[i];
        ss += v * v;
    }
    __shared__ float red[256];
    red[threadIdx.x] = ss;
    __syncthreads();
    for (int s = 128; s > 0; s >>= 1) {
        if (threadIdx.x < s) red[threadIdx.x] += red[threadIdx.x + s];
        __syncthreads();
    }
    float r = rsqrtf(red[0] / (float)D + EPS_);
    const float* wp = w + (size_t)b * wStride;
    __half* op = out + row * (long)D;
    for (int i = threadIdx.x; i < D; i += blockDim.x)
        op[i] = __float2half(xp[i] * r * (1.0f + wp[i]));
}

// ---------------- row softmax fp32 -> fp16 probs ----------------
__global__ void softmax_kernel(const float* __restrict__ scores, __half* __restrict__ probs) {
    const float* p = scores + (size_t)blockIdx.x * S_;
    __half* o = probs + (size_t)blockIdx.x * S_;
    __shared__ float red[256];
    int tid = threadIdx.x;
    float m = -3.4e38f;
    for (int i = tid; i < S_; i += 256) m = fmaxf(m, p[i]);
    red[tid] = m;
    __syncthreads();
    for (int s = 128; s > 0; s >>= 1) {
        if (tid < s) red[tid] = fmaxf(red[tid], red[tid + s]);
        __syncthreads();
    }
    m = red[0];
    __syncthreads();
    float sum = 0.f;
    float loc[4];
    for (int c = 0, i = tid; i < S_; i += 256, c++) {
        float e = expf(p[i] - m);
        loc[c] = e;
        sum += e;
    }
    red[tid] = sum;
    __syncthreads();
    for (int s = 128; s > 0; s >>= 1) {
        if (tid < s) red[tid] += red[tid + s];
        __syncthreads();
    }
    float inv = 1.0f / red[0];
    for (int c = 0, i = tid; i < S_; i += 256, c++)
        o[i] = __float2half(loc[c] * inv);
}

// ---------------- host helper ----------------
struct TcArgs {
    const __half* A; const __half* Bt;
    float* C; __half* Ch = nullptr;
    int M, N, Kp, epi;
    const float* aux = nullptr;
    int rpb = 0, obatch = 0, ldc = 0;
    int zcount = 1, zdiv = 1;
    size_t zA1 = 0, zA2 = 0, zB1 = 0, zB2 = 0, zC1 = 0, zC2 = 0, zAux = 0, zGv = 0;
    const int* cs = nullptr; const int* pad = nullptr;
    int maskStride = 0; float scale = 1.0f;
    const float* gvec = nullptr; int gstride = 0, gdiv = 1;
};

static void launch_tc(const TcArgs& a) {
    cudaFuncSetAttribute(tc_gemm_kernel, cudaFuncAttributeMaxDynamicSharedMemorySize, TC_SMEM);
    TcP p;
    p.A = a.A; p.Bt = a.Bt; p.C = a.C; p.Ch = a.Ch; p.aux = a.aux; p.gvec = a.gvec;
    p.cs = a.cs; p.pad = a.pad;
    p.zA1 = a.zA1; p.zA2 = a.zA2; p.zB1 = a.zB1; p.zB2 = a.zB2;
    p.zC1 = a.zC1; p.zC2 = a.zC2; p.zAux = a.zAux; p.zGv = a.zGv;
    p.zdiv = a.zdiv; p.gstride = a.gstride; p.gdiv = a.gdiv;
    p.maskStride = a.maskStride; p.scale = a.scale;
    p.M = a.M; p.N = a.N; p.Kp = a.Kp; p.epi = a.epi;
    p.rpb = a.rpb ? a.rpb : a.M; p.obatch = a.obatch; p.ldc = a.ldc ? a.ldc : a.N;
    dim3 grid((a.N + 127) / 128, (a.M + 127) / 128, a.zcount);
    tc_gemm_kernel<<<grid, 256, TC_SMEM>>>(p);
}

static void launch_wtrans(const float* W, __half* out, int K, int N,
                          int z = 1, size_t inZ = 0, size_t outZ = 0) {
    dim3 grid(N / 32, K / 32, z);
    wtrans_kernel<<<grid, dim3(32, 8)>>>(W, out, K, N, inZ, outZ);
}

extern "C" void kernel_launch(void* const* d_in, const int* in_sizes, int n_in,
                              void* d_out, int out_size) {
    const float* x0         = (const float*)d_in[0];
    const float* x1         = (const float*)d_in[1];
    const float* cond1      = (const float*)d_in[2];
    const float* w_q0       = (const float*)d_in[3];
    const float* w_k0       = (const float*)d_in[4];
    const float* w_v0       = (const float*)d_in[5];
    const float* w_o0       = (const float*)d_in[6];
    const float* norm1_w0   = (const float*)d_in[7];
    const float* norm2_w0   = (const float*)d_in[8];
    const float* w_gate0    = (const float*)d_in[9];
    const float* w_up0      = (const float*)d_in[10];
    const float* w_down0    = (const float*)d_in[11];
    const float* w_q1       = (const float*)d_in[12];
    const float* w_k1       = (const float*)d_in[13];
    const float* w_v1       = (const float*)d_in[14];
    const float* w_o1       = (const float*)d_in[15];
    const float* ada_in_w1  = (const float*)d_in[16];
    const float* ada_in_b1  = (const float*)d_in[17];
    const float* ada_post_w1= (const float*)d_in[18];
    const float* ada_post_b1= (const float*)d_in[19];
    const float* w_gate1    = (const float*)d_in[20];
    const float* w_up1      = (const float*)d_in[21];
    const float* w_down1    = (const float*)d_in[22];
    const int*   pad_masks  = (const int*)d_in[23];
    const int*   att_masks  = (const int*)d_in[24];

    float* out0 = (float*)d_out;
    float* out1 = out0 + (size_t)B_ * S1_ * D0_;

    float *modin, *modpost, *q, *k, *v, *scores, *r0, *r1, *gu0, *gu1;
    int *pos, *cs;
    __half *hc0, *hc1, *qr, *kr, *vt, *ph, *atth, *yc0, *yc1, *gu0h, *gu1h;
    __half *wq0t, *wk0t, *wv0t, *wo0t, *wg0t, *wu0t, *wd0t;
    __half *wq1t, *wk1t, *wv1t, *wo1t, *wg1t, *wu1t, *wd1t;
    cudaGetSymbolAddress((void**)&modin, g_mod_in);
    cudaGetSymbolAddress((void**)&modpost, g_mod_post);
    cudaGetSymbolAddress((void**)&q, g_q);
    cudaGetSymbolAddress((void**)&k, g_k);
    cudaGetSymbolAddress((void**)&v, g_v);
    cudaGetSymbolAddress((void**)&scores, g_scores);
    cudaGetSymbolAddress((void**)&r0, g_r0);
    cudaGetSymbolAddress((void**)&r1, g_r1);
    cudaGetSymbolAddress((void**)&gu0, g_gu0);
    cudaGetSymbolAddress((void**)&gu1, g_gu1);
    cudaGetSymbolAddress((void**)&pos, g_pos);
    cudaGetSymbolAddress((void**)&cs, g_cs);
    cudaGetSymbolAddress((void**)&hc0, g_hc0);
    cudaGetSymbolAddress((void**)&hc1, g_hc1);
    cudaGetSymbolAddress((void**)&qr, g_qr);
    cudaGetSymbolAddress((void**)&kr, g_kr);
    cudaGetSymbolAddress((void**)&vt, g_vt);
    cudaGetSymbolAddress((void**)&ph, g_ph);
    cudaGetSymbolAddress((void**)&atth, g_atth);
    cudaGetSymbolAddress((void**)&yc0, g_yc0);
    cudaGetSymbolAddress((void**)&yc1, g_yc1);
    cudaGetSymbolAddress((void**)&gu0h, g_gu0h);
    cudaGetSymbolAddress((void**)&gu1h, g_gu1h);
    cudaGetSymbolAddress((void**)&wq0t, g_wq0t);
    cudaGetSymbolAddress((void**)&wk0t, g_wk0t);
    cudaGetSymbolAddress((void**)&wv0t, g_wv0t);
    cudaGetSymbolAddress((void**)&wo0t, g_wo0t);
    cudaGetSymbolAddress((void**)&wg0t, g_wg0t);
    cudaGetSymbolAddress((void**)&wu0t, g_wu0t);
    cudaGetSymbolAddress((void**)&wd0t, g_wd0t);
    cudaGetSymbolAddress((void**)&wq1t, g_wq1t);
    cudaGetSymbolAddress((void**)&wk1t, g_wk1t);
    cudaGetSymbolAddress((void**)&wv1t, g_wv1t);
    cudaGetSymbolAddress((void**)&wo1t, g_wo1t);
    cudaGetSymbolAddress((void**)&wg1t, g_wg1t);
    cudaGetSymbolAddress((void**)&wu1t, g_wu1t);
    cudaGetSymbolAddress((void**)&wd1t, g_wd1t);

    const int M0 = B_ * S1_;   // 3072
    const int M1 = B_ * S2_;   // 256

    // ---- weight prep (transpose + fp16) ----
    launch_wtrans(w_q0,    wq0t, D0_, H_ * HD_);
    launch_wtrans(w_k0,    wk0t, D0_, HD_);
    launch_wtrans(w_v0,    wv0t, D0_, HD_);
    launch_wtrans(w_o0,    wo0t, H_ * HD_, D0_);
    launch_wtrans(w_gate0, wg0t, D0_, F0_);
    launch_wtrans(w_up0,   wu0t, D0_, F0_);
    launch_wtrans(w_down0, wd0t, F0_, D0_);
    launch_wtrans(w_q1,    wq1t, D1_, H_ * HD_);
    launch_wtrans(w_k1,    wk1t, D1_, HD_);
    launch_wtrans(w_v1,    wv1t, D1_, HD_);
    launch_wtrans(w_o1,    wo1t, H_ * HD_, D1_);
    launch_wtrans(w_gate1, wg1t, D1_, F1_);
    launch_wtrans(w_up1,   wu1t, D1_, F1_);
    launch_wtrans(w_down1, wd1t, F1_, D1_);

    // ---- adaLN modulation + scans ----
    {
        dim3 mg((2 * D1_ + 255) / 256, B_);
        mod_kernel<<<mg, 256>>>(cond1, ada_in_w1,   ada_in_b1,   modin,   D1_, 2 * D1_);
        mod_kernel<<<mg, 256>>>(cond1, ada_post_w1, ada_post_b1, modpost, D1_, 2 * D1_);
    }
    scan_kernel<<<1, 32>>>(pad_masks, att_masks, pos, cs);

    // ---- input norms -> fp16 ----
    rmsnorm_kernel<<<M0, 256>>>(x0, hc0, norm1_w0, 0, D0_, S1_);
    rmsnorm_kernel<<<M1, 256>>>(x1, hc1, modin, 2 * D1_, D1_, S2_);

    // ---- QKV projections (fp32 out, row remap into S=832 layout) ----
    { TcArgs a{hc0, wq0t, q, nullptr, M0, H_ * HD_, D0_, EPI_NONE};
      a.rpb = S1_; a.obatch = S_; a.ldc = H_ * HD_; launch_tc(a); }
    { TcArgs a{hc0, wk0t, k, nullptr, M0, HD_, D0_, EPI_NONE};
      a.rpb = S1_; a.obatch = S_; a.ldc = HD_; launch_tc(a); }
    { TcArgs a{hc0, wv0t, v, nullptr, M0, HD_, D0_, EPI_NONE};
      a.rpb = S1_; a.obatch = S_; a.ldc = HD_; launch_tc(a); }
    { TcArgs a{hc1, wq1t, q + (size_t)S1_ * H_ * HD_, nullptr, M1, H_ * HD_, D1_, EPI_NONE};
      a.rpb = S2_; a.obatch = S_; a.ldc = H_ * HD_; launch_tc(a); }
    { TcArgs a{hc1, wk1t, k + (size_t)S1_ * HD_, nullptr, M1, HD_, D1_, EPI_NONE};
      a.rpb = S2_; a.obatch = S_; a.ldc = HD_; launch_tc(a); }
    { TcArgs a{hc1, wv1t, v + (size_t)S1_ * HD_, nullptr, M1, HD_, D1_, EPI_NONE};
      a.rpb = S2_; a.obatch = S_; a.ldc = HD_; launch_tc(a); }

    // ---- RoPE (-> fp16) and V transpose (-> fp16) ----
    {
        long nq = (long)B_ * H_ * S_ * 128;
        rope_q_kernel<<<(unsigned)((nq + 255) / 256), 256>>>(q, pos, qr);
        long nk = (long)B_ * S_ * 128;
        rope_k_kernel<<<(unsigned)((nk + 255) / 256), 256>>>(k, pos, kr);
        launch_wtrans(v, vt, S_, HD_, B_, (size_t)S_ * HD_, (size_t)HD_ * S_);
    }

    // ---- scores = Q K^T * scale, masked (z = B*H) ----
    { TcArgs a{qr, kr, scores, nullptr, S_, S_, HD_, EPI_SCORES};
      a.zcount = B_ * H_; a.zdiv = H_;
      a.zA1 = (size_t)H_ * S_ * HD_; a.zA2 = (size_t)S_ * HD_;
      a.zB1 = (size_t)S_ * HD_;
      a.zC1 = (size_t)H_ * S_ * S_; a.zC2 = (size_t)S_ * S_;
      a.cs = cs; a.pad = pad_masks; a.maskStride = S_; a.scale = 0.0625f;
      launch_tc(a); }

    softmax_kernel<<<B_ * H_ * S_, 256>>>(scores, ph);

    // ---- PV (z = B*H) -> atth [B,S,H*HD] fp16 ----
    { TcArgs a{ph, vt, nullptr, atth, S_, HD_, S_, EPI_H};
      a.ldc = H_ * HD_;
      a.zcount = B_ * H_; a.zdiv = H_;
      a.zA1 = (size_t)H_ * S_ * S_; a.zA2 = (size_t)S_ * S_;
      a.zB1 = (size_t)HD_ * S_;
      a.zC1 = (size_t)S_ * H_ * HD_; a.zC2 = (size_t)HD_;
      launch_tc(a); }

    // ---- output projections (z = B) ----
    { TcArgs a{atth, wo0t, r0, nullptr, S1_, D0_, H_ * HD_, EPI_RES};
      a.aux = x0;
      a.zcount = B_;
      a.zA1 = (size_t)S_ * H_ * HD_; a.zC1 = (size_t)S1_ * D0_; a.zAux = (size_t)S1_ * D0_;
      launch_tc(a); }
    { TcArgs a{atth + (size_t)S1_ * H_ * HD_, wo1t, r1, nullptr, S2_, D1_, H_ * HD_, EPI_RES_GATE};
      a.aux = x1;
      a.zcount = B_;
      a.zA1 = (size_t)S_ * H_ * HD_; a.zC1 = (size_t)S2_ * D1_; a.zAux = (size_t)S2_ * D1_;
      a.gvec = modin + D1_; a.zGv = (size_t)2 * D1_; a.gdiv = S2_; a.gstride = 0;
      launch_tc(a); }

    // ---- post norms -> fp16 ----
    rmsnorm_kernel<<<M0, 256>>>(r0, yc0, norm2_w0, 0, D0_, S1_);
    rmsnorm_kernel<<<M1, 256>>>(r1, yc1, modpost, 2 * D1_, D1_, S2_);

    // ---- MLP stream 0 ----
    { TcArgs a{yc0, wg0t, gu0, nullptr, M0, F0_, D0_, EPI_NONE}; launch_tc(a); }
    { TcArgs a{yc0, wu0t, nullptr, gu0h, M0, F0_, D0_, EPI_GELUMUL_H}; a.aux = gu0; launch_tc(a); }
    { TcArgs a{gu0h, wd0t, out0, nullptr, M0, D0_, F0_, EPI_RES}; a.aux = r0; launch_tc(a); }

    // ---- MLP stream 1 ----
    { TcArgs a{yc1, wg1t, gu1, nullptr, M1, F1_, D1_, EPI_NONE}; launch_tc(a); }
    { TcArgs a{yc1, wu1t, nullptr, gu1h, M1, F1_, D1_, EPI_GELUMUL_H}; a.aux = gu1; launch_tc(a); }
    { TcArgs a{gu1h, wd1t, out1, nullptr, M1, D1_, F1_, EPI_RES_GATE};
      a.aux = r1;
      a.gvec = modpost + D1_; a.gstride = 2 * D1_; a.gdiv = S2_;
      launch_tc(a); }
}

// round 10
// speedup vs baseline: 3.8391x; 1.0377x over previous
#include <cuda_runtime.h>
#include <cuda_fp16.h>
#include <math.h>
#include <stdint.h>

// ---------------- problem constants ----------------
#define B_   4
#define S1_  768
#define S2_  64
#define S_   832
#define D0_  2048
#define F0_  16384
#define D1_  1024
#define F1_  4096
#define H_   8
#define HD_  256
#define EPS_ 1e-6f
#define MASK_VAL_ -1000000000.0f
#define NQKV_ (H_*HD_ + 2*HD_)   // 2560

// ---------------- scratch (device globals) ----------------
__device__ float g_mod_in[B_*2*D1_];
__device__ float g_mod_post[B_*2*D1_];
__device__ float g_q[(size_t)B_*S_*H_*HD_];
__device__ float g_k[B_*S_*HD_];
__device__ float g_v[B_*S_*HD_];
__device__ float g_scores[(size_t)B_*H_*S_*S_];
__device__ float g_r0[B_*S1_*D0_];
__device__ float g_r1[B_*S2_*D1_];
__device__ float g_gu0[(size_t)B_*S1_*F0_];
__device__ float g_gu1[(size_t)B_*S2_*2*F1_];
__device__ int   g_pos[B_*S_];
__device__ int   g_cs[B_*S_];
// fp16 operands
__device__ __half g_hc0[(size_t)B_*S1_*D0_];
__device__ __half g_hc1[B_*S2_*D1_];
__device__ __half g_qr[(size_t)B_*H_*S_*HD_];
__device__ __half g_kr[B_*S_*HD_];
__device__ __half g_vt[B_*HD_*S_];
__device__ __half g_ph[(size_t)B_*H_*S_*S_];
__device__ __half g_atth[(size_t)B_*S_*H_*HD_];
__device__ __half g_yc0[(size_t)B_*S1_*D0_];
__device__ __half g_yc1[B_*S2_*D1_];
__device__ __half g_gu0h[(size_t)B_*S1_*F0_];
__device__ __half g_gu1h[B_*S2_*F1_];
// transposed fp16 weights [N, K]
__device__ __half g_wqkv0t[(size_t)NQKV_*2048];
__device__ __half g_wqkv1t[(size_t)NQKV_*1024];
__device__ __half g_wo0t[(size_t)2048*2048];
__device__ __half g_wg0t[(size_t)16384*2048];
__device__ __half g_wu0t[(size_t)16384*2048];
__device__ __half g_wd0t[(size_t)2048*16384];
__device__ __half g_wo1t[(size_t)1024*2048];
__device__ __half g_wgu1t[(size_t)2*4096*1024];
__device__ __half g_wd1t[(size_t)1024*4096];

// ---------------- helpers ----------------
__device__ __forceinline__ float gelu_tanh(float x) {
    float x3 = x * x * x;
    return 0.5f * x * (1.0f + tanhf(0.79788456080286535588f * (x + 0.044715f * x3)));
}
__device__ __forceinline__ uint32_t smem_u32(const void* p) {
    uint32_t a;
    asm("{ .reg .u64 t; cvta.to.shared.u64 t, %1; cvt.u32.u64 %0, t; }" : "=r"(a) : "l"(p));
    return a;
}
#define CP_ASYNC16(sm, gm) \
    asm volatile("cp.async.cg.shared.global [%0], [%1], 16;" :: "r"(sm), "l"(gm))
#define CP_COMMIT() asm volatile("cp.async.commit_group;")
#define CP_WAIT(n)  asm volatile("cp.async.wait_group %0;" :: "n"(n))

__device__ __forceinline__ void ldsm_x4(uint32_t* r, uint32_t addr) {
    asm volatile("ldmatrix.sync.aligned.m8n8.x4.shared.b16 {%0,%1,%2,%3}, [%4];"
                 : "=r"(r[0]), "=r"(r[1]), "=r"(r[2]), "=r"(r[3]) : "r"(addr));
}
__device__ __forceinline__ void mma_f16(float* c, const uint32_t* a, uint32_t b0, uint32_t b1) {
    asm volatile("mma.sync.aligned.m16n8k16.row.col.f32.f16.f16.f32 "
                 "{%0,%1,%2,%3}, {%4,%5,%6,%7}, {%8,%9}, {%0,%1,%2,%3};"
                 : "+f"(c[0]), "+f"(c[1]), "+f"(c[2]), "+f"(c[3])
                 : "r"(a[0]), "r"(a[1]), "r"(a[2]), "r"(a[3]), "r"(b0), "r"(b1));
}
__device__ __forceinline__ uint32_t sw_addr(uint32_t base, int row, int chunk) {
    return base + (uint32_t)(((row << 3) + (chunk ^ (row & 7))) << 4);
}

// ---------------- epilogue modes ----------------
#define EPI_NONE       0
#define EPI_SCORES     1
#define EPI_RES        2
#define EPI_RES_GATE   3
#define EPI_H          4
#define EPI_GELUMUL_H  5
#define EPI_QKV        6   // column-routed q/k/v fp32 stores

// ---------------- TC fp16 GEMM: C[M,N] = A[M,Kp] * Bt[N,Kp]^T ----------------
struct TcP {
    const __half* A; const __half* Bt;
    float* C; __half* Ch;
    float* Ck; float* Cv;       // EPI_QKV extra targets
    const float* aux; const float* gvec;
    const int *cs, *pad;
    size_t zA1, zA2, zB1, zB2, zC1, zC2, zAux, zGv;
    int zdiv;
    int gstride, gdiv;
    int maskStride; float scale;
    int M, N, Kp, epi;
    int rpb, obatch, ldc;
};

#define TC_STAGES 3
#define TC_STAGE_BYTES 32768
#define TC_SMEM (TC_STAGES * TC_STAGE_BYTES)

__global__ __launch_bounds__(256) void tc_gemm_kernel(TcP p) {
    extern __shared__ char dsm[];
    uint32_t sbase = smem_u32(dsm);

    int tid  = threadIdx.x;
    int wid  = tid >> 5;
    int lane = tid & 31;
    int wm = wid >> 2;
    int wn = wid & 3;

    int m0 = blockIdx.y * 128;
    int n0 = blockIdx.x * 128;
    int z  = blockIdx.z;
    int zb = z / p.zdiv;
    int zr = z - zb * p.zdiv;

    const __half* Ab = p.A  + (size_t)zb * p.zA1 + (size_t)zr * p.zA2;
    const __half* Bb = p.Bt + (size_t)zb * p.zB1 + (size_t)zr * p.zB2;

    int kc = tid & 7;
    int rb = tid >> 3;

    float acc[4][4][4];
    #pragma unroll
    for (int i = 0; i < 4; i++)
        #pragma unroll
        for (int j = 0; j < 4; j++)
            #pragma unroll
            for (int e = 0; e < 4; e++) acc[i][j][e] = 0.f;

    int nIter = p.Kp >> 6;

    auto issue = [&](int it) {
        int st = it % TC_STAGES;
        uint32_t sa = sbase + st * TC_STAGE_BYTES;
        uint32_t sb = sa + 16384;
        int k0 = it << 6;
        #pragma unroll
        for (int i = 0; i < 4; i++) {
            int row = rb + i * 32;
            int ra = m0 + row; if (ra > p.M - 1) ra = p.M - 1;
            CP_ASYNC16(sw_addr(sa, row, kc), Ab + (size_t)ra * p.Kp + k0 + kc * 8);
            int rn = n0 + row; if (rn > p.N - 1) rn = p.N - 1;
            CP_ASYNC16(sw_addr(sb, row, kc), Bb + (size_t)rn * p.Kp + k0 + kc * 8);
        }
        CP_COMMIT();
    };

    #pragma unroll
    for (int s = 0; s < TC_STAGES - 1; s++) issue(s);

    int grp = lane >> 3;
    int lr  = lane & 7;

    for (int it = 0; it < nIter; it++) {
        if (it + TC_STAGES - 1 < nIter) {
            issue(it + TC_STAGES - 1);
            CP_WAIT(TC_STAGES - 2);
        } else {
            CP_WAIT(0);
        }
        __syncthreads();

        int st = it % TC_STAGES;
        uint32_t sa = sbase + st * TC_STAGE_BYTES;
        uint32_t sb = sa + 16384;

        #pragma unroll
        for (int kb = 0; kb < 4; kb++) {
            int chA = 2 * kb + (grp >> 1);
            uint32_t a[4][4];
            #pragma unroll
            for (int mi = 0; mi < 4; mi++) {
                int row = wm * 64 + mi * 16 + (grp & 1) * 8 + lr;
                ldsm_x4(a[mi], sw_addr(sa, row, chA));
            }
            uint32_t bf[2][4];
            #pragma unroll
            for (int bi = 0; bi < 2; bi++) {
                int row = wn * 32 + bi * 16 + (grp & 1) * 8 + lr;
                ldsm_x4(bf[bi], sw_addr(sb, row, chA));
            }
            #pragma unroll
            for (int mi = 0; mi < 4; mi++)
                #pragma unroll
                for (int ni = 0; ni < 4; ni++) {
                    int bi = ni >> 1, wh = ni & 1;
                    mma_f16(acc[mi][ni], a[mi], bf[bi][wh], bf[bi][wh + 2]);
                }
        }
        __syncthreads();
    }

    // ---- epilogue ----
    const int* csb  = p.cs  ? p.cs  + (size_t)zb * p.maskStride : nullptr;
    const int* padb = p.pad ? p.pad + (size_t)zb * p.maskStride : nullptr;
    const float* auxz = p.aux ? p.aux + (size_t)zb * p.zAux : nullptr;
    const float* gvz  = p.gvec ? p.gvec + (size_t)zb * p.zGv : nullptr;
    float* Cz = p.C + (size_t)zb * p.zC1 + (size_t)zr * p.zC2;
    __half* Chz = p.Ch + (size_t)zb * p.zC1 + (size_t)zr * p.zC2;
    int qrow = lane >> 2;
    int qcol = (lane & 3) * 2;
    #pragma unroll
    for (int mi = 0; mi < 4; mi++) {
        #pragma unroll
        for (int half_ = 0; half_ < 2; half_++) {
            int r = m0 + wm * 64 + mi * 16 + half_ * 8 + qrow;
            if (r >= p.M) continue;
            int orow = (r / p.rpb) * p.obatch + (r % p.rpb);
            #pragma unroll
            for (int ni = 0; ni < 4; ni++) {
                int col = n0 + wn * 32 + ni * 8 + qcol;
                if (col >= p.N) continue;
                float v0 = acc[mi][ni][half_ * 2 + 0];
                float v1 = acc[mi][ni][half_ * 2 + 1];
                if (p.epi == EPI_QKV) {
                    float2 ov = make_float2(v0, v1);
                    if (col < H_ * HD_)
                        *(float2*)&p.C[(size_t)orow * (H_ * HD_) + col] = ov;
                    else if (col < H_ * HD_ + HD_)
                        *(float2*)&p.Ck[(size_t)orow * HD_ + (col - H_ * HD_)] = ov;
                    else
                        *(float2*)&p.Cv[(size_t)orow * HD_ + (col - H_ * HD_ - HD_)] = ov;
                    continue;
                } else if (p.epi == EPI_H) {
                    __half2 hv; hv.x = __float2half(v0); hv.y = __float2half(v1);
                    *(__half2*)&Chz[(size_t)orow * p.ldc + col] = hv;
                    continue;
                } else if (p.epi == EPI_GELUMUL_H) {
                    float2 ax = *(const float2*)&auxz[(size_t)r * p.N + col];
                    __half2 hv;
                    hv.x = __float2half(gelu_tanh(ax.x) * v0);
                    hv.y = __float2half(gelu_tanh(ax.y) * v1);
                    *(__half2*)&Chz[(size_t)orow * p.ldc + col] = hv;
                    continue;
                } else if (p.epi == EPI_SCORES) {
                    int csr = csb[r];
                    bool okr = padb[r] != 0;
                    bool ok0 = (csb[col] <= csr) && okr && (padb[col] != 0);
                    bool ok1 = (csb[col + 1] <= csr) && okr && (padb[col + 1] != 0);
                    v0 = ok0 ? v0 * p.scale : MASK_VAL_;
                    v1 = ok1 ? v1 * p.scale : MASK_VAL_;
                } else if (p.epi == EPI_RES) {
                    float2 ax = *(const float2*)&auxz[(size_t)r * p.N + col];
                    v0 += ax.x; v1 += ax.y;
                } else if (p.epi == EPI_RES_GATE) {
                    float2 ax = *(const float2*)&auxz[(size_t)r * p.N + col];
                    float2 gx = *(const float2*)&gvz[(size_t)(r / p.gdiv) * p.gstride + col];
                    v0 = ax.x + gx.x * v0;
                    v1 = ax.y + gx.y * v1;
                }
                *(float2*)&Cz[(size_t)orow * p.ldc + col] = make_float2(v0, v1);
            }
        }
    }
}

// ---------------- transpose fp32 -> fp16: out[n*K+k] = W[k*N+n]; batched via z ----------------
__global__ void wtrans_kernel(const float* __restrict__ W, __half* __restrict__ out,
                              int K, int N, size_t inZ, size_t outZ) {
    W   += blockIdx.z * inZ;
    out += blockIdx.z * outZ;
    __shared__ float t[32][33];
    int k0 = blockIdx.y * 32, n0 = blockIdx.x * 32;
    int tx = threadIdx.x, ty = threadIdx.y;   // 32 x 8
    #pragma unroll
    for (int i = 0; i < 4; i++)
        t[ty + i * 8][tx] = W[(size_t)(k0 + ty + i * 8) * N + n0 + tx];
    __syncthreads();
    #pragma unroll
    for (int i = 0; i < 4; i++) {
        int n = n0 + ty + i * 8;
        int k = k0 + tx;
        out[(size_t)n * K + k] = __float2half(t[tx][ty + i * 8]);
    }
}

// RoPE -> fp16 for Q: q[B,S,H,HD] -> qr[B,H,S,HD]
__global__ void rope_q_kernel(const float* __restrict__ q, const int* __restrict__ pos,
                              __half* __restrict__ out) {
    long idx = blockIdx.x * (long)blockDim.x + threadIdx.x;
    if (idx >= (long)B_ * H_ * S_ * 128) return;
    int i = (int)(idx & 127);
    long t = idx >> 7;
    int s = (int)(t % S_); t /= S_;
    int h = (int)(t % H_);
    int b = (int)(t / H_);
    const float* base = q + ((size_t)(b * S_ + s) * H_ + h) * HD_;
    float x1 = base[i], x2 = base[i + 128];
    float f = (float)pos[b * S_ + s] * expf(-((float)i / 128.0f) * 9.210340371976184f);
    float sn, c; sincosf(f, &sn, &c);
    __half* ob = out + ((size_t)(b * H_ + h) * S_ + s) * HD_;
    ob[i]       = __float2half(x1 * c - x2 * sn);
    ob[i + 128] = __float2half(x2 * c + x1 * sn);
}

// RoPE -> fp16 for K
__global__ void rope_k_kernel(const float* __restrict__ k, const int* __restrict__ pos,
                              __half* __restrict__ out) {
    long idx = blockIdx.x * (long)blockDim.x + threadIdx.x;
    if (idx >= (long)B_ * S_ * 128) return;
    int i = (int)(idx & 127);
    long t = idx >> 7;
    int s = (int)(t % S_);
    int b = (int)(t / S_);
    const float* base = k + (size_t)(b * S_ + s) * HD_;
    float x1 = base[i], x2 = base[i + 128];
    float f = (float)pos[b * S_ + s] * expf(-((float)i / 128.0f) * 9.210340371976184f);
    float sn, c; sincosf(f, &sn, &c);
    __half* ob = out + (size_t)(b * S_ + s) * HD_;
    ob[i]       = __float2half(x1 * c - x2 * sn);
    ob[i + 128] = __float2half(x2 * c + x1 * sn);
}

// elementwise: out[r][j] = half(gelu(gu[r][j]) * gu[r][F+j]), gu is [M][2F]
__global__ void ew_gelumul_kernel(const float* __restrict__ gu, __half* __restrict__ out,
                                  int M, int F) {
    long idx = blockIdx.x * (long)blockDim.x + threadIdx.x;
    if (idx >= (long)M * F) return;
    int r = (int)(idx / F), j = (int)(idx % F);
    const float* g = gu + (size_t)r * 2 * F;
    out[(size_t)r * F + j] = __float2half(gelu_tanh(g[j]) * g[F + j]);
}

// ---------------- mod GEMV ----------------
__global__ void mod_kernel(const float* __restrict__ cond, const float* __restrict__ W,
                           const float* __restrict__ bias, float* __restrict__ out,
                           int D, int N) {
    int j = blockIdx.x * blockDim.x + threadIdx.x;
    int b = blockIdx.y;
    if (j >= N) return;
    float s = bias[j];
    const float* c = cond + (size_t)b * D;
    for (int kk = 0; kk < D; kk++)
        s += c[kk] * W[(size_t)kk * N + j];
    out[(size_t)b * N + j] = s;
}

// ---------------- prefix scans ----------------
__global__ void scan_kernel(const int* __restrict__ pad, const int* __restrict__ att,
                            int* __restrict__ pos, int* __restrict__ cs) {
    int b = threadIdx.x;
    if (b >= B_) return;
    int cp = 0, ca = 0;
    for (int s = 0; s < S_; s++) {
        cp += pad[b * S_ + s];
        ca += att[b * S_ + s];
        pos[b * S_ + s] = cp - 1;
        cs[b * S_ + s] = ca;
    }
}

// ---------------- RMSNorm -> fp16 ----------------
__global__ void rmsnorm_kernel(const float* __restrict__ x, __half* __restrict__ out,
                               const float* __restrict__ w, int wStride,
                               int D, int rowsPerBatch) {
    long row = blockIdx.x;
    int b = (int)(row / rowsPerBatch);
    const float* xp = x + row * (long)D;
    float ss = 0.f;
    for (int i = threadIdx.x; i < D; i += blockDim.x) {
        float v = xp[i];
        ss += v * v;
    }
    __shared__ float red[256];
    red[threadIdx.x] = ss;
    __syncthreads();
    for (int s = 128; s > 0; s >>= 1) {
        if (threadIdx.x < s) red[threadIdx.x] += red[threadIdx.x + s];
        __syncthreads();
    }
    float r = rsqrtf(red[0] / (float)D + EPS_);
    const float* wp = w + (size_t)b * wStride;
    __half* op = out + row * (long)D;
    for (int i = threadIdx.x; i < D; i += blockDim.x)
        op[i] = __float2half(xp[i] * r * (1.0f + wp[i]));
}

// ---------------- row softmax fp32 -> fp16 probs ----------------
__global__ void softmax_kernel(const float* __restrict__ scores, __half* __restrict__ probs) {
    const float* p = scores + (size_t)blockIdx.x * S_;
    __half* o = probs + (size_t)blockIdx.x * S_;
    __shared__ float red[256];
    int tid = threadIdx.x;
    float m = -3.4e38f;
    for (int i = tid; i < S_; i += 256) m = fmaxf(m, p[i]);
    red[tid] = m;
    __syncthreads();
    for (int s = 128; s > 0; s >>= 1) {
        if (tid < s) red[tid] = fmaxf(red[tid], red[tid + s]);
        __syncthreads();
    }
    m = red[0];
    __syncthreads();
    float sum = 0.f;
    float loc[4];
    for (int c = 0, i = tid; i < S_; i += 256, c++) {
        float e = expf(p[i] - m);
        loc[c] = e;
        sum += e;
    }
    red[tid] = sum;
    __syncthreads();
    for (int s = 128; s > 0; s >>= 1) {
        if (tid < s) red[tid] += red[tid + s];
        __syncthreads();
    }
    float inv = 1.0f / red[0];
    for (int c = 0, i = tid; i < S_; i += 256, c++)
        o[i] = __float2half(loc[c] * inv);
}

// ---------------- host helper ----------------
// NOTE: new members (Ck, Cv) live at the TAIL so positional {A,Bt,C,Ch,M,N,Kp,epi}
// initializers keep their meaning (R9 post-mortem).
struct TcArgs {
    const __half* A; const __half* Bt;
    float* C; __half* Ch = nullptr;
    int M = 0, N = 0, Kp = 0, epi = 0;
    const float* aux = nullptr;
    int rpb = 0, obatch = 0, ldc = 0;
    int zcount = 1, zdiv = 1;
    size_t zA1 = 0, zA2 = 0, zB1 = 0, zB2 = 0, zC1 = 0, zC2 = 0, zAux = 0, zGv = 0;
    const int* cs = nullptr; const int* pad = nullptr;
    int maskStride = 0; float scale = 1.0f;
    const float* gvec = nullptr; int gstride = 0, gdiv = 1;
    float* Ck = nullptr; float* Cv = nullptr;
};

static void launch_tc(const TcArgs& a) {
    cudaFuncSetAttribute(tc_gemm_kernel, cudaFuncAttributeMaxDynamicSharedMemorySize, TC_SMEM);
    TcP p;
    p.A = a.A; p.Bt = a.Bt; p.C = a.C; p.Ch = a.Ch; p.Ck = a.Ck; p.Cv = a.Cv;
    p.aux = a.aux; p.gvec = a.gvec;
    p.cs = a.cs; p.pad = a.pad;
    p.zA1 = a.zA1; p.zA2 = a.zA2; p.zB1 = a.zB1; p.zB2 = a.zB2;
    p.zC1 = a.zC1; p.zC2 = a.zC2; p.zAux = a.zAux; p.zGv = a.zGv;
    p.zdiv = a.zdiv; p.gstride = a.gstride; p.gdiv = a.gdiv;
    p.maskStride = a.maskStride; p.scale = a.scale;
    p.M = a.M; p.N = a.N; p.Kp = a.Kp; p.epi = a.epi;
    p.rpb = a.rpb ? a.rpb : a.M; p.obatch = a.obatch; p.ldc = a.ldc ? a.ldc : a.N;
    dim3 grid((a.N + 127) / 128, (a.M + 127) / 128, a.zcount);
    tc_gemm_kernel<<<grid, 256, TC_SMEM>>>(p);
}

static void launch_wtrans(const float* W, __half* out, int K, int N,
                          int z = 1, size_t inZ = 0, size_t outZ = 0) {
    dim3 grid(N / 32, K / 32, z);
    wtrans_kernel<<<grid, dim3(32, 8)>>>(W, out, K, N, inZ, outZ);
}

extern "C" void kernel_launch(void* const* d_in, const int* in_sizes, int n_in,
                              void* d_out, int out_size) {
    const float* x0         = (const float*)d_in[0];
    const float* x1         = (const float*)d_in[1];
    const float* cond1      = (const float*)d_in[2];
    const float* w_q0       = (const float*)d_in[3];
    const float* w_k0       = (const float*)d_in[4];
    const float* w_v0       = (const float*)d_in[5];
    const float* w_o0       = (const float*)d_in[6];
    const float* norm1_w0   = (const float*)d_in[7];
    const float* norm2_w0   = (const float*)d_in[8];
    const float* w_gate0    = (const float*)d_in[9];
    const float* w_up0      = (const float*)d_in[10];
    const float* w_down0    = (const float*)d_in[11];
    const float* w_q1       = (const float*)d_in[12];
    const float* w_k1       = (const float*)d_in[13];
    const float* w_v1       = (const float*)d_in[14];
    const float* w_o1       = (const float*)d_in[15];
    const float* ada_in_w1  = (const float*)d_in[16];
    const float* ada_in_b1  = (const float*)d_in[17];
    const float* ada_post_w1= (const float*)d_in[18];
    const float* ada_post_b1= (const float*)d_in[19];
    const float* w_gate1    = (const float*)d_in[20];
    const float* w_up1      = (const float*)d_in[21];
    const float* w_down1    = (const float*)d_in[22];
    const int*   pad_masks  = (const int*)d_in[23];
    const int*   att_masks  = (const int*)d_in[24];

    float* out0 = (float*)d_out;
    float* out1 = out0 + (size_t)B_ * S1_ * D0_;

    float *modin, *modpost, *q, *k, *v, *scores, *r0, *r1, *gu0, *gu1;
    int *pos, *cs;
    __half *hc0, *hc1, *qr, *kr, *vt, *ph, *atth, *yc0, *yc1, *gu0h, *gu1h;
    __half *wqkv0t, *wqkv1t, *wo0t, *wg0t, *wu0t, *wd0t, *wo1t, *wgu1t, *wd1t;
    cudaGetSymbolAddress((void**)&modin, g_mod_in);
    cudaGetSymbolAddress((void**)&modpost, g_mod_post);
    cudaGetSymbolAddress((void**)&q, g_q);
    cudaGetSymbolAddress((void**)&k, g_k);
    cudaGetSymbolAddress((void**)&v, g_v);
    cudaGetSymbolAddress((void**)&scores, g_scores);
    cudaGetSymbolAddress((void**)&r0, g_r0);
    cudaGetSymbolAddress((void**)&r1, g_r1);
    cudaGetSymbolAddress((void**)&gu0, g_gu0);
    cudaGetSymbolAddress((void**)&gu1, g_gu1);
    cudaGetSymbolAddress((void**)&pos, g_pos);
    cudaGetSymbolAddress((void**)&cs, g_cs);
    cudaGetSymbolAddress((void**)&hc0, g_hc0);
    cudaGetSymbolAddress((void**)&hc1, g_hc1);
    cudaGetSymbolAddress((void**)&qr, g_qr);
    cudaGetSymbolAddress((void**)&kr, g_kr);
    cudaGetSymbolAddress((void**)&vt, g_vt);
    cudaGetSymbolAddress((void**)&ph, g_ph);
    cudaGetSymbolAddress((void**)&atth, g_atth);
    cudaGetSymbolAddress((void**)&yc0, g_yc0);
    cudaGetSymbolAddress((void**)&yc1, g_yc1);
    cudaGetSymbolAddress((void**)&gu0h, g_gu0h);
    cudaGetSymbolAddress((void**)&gu1h, g_gu1h);
    cudaGetSymbolAddress((void**)&wqkv0t, g_wqkv0t);
    cudaGetSymbolAddress((void**)&wqkv1t, g_wqkv1t);
    cudaGetSymbolAddress((void**)&wo0t, g_wo0t);
    cudaGetSymbolAddress((void**)&wg0t, g_wg0t);
    cudaGetSymbolAddress((void**)&wu0t, g_wu0t);
    cudaGetSymbolAddress((void**)&wd0t, g_wd0t);
    cudaGetSymbolAddress((void**)&wo1t, g_wo1t);
    cudaGetSymbolAddress((void**)&wgu1t, g_wgu1t);
    cudaGetSymbolAddress((void**)&wd1t, g_wd1t);

    const int M0 = B_ * S1_;   // 3072
    const int M1 = B_ * S2_;   // 256

    // ---- weight prep (transpose + fp16) into fused buffers ----
    launch_wtrans(w_q0, wqkv0t, D0_, H_ * HD_);
    launch_wtrans(w_k0, wqkv0t + (size_t)(H_ * HD_) * D0_, D0_, HD_);
    launch_wtrans(w_v0, wqkv0t + (size_t)(H_ * HD_ + HD_) * D0_, D0_, HD_);
    launch_wtrans(w_o0,    wo0t, H_ * HD_, D0_);
    launch_wtrans(w_gate0, wg0t, D0_, F0_);
    launch_wtrans(w_up0,   wu0t, D0_, F0_);
    launch_wtrans(w_down0, wd0t, F0_, D0_);
    launch_wtrans(w_q1, wqkv1t, D1_, H_ * HD_);
    launch_wtrans(w_k1, wqkv1t + (size_t)(H_ * HD_) * D1_, D1_, HD_);
    launch_wtrans(w_v1, wqkv1t + (size_t)(H_ * HD_ + HD_) * D1_, D1_, HD_);
    launch_wtrans(w_o1,    wo1t, H_ * HD_, D1_);
    launch_wtrans(w_gate1, wgu1t, D1_, F1_);
    launch_wtrans(w_up1,   wgu1t + (size_t)F1_ * D1_, D1_, F1_);
    launch_wtrans(w_down1, wd1t, F1_, D1_);

    // ---- adaLN modulation + scans ----
    {
        dim3 mg((2 * D1_ + 255) / 256, B_);
        mod_kernel<<<mg, 256>>>(cond1, ada_in_w1,   ada_in_b1,   modin,   D1_, 2 * D1_);
        mod_kernel<<<mg, 256>>>(cond1, ada_post_w1, ada_post_b1, modpost, D1_, 2 * D1_);
    }
    scan_kernel<<<1, 32>>>(pad_masks, att_masks, pos, cs);

    // ---- input norms -> fp16 ----
    rmsnorm_kernel<<<M0, 256>>>(x0, hc0, norm1_w0, 0, D0_, S1_);
    rmsnorm_kernel<<<M1, 256>>>(x1, hc1, modin, 2 * D1_, D1_, S2_);

    // ---- fused QKV projections (column-routed, row remap into S=832 layout) ----
    { TcArgs a{hc0, wqkv0t, q, nullptr, M0, NQKV_, D0_, EPI_QKV};
      a.Ck = k; a.Cv = v;
      a.rpb = S1_; a.obatch = S_; launch_tc(a); }
    { TcArgs a{hc1, wqkv1t, q + (size_t)S1_ * H_ * HD_, nullptr, M1, NQKV_, D1_, EPI_QKV};
      a.Ck = k + (size_t)S1_ * HD_; a.Cv = v + (size_t)S1_ * HD_;
      a.rpb = S2_; a.obatch = S_; launch_tc(a); }

    // ---- RoPE (-> fp16) and V transpose (-> fp16) ----
    {
        long nq = (long)B_ * H_ * S_ * 128;
        rope_q_kernel<<<(unsigned)((nq + 255) / 256), 256>>>(q, pos, qr);
        long nk = (long)B_ * S_ * 128;
        rope_k_kernel<<<(unsigned)((nk + 255) / 256), 256>>>(k, pos, kr);
        launch_wtrans(v, vt, S_, HD_, B_, (size_t)S_ * HD_, (size_t)HD_ * S_);
    }

    // ---- scores = Q K^T * scale, masked (z = B*H) ----
    { TcArgs a{qr, kr, scores, nullptr, S_, S_, HD_, EPI_SCORES};
      a.zcount = B_ * H_; a.zdiv = H_;
      a.zA1 = (size_t)H_ * S_ * HD_; a.zA2 = (size_t)S_ * HD_;
      a.zB1 = (size_t)S_ * HD_;
      a.zC1 = (size_t)H_ * S_ * S_; a.zC2 = (size_t)S_ * S_;
      a.cs = cs; a.pad = pad_masks; a.maskStride = S_; a.scale = 0.0625f;
      launch_tc(a); }

    softmax_kernel<<<B_ * H_ * S_, 256>>>(scores, ph);

    // ---- PV (z = B*H) -> atth [B,S,H*HD] fp16 ----
    { TcArgs a{ph, vt, nullptr, atth, S_, HD_, S_, EPI_H};
      a.ldc = H_ * HD_;
      a.zcount = B_ * H_; a.zdiv = H_;
      a.zA1 = (size_t)H_ * S_ * S_; a.zA2 = (size_t)S_ * S_;
      a.zB1 = (size_t)HD_ * S_;
      a.zC1 = (size_t)S_ * H_ * HD_; a.zC2 = (size_t)HD_;
      launch_tc(a); }

    // ---- output projections (z = B) ----
    { TcArgs a{atth, wo0t, r0, nullptr, S1_, D0_, H_ * HD_, EPI_RES};
      a.aux = x0;
      a.zcount = B_;
      a.zA1 = (size_t)S_ * H_ * HD_; a.zC1 = (size_t)S1_ * D0_; a.zAux = (size_t)S1_ * D0_;
      launch_tc(a); }
    { TcArgs a{atth + (size_t)S1_ * H_ * HD_, wo1t, r1, nullptr, S2_, D1_, H_ * HD_, EPI_RES_GATE};
      a.aux = x1;
      a.zcount = B_;
      a.zA1 = (size_t)S_ * H_ * HD_; a.zC1 = (size_t)S2_ * D1_; a.zAux = (size_t)S2_ * D1_;
      a.gvec = modin + D1_; a.zGv = (size_t)2 * D1_; a.gdiv = S2_; a.gstride = 0;
      launch_tc(a); }

    // ---- post norms -> fp16 ----
    rmsnorm_kernel<<<M0, 256>>>(r0, yc0, norm2_w0, 0, D0_, S1_);
    rmsnorm_kernel<<<M1, 256>>>(r1, yc1, modpost, 2 * D1_, D1_, S2_);

    // ---- MLP stream 0 ----
    { TcArgs a{yc0, wg0t, gu0, nullptr, M0, F0_, D0_, EPI_NONE}; launch_tc(a); }
    { TcArgs a{yc0, wu0t, nullptr, gu0h, M0, F0_, D0_, EPI_GELUMUL_H}; a.aux = gu0; launch_tc(a); }
    { TcArgs a{gu0h, wd0t, out0, nullptr, M0, D0_, F0_, EPI_RES}; a.aux = r0; launch_tc(a); }

    // ---- MLP stream 1 (fused gate|up, then elementwise, then down) ----
    { TcArgs a{yc1, wgu1t, gu1, nullptr, M1, 2 * F1_, D1_, EPI_NONE}; launch_tc(a); }
    {
        long n = (long)M1 * F1_;
        ew_gelumul_kernel<<<(unsigned)((n + 255) / 256), 256>>>(gu1, gu1h, M1, F1_);
    }
    { TcArgs a{gu1h, wd1t, out1, nullptr, M1, D1_, F1_, EPI_RES_GATE};
      a.aux = r1;
      a.gvec = modpost + D1_; a.gstride = 2 * D1_; a.gdiv = S2_;
      launch_tc(a); }
}

// round 11
// speedup vs baseline: 4.1535x; 1.0819x over previous
#include <cuda_runtime.h>
#include <cuda_fp16.h>
#include <math.h>
#include <stdint.h>

// ---------------- problem constants ----------------
#define B_   4
#define S1_  768
#define S2_  64
#define S_   832
#define D0_  2048
#define F0_  16384
#define D1_  1024
#define F1_  4096
#define H_   8
#define HD_  256
#define EPS_ 1e-6f
#define MASK_VAL_ -1000000000.0f
#define MASK_H_  -60000.0f
#define NQKV_ (H_*HD_ + 2*HD_)   // 2560

// ---------------- scratch (device globals) ----------------
__device__ float g_mod_in[B_*2*D1_];
__device__ float g_mod_post[B_*2*D1_];
__device__ float g_q[(size_t)B_*S_*H_*HD_];
__device__ float g_k[B_*S_*HD_];
__device__ float g_v[B_*S_*HD_];
__device__ float g_r0[B_*S1_*D0_];
__device__ float g_r1[B_*S2_*D1_];
__device__ int   g_pos[B_*S_];
__device__ int   g_cs[B_*S_];
// fp16 operands
__device__ __half g_hc0[(size_t)B_*S1_*D0_];
__device__ __half g_hc1[B_*S2_*D1_];
__device__ __half g_qr[(size_t)B_*H_*S_*HD_];
__device__ __half g_kr[B_*S_*HD_];
__device__ __half g_vt[B_*HD_*S_];
__device__ __half g_ph[(size_t)B_*H_*S_*S_];
__device__ __half g_atth[(size_t)B_*S_*H_*HD_];
__device__ __half g_yc0[(size_t)B_*S1_*D0_];
__device__ __half g_yc1[B_*S2_*D1_];
__device__ __half g_gu0hg[(size_t)B_*S1_*F0_];   // gate0 fp16
__device__ __half g_gu0h[(size_t)B_*S1_*F0_];    // gelu(gate)*up fp16
__device__ __half g_gu1h2[(size_t)B_*S2_*2*F1_]; // fused gate|up fp16
__device__ __half g_gu1h[B_*S2_*F1_];
// transposed fp16 weights [N, K]
__device__ __half g_wqkv0t[(size_t)NQKV_*2048];
__device__ __half g_wqkv1t[(size_t)NQKV_*1024];
__device__ __half g_wo0t[(size_t)2048*2048];
__device__ __half g_wg0t[(size_t)16384*2048];
__device__ __half g_wu0t[(size_t)16384*2048];
__device__ __half g_wd0t[(size_t)2048*16384];
__device__ __half g_wo1t[(size_t)1024*2048];
__device__ __half g_wgu1t[(size_t)2*4096*1024];
__device__ __half g_wd1t[(size_t)1024*4096];

// ---------------- helpers ----------------
__device__ __forceinline__ float gelu_tanh(float x) {
    float x3 = x * x * x;
    return 0.5f * x * (1.0f + tanhf(0.79788456080286535588f * (x + 0.044715f * x3)));
}
__device__ __forceinline__ uint32_t smem_u32(const void* p) {
    uint32_t a;
    asm("{ .reg .u64 t; cvta.to.shared.u64 t, %1; cvt.u32.u64 %0, t; }" : "=r"(a) : "l"(p));
    return a;
}
#define CP_ASYNC16(sm, gm) \
    asm volatile("cp.async.cg.shared.global [%0], [%1], 16;" :: "r"(sm), "l"(gm))
#define CP_COMMIT() asm volatile("cp.async.commit_group;")
#define CP_WAIT(n)  asm volatile("cp.async.wait_group %0;" :: "n"(n))

__device__ __forceinline__ void ldsm_x4(uint32_t* r, uint32_t addr) {
    asm volatile("ldmatrix.sync.aligned.m8n8.x4.shared.b16 {%0,%1,%2,%3}, [%4];"
                 : "=r"(r[0]), "=r"(r[1]), "=r"(r[2]), "=r"(r[3]) : "r"(addr));
}
__device__ __forceinline__ void mma_f16(float* c, const uint32_t* a, uint32_t b0, uint32_t b1) {
    asm volatile("mma.sync.aligned.m16n8k16.row.col.f32.f16.f16.f32 "
                 "{%0,%1,%2,%3}, {%4,%5,%6,%7}, {%8,%9}, {%0,%1,%2,%3};"
                 : "+f"(c[0]), "+f"(c[1]), "+f"(c[2]), "+f"(c[3])
                 : "r"(a[0]), "r"(a[1]), "r"(a[2]), "r"(a[3]), "r"(b0), "r"(b1));
}
__device__ __forceinline__ uint32_t sw_addr(uint32_t base, int row, int chunk) {
    return base + (uint32_t)(((row << 3) + (chunk ^ (row & 7))) << 4);
}

// ---------------- epilogue modes ----------------
#define EPI_NONE        0
#define EPI_SCORES_H    1   // half Ch = masked+scaled
#define EPI_RES         2
#define EPI_RES_GATE    3
#define EPI_H           4
#define EPI_GELUMUL_HH  5   // half Ch = gelu(auxh)*v (auxh half)
#define EPI_QKV         6

// ---------------- TC fp16 GEMM: C[M,N] = A[M,Kp] * Bt[N,Kp]^T ----------------
struct TcP {
    const __half* A; const __half* Bt;
    float* C; __half* Ch;
    float* Ck; float* Cv;
    const float* aux; const __half* auxh; const float* gvec;
    const int *cs, *pad;
    size_t zA1, zA2, zB1, zB2, zC1, zC2, zAux, zGv;
    int zdiv;
    int gstride, gdiv;
    int maskStride; float scale;
    int M, N, Kp, epi;
    int rpb, obatch, ldc;
};

#define TC_STAGES 3
#define TC_STAGE_BYTES 32768
#define TC_SMEM (TC_STAGES * TC_STAGE_BYTES)

__global__ __launch_bounds__(256) void tc_gemm_kernel(TcP p) {
    extern __shared__ char dsm[];
    uint32_t sbase = smem_u32(dsm);

    int tid  = threadIdx.x;
    int wid  = tid >> 5;
    int lane = tid & 31;
    int wm = wid >> 2;
    int wn = wid & 3;

    int m0 = blockIdx.y * 128;
    int n0 = blockIdx.x * 128;
    int z  = blockIdx.z;
    int zb = z / p.zdiv;
    int zr = z - zb * p.zdiv;

    const __half* Ab = p.A  + (size_t)zb * p.zA1 + (size_t)zr * p.zA2;
    const __half* Bb = p.Bt + (size_t)zb * p.zB1 + (size_t)zr * p.zB2;

    int kc = tid & 7;
    int rb = tid >> 3;

    float acc[4][4][4];
    #pragma unroll
    for (int i = 0; i < 4; i++)
        #pragma unroll
        for (int j = 0; j < 4; j++)
            #pragma unroll
            for (int e = 0; e < 4; e++) acc[i][j][e] = 0.f;

    int nIter = p.Kp >> 6;

    auto issue = [&](int it) {
        int st = it % TC_STAGES;
        uint32_t sa = sbase + st * TC_STAGE_BYTES;
        uint32_t sb = sa + 16384;
        int k0 = it << 6;
        #pragma unroll
        for (int i = 0; i < 4; i++) {
            int row = rb + i * 32;
            int ra = m0 + row; if (ra > p.M - 1) ra = p.M - 1;
            CP_ASYNC16(sw_addr(sa, row, kc), Ab + (size_t)ra * p.Kp + k0 + kc * 8);
            int rn = n0 + row; if (rn > p.N - 1) rn = p.N - 1;
            CP_ASYNC16(sw_addr(sb, row, kc), Bb + (size_t)rn * p.Kp + k0 + kc * 8);
        }
        CP_COMMIT();
    };

    #pragma unroll
    for (int s = 0; s < TC_STAGES - 1; s++) issue(s);

    int grp = lane >> 3;
    int lr  = lane & 7;

    for (int it = 0; it < nIter; it++) {
        if (it + TC_STAGES - 1 < nIter) {
            issue(it + TC_STAGES - 1);
            CP_WAIT(TC_STAGES - 2);
        } else {
            CP_WAIT(0);
        }
        __syncthreads();

        int st = it % TC_STAGES;
        uint32_t sa = sbase + st * TC_STAGE_BYTES;
        uint32_t sb = sa + 16384;

        #pragma unroll
        for (int kb = 0; kb < 4; kb++) {
            int chA = 2 * kb + (grp >> 1);
            uint32_t a[4][4];
            #pragma unroll
            for (int mi = 0; mi < 4; mi++) {
                int row = wm * 64 + mi * 16 + (grp & 1) * 8 + lr;
                ldsm_x4(a[mi], sw_addr(sa, row, chA));
            }
            uint32_t bf[2][4];
            #pragma unroll
            for (int bi = 0; bi < 2; bi++) {
                int row = wn * 32 + bi * 16 + (grp & 1) * 8 + lr;
                ldsm_x4(bf[bi], sw_addr(sb, row, chA));
            }
            #pragma unroll
            for (int mi = 0; mi < 4; mi++)
                #pragma unroll
                for (int ni = 0; ni < 4; ni++) {
                    int bi = ni >> 1, wh = ni & 1;
                    mma_f16(acc[mi][ni], a[mi], bf[bi][wh], bf[bi][wh + 2]);
                }
        }
        __syncthreads();
    }

    // ---- epilogue ----
    const int* csb  = p.cs  ? p.cs  + (size_t)zb * p.maskStride : nullptr;
    const int* padb = p.pad ? p.pad + (size_t)zb * p.maskStride : nullptr;
    const float* auxz = p.aux ? p.aux + (size_t)zb * p.zAux : nullptr;
    const __half* auxhz = p.auxh ? p.auxh + (size_t)zb * p.zAux : nullptr;
    const float* gvz  = p.gvec ? p.gvec + (size_t)zb * p.zGv : nullptr;
    float* Cz = p.C + (size_t)zb * p.zC1 + (size_t)zr * p.zC2;
    __half* Chz = p.Ch + (size_t)zb * p.zC1 + (size_t)zr * p.zC2;
    int qrow = lane >> 2;
    int qcol = (lane & 3) * 2;
    #pragma unroll
    for (int mi = 0; mi < 4; mi++) {
        #pragma unroll
        for (int half_ = 0; half_ < 2; half_++) {
            int r = m0 + wm * 64 + mi * 16 + half_ * 8 + qrow;
            if (r >= p.M) continue;
            int orow = (r / p.rpb) * p.obatch + (r % p.rpb);
            #pragma unroll
            for (int ni = 0; ni < 4; ni++) {
                int col = n0 + wn * 32 + ni * 8 + qcol;
                if (col >= p.N) continue;
                float v0 = acc[mi][ni][half_ * 2 + 0];
                float v1 = acc[mi][ni][half_ * 2 + 1];
                if (p.epi == EPI_QKV) {
                    float2 ov = make_float2(v0, v1);
                    if (col < H_ * HD_)
                        *(float2*)&p.C[(size_t)orow * (H_ * HD_) + col] = ov;
                    else if (col < H_ * HD_ + HD_)
                        *(float2*)&p.Ck[(size_t)orow * HD_ + (col - H_ * HD_)] = ov;
                    else
                        *(float2*)&p.Cv[(size_t)orow * HD_ + (col - H_ * HD_ - HD_)] = ov;
                    continue;
                } else if (p.epi == EPI_H) {
                    __half2 hv; hv.x = __float2half(v0); hv.y = __float2half(v1);
                    *(__half2*)&Chz[(size_t)orow * p.ldc + col] = hv;
                    continue;
                } else if (p.epi == EPI_GELUMUL_HH) {
                    __half2 ah = *(const __half2*)&auxhz[(size_t)r * p.N + col];
                    __half2 hv;
                    hv.x = __float2half(gelu_tanh(__half2float(ah.x)) * v0);
                    hv.y = __float2half(gelu_tanh(__half2float(ah.y)) * v1);
                    *(__half2*)&Chz[(size_t)orow * p.ldc + col] = hv;
                    continue;
                } else if (p.epi == EPI_SCORES_H) {
                    int csr = csb[r];
                    bool okr = padb[r] != 0;
                    bool ok0 = (csb[col] <= csr) && okr && (padb[col] != 0);
                    bool ok1 = (csb[col + 1] <= csr) && okr && (padb[col + 1] != 0);
                    __half2 hv;
                    hv.x = __float2half(ok0 ? v0 * p.scale : MASK_H_);
                    hv.y = __float2half(ok1 ? v1 * p.scale : MASK_H_);
                    *(__half2*)&Chz[(size_t)orow * p.ldc + col] = hv;
                    continue;
                } else if (p.epi == EPI_RES) {
                    float2 ax = *(const float2*)&auxz[(size_t)r * p.N + col];
                    v0 += ax.x; v1 += ax.y;
                } else if (p.epi == EPI_RES_GATE) {
                    float2 ax = *(const float2*)&auxz[(size_t)r * p.N + col];
                    float2 gx = *(const float2*)&gvz[(size_t)(r / p.gdiv) * p.gstride + col];
                    v0 = ax.x + gx.x * v0;
                    v1 = ax.y + gx.y * v1;
                }
                *(float2*)&Cz[(size_t)orow * p.ldc + col] = make_float2(v0, v1);
            }
        }
    }
}

// ---------------- transpose fp32 -> fp16 (64k x 32n tile, half2 writes) ----------------
__global__ void wtrans_kernel(const float* __restrict__ W, __half* __restrict__ out,
                              int K, int N, size_t inZ, size_t outZ) {
    W   += blockIdx.z * inZ;
    out += blockIdx.z * outZ;
    __shared__ float t[64][33];
    int k0 = blockIdx.y * 64, n0 = blockIdx.x * 32;
    int tx = threadIdx.x, ty = threadIdx.y;   // 32 x 8
    #pragma unroll
    for (int i = 0; i < 8; i++)
        t[ty + i * 8][tx] = W[(size_t)(k0 + ty + i * 8) * N + n0 + tx];
    __syncthreads();
    #pragma unroll
    for (int j = 0; j < 4; j++) {
        int nl = j * 8 + ty;
        __half2 hv;
        hv.x = __float2half(t[2 * tx][nl]);
        hv.y = __float2half(t[2 * tx + 1][nl]);
        *(__half2*)&out[(size_t)(n0 + nl) * K + k0 + 2 * tx] = hv;
    }
}

// RoPE -> fp16 for Q: q[B,S,H,HD] -> qr[B,H,S,HD]
__global__ void rope_q_kernel(const float* __restrict__ q, const int* __restrict__ pos,
                              __half* __restrict__ out) {
    long idx = blockIdx.x * (long)blockDim.x + threadIdx.x;
    if (idx >= (long)B_ * H_ * S_ * 128) return;
    int i = (int)(idx & 127);
    long t = idx >> 7;
    int s = (int)(t % S_); t /= S_;
    int h = (int)(t % H_);
    int b = (int)(t / H_);
    const float* base = q + ((size_t)(b * S_ + s) * H_ + h) * HD_;
    float x1 = base[i], x2 = base[i + 128];
    float f = (float)pos[b * S_ + s] * expf(-((float)i / 128.0f) * 9.210340371976184f);
    float sn, c; sincosf(f, &sn, &c);
    __half* ob = out + ((size_t)(b * H_ + h) * S_ + s) * HD_;
    ob[i]       = __float2half(x1 * c - x2 * sn);
    ob[i + 128] = __float2half(x2 * c + x1 * sn);
}

// RoPE -> fp16 for K
__global__ void rope_k_kernel(const float* __restrict__ k, const int* __restrict__ pos,
                              __half* __restrict__ out) {
    long idx = blockIdx.x * (long)blockDim.x + threadIdx.x;
    if (idx >= (long)B_ * S_ * 128) return;
    int i = (int)(idx & 127);
    long t = idx >> 7;
    int s = (int)(t % S_);
    int b = (int)(t / S_);
    const float* base = k + (size_t)(b * S_ + s) * HD_;
    float x1 = base[i], x2 = base[i + 128];
    float f = (float)pos[b * S_ + s] * expf(-((float)i / 128.0f) * 9.210340371976184f);
    float sn, c; sincosf(f, &sn, &c);
    __half* ob = out + (size_t)(b * S_ + s) * HD_;
    ob[i]       = __float2half(x1 * c - x2 * sn);
    ob[i + 128] = __float2half(x2 * c + x1 * sn);
}

// elementwise: out[r][j] = half(gelu(gu[r][j]) * gu[r][F+j]), gu half [M][2F]
__global__ void ew_gelumul_kernel(const __half* __restrict__ gu, __half* __restrict__ out,
                                  int M, int F) {
    long idx = blockIdx.x * (long)blockDim.x + threadIdx.x;
    if (idx >= (long)M * F) return;
    int r = (int)(idx / F), j = (int)(idx % F);
    const __half* g = gu + (size_t)r * 2 * F;
    out[(size_t)r * F + j] =
        __float2half(gelu_tanh(__half2float(g[j])) * __half2float(g[F + j]));
}

// ---------------- mod GEMV (k-split x4 + smem reduce) ----------------
__global__ void mod_kernel(const float* __restrict__ cond, const float* __restrict__ W,
                           const float* __restrict__ bias, float* __restrict__ out,
                           int D, int N) {
    __shared__ float red[256];
    int tid = threadIdx.x;
    int j = blockIdx.x * 64 + (tid & 63);
    int ks = tid >> 6;            // 0..3
    int b = blockIdx.y;
    const float* c = cond + (size_t)b * D;
    int kseg = D >> 2;
    int kbeg = ks * kseg;
    float s = 0.f;
    for (int kk = kbeg; kk < kbeg + kseg; kk++)
        s += c[kk] * W[(size_t)kk * N + j];
    red[tid] = s;
    __syncthreads();
    if (ks == 0)
        out[(size_t)b * N + j] = bias[j] + red[tid] + red[tid + 64] + red[tid + 128] + red[tid + 192];
}

// ---------------- prefix scans ----------------
__global__ void scan_kernel(const int* __restrict__ pad, const int* __restrict__ att,
                            int* __restrict__ pos, int* __restrict__ cs) {
    int b = threadIdx.x;
    if (b >= B_) return;
    int cp = 0, ca = 0;
    for (int s = 0; s < S_; s++) {
        cp += pad[b * S_ + s];
        ca += att[b * S_ + s];
        pos[b * S_ + s] = cp - 1;
        cs[b * S_ + s] = ca;
    }
}

// ---------------- RMSNorm -> fp16 ----------------
__global__ void rmsnorm_kernel(const float* __restrict__ x, __half* __restrict__ out,
                               const float* __restrict__ w, int wStride,
                               int D, int rowsPerBatch) {
    long row = blockIdx.x;
    int b = (int)(row / rowsPerBatch);
    const float* xp = x + row * (long)D;
    float ss = 0.f;
    for (int i = threadIdx.x; i < D; i += blockDim.x) {
        float v = xp[i];
        ss += v * v;
    }
    __shared__ float red[256];
    red[threadIdx.x] = ss;
    __syncthreads();
    for (int s = 128; s > 0; s >>= 1) {
        if (threadIdx.x < s) red[threadIdx.x] += red[threadIdx.x + s];
        __syncthreads();
    }
    float r = rsqrtf(red[0] / (float)D + EPS_);
    const float* wp = w + (size_t)b * wStride;
    __half* op = out + row * (long)D;
    for (int i = threadIdx.x; i < D; i += blockDim.x)
        op[i] = __float2half(xp[i] * r * (1.0f + wp[i]));
}

// ---------------- row softmax on fp16 in-place ----------------
__global__ void softmax_h_kernel(__half* __restrict__ probs) {
    __half* p = probs + (size_t)blockIdx.x * S_;
    __shared__ float red[256];
    int tid = threadIdx.x;
    float loc[4];
    float m = -3.4e38f;
    for (int c = 0, i = tid; i < S_; i += 256, c++) {
        loc[c] = __half2float(p[i]);
        m = fmaxf(m, loc[c]);
    }
    red[tid] = m;
    __syncthreads();
    for (int s = 128; s > 0; s >>= 1) {
        if (tid < s) red[tid] = fmaxf(red[tid], red[tid + s]);
        __syncthreads();
    }
    m = red[0];
    __syncthreads();
    float sum = 0.f;
    for (int c = 0, i = tid; i < S_; i += 256, c++) {
        float e = expf(loc[c] - m);
        loc[c] = e;
        sum += e;
    }
    red[tid] = sum;
    __syncthreads();
    for (int s = 128; s > 0; s >>= 1) {
        if (tid < s) red[tid] += red[tid + s];
        __syncthreads();
    }
    float inv = 1.0f / red[0];
    for (int c = 0, i = tid; i < S_; i += 256, c++)
        p[i] = __float2half(loc[c] * inv);
}

// ---------------- host helper ----------------
// new members at the TAIL (positional-init safety)
struct TcArgs {
    const __half* A; const __half* Bt;
    float* C; __half* Ch = nullptr;
    int M = 0, N = 0, Kp = 0, epi = 0;
    const float* aux = nullptr;
    int rpb = 0, obatch = 0, ldc = 0;
    int zcount = 1, zdiv = 1;
    size_t zA1 = 0, zA2 = 0, zB1 = 0, zB2 = 0, zC1 = 0, zC2 = 0, zAux = 0, zGv = 0;
    const int* cs = nullptr; const int* pad = nullptr;
    int maskStride = 0; float scale = 1.0f;
    const float* gvec = nullptr; int gstride = 0, gdiv = 1;
    float* Ck = nullptr; float* Cv = nullptr;
    const __half* auxh = nullptr;
};

static void launch_tc(const TcArgs& a) {
    cudaFuncSetAttribute(tc_gemm_kernel, cudaFuncAttributeMaxDynamicSharedMemorySize, TC_SMEM);
    TcP p;
    p.A = a.A; p.Bt = a.Bt; p.C = a.C; p.Ch = a.Ch; p.Ck = a.Ck; p.Cv = a.Cv;
    p.aux = a.aux; p.auxh = a.auxh; p.gvec = a.gvec;
    p.cs = a.cs; p.pad = a.pad;
    p.zA1 = a.zA1; p.zA2 = a.zA2; p.zB1 = a.zB1; p.zB2 = a.zB2;
    p.zC1 = a.zC1; p.zC2 = a.zC2; p.zAux = a.zAux; p.zGv = a.zGv;
    p.zdiv = a.zdiv; p.gstride = a.gstride; p.gdiv = a.gdiv;
    p.maskStride = a.maskStride; p.scale = a.scale;
    p.M = a.M; p.N = a.N; p.Kp = a.Kp; p.epi = a.epi;
    p.rpb = a.rpb ? a.rpb : a.M; p.obatch = a.obatch; p.ldc = a.ldc ? a.ldc : a.N;
    dim3 grid((a.N + 127) / 128, (a.M + 127) / 128, a.zcount);
    tc_gemm_kernel<<<grid, 256, TC_SMEM>>>(p);
}

static void launch_wtrans(const float* W, __half* out, int K, int N,
                          int z = 1, size_t inZ = 0, size_t outZ = 0) {
    dim3 grid(N / 32, K / 64, z);
    wtrans_kernel<<<grid, dim3(32, 8)>>>(W, out, K, N, inZ, outZ);
}

extern "C" void kernel_launch(void* const* d_in, const int* in_sizes, int n_in,
                              void* d_out, int out_size) {
    const float* x0         = (const float*)d_in[0];
    const float* x1         = (const float*)d_in[1];
    const float* cond1      = (const float*)d_in[2];
    const float* w_q0       = (const float*)d_in[3];
    const float* w_k0       = (const float*)d_in[4];
    const float* w_v0       = (const float*)d_in[5];
    const float* w_o0       = (const float*)d_in[6];
    const float* norm1_w0   = (const float*)d_in[7];
    const float* norm2_w0   = (const float*)d_in[8];
    const float* w_gate0    = (const float*)d_in[9];
    const float* w_up0      = (const float*)d_in[10];
    const float* w_down0    = (const float*)d_in[11];
    const float* w_q1       = (const float*)d_in[12];
    const float* w_k1       = (const float*)d_in[13];
    const float* w_v1       = (const float*)d_in[14];
    const float* w_o1       = (const float*)d_in[15];
    const float* ada_in_w1  = (const float*)d_in[16];
    const float* ada_in_b1  = (const float*)d_in[17];
    const float* ada_post_w1= (const float*)d_in[18];
    const float* ada_post_b1= (const float*)d_in[19];
    const float* w_gate1    = (const float*)d_in[20];
    const float* w_up1      = (const float*)d_in[21];
    const float* w_down1    = (const float*)d_in[22];
    const int*   pad_masks  = (const int*)d_in[23];
    const int*   att_masks  = (const int*)d_in[24];

    float* out0 = (float*)d_out;
    float* out1 = out0 + (size_t)B_ * S1_ * D0_;

    float *modin, *modpost, *q, *k, *v, *r0, *r1;
    int *pos, *cs;
    __half *hc0, *hc1, *qr, *kr, *vt, *ph, *atth, *yc0, *yc1;
    __half *gu0hg, *gu0h, *gu1h2, *gu1h;
    __half *wqkv0t, *wqkv1t, *wo0t, *wg0t, *wu0t, *wd0t, *wo1t, *wgu1t, *wd1t;
    cudaGetSymbolAddress((void**)&modin, g_mod_in);
    cudaGetSymbolAddress((void**)&modpost, g_mod_post);
    cudaGetSymbolAddress((void**)&q, g_q);
    cudaGetSymbolAddress((void**)&k, g_k);
    cudaGetSymbolAddress((void**)&v, g_v);
    cudaGetSymbolAddress((void**)&r0, g_r0);
    cudaGetSymbolAddress((void**)&r1, g_r1);
    cudaGetSymbolAddress((void**)&pos, g_pos);
    cudaGetSymbolAddress((void**)&cs, g_cs);
    cudaGetSymbolAddress((void**)&hc0, g_hc0);
    cudaGetSymbolAddress((void**)&hc1, g_hc1);
    cudaGetSymbolAddress((void**)&qr, g_qr);
    cudaGetSymbolAddress((void**)&kr, g_kr);
    cudaGetSymbolAddress((void**)&vt, g_vt);
    cudaGetSymbolAddress((void**)&ph, g_ph);
    cudaGetSymbolAddress((void**)&atth, g_atth);
    cudaGetSymbolAddress((void**)&yc0, g_yc0);
    cudaGetSymbolAddress((void**)&yc1, g_yc1);
    cudaGetSymbolAddress((void**)&gu0hg, g_gu0hg);
    cudaGetSymbolAddress((void**)&gu0h, g_gu0h);
    cudaGetSymbolAddress((void**)&gu1h2, g_gu1h2);
    cudaGetSymbolAddress((void**)&gu1h, g_gu1h);
    cudaGetSymbolAddress((void**)&wqkv0t, g_wqkv0t);
    cudaGetSymbolAddress((void**)&wqkv1t, g_wqkv1t);
    cudaGetSymbolAddress((void**)&wo0t, g_wo0t);
    cudaGetSymbolAddress((void**)&wg0t, g_wg0t);
    cudaGetSymbolAddress((void**)&wu0t, g_wu0t);
    cudaGetSymbolAddress((void**)&wd0t, g_wd0t);
    cudaGetSymbolAddress((void**)&wo1t, g_wo1t);
    cudaGetSymbolAddress((void**)&wgu1t, g_wgu1t);
    cudaGetSymbolAddress((void**)&wd1t, g_wd1t);

    const int M0 = B_ * S1_;   // 3072
    const int M1 = B_ * S2_;   // 256

    // ---- weight prep (transpose + fp16) into fused buffers ----
    launch_wtrans(w_q0, wqkv0t, D0_, H_ * HD_);
    launch_wtrans(w_k0, wqkv0t + (size_t)(H_ * HD_) * D0_, D0_, HD_);
    launch_wtrans(w_v0, wqkv0t + (size_t)(H_ * HD_ + HD_) * D0_, D0_, HD_);
    launch_wtrans(w_o0,    wo0t, H_ * HD_, D0_);
    launch_wtrans(w_gate0, wg0t, D0_, F0_);
    launch_wtrans(w_up0,   wu0t, D0_, F0_);
    launch_wtrans(w_down0, wd0t, F0_, D0_);
    launch_wtrans(w_q1, wqkv1t, D1_, H_ * HD_);
    launch_wtrans(w_k1, wqkv1t + (size_t)(H_ * HD_) * D1_, D1_, HD_);
    launch_wtrans(w_v1, wqkv1t + (size_t)(H_ * HD_ + HD_) * D1_, D1_, HD_);
    launch_wtrans(w_o1,    wo1t, H_ * HD_, D1_);
    launch_wtrans(w_gate1, wgu1t, D1_, F1_);
    launch_wtrans(w_up1,   wgu1t + (size_t)F1_ * D1_, D1_, F1_);
    launch_wtrans(w_down1, wd1t, F1_, D1_);

    // ---- adaLN modulation + scans ----
    {
        dim3 mg(2 * D1_ / 64, B_);
        mod_kernel<<<mg, 256>>>(cond1, ada_in_w1,   ada_in_b1,   modin,   D1_, 2 * D1_);
        mod_kernel<<<mg, 256>>>(cond1, ada_post_w1, ada_post_b1, modpost, D1_, 2 * D1_);
    }
    scan_kernel<<<1, 32>>>(pad_masks, att_masks, pos, cs);

    // ---- input norms -> fp16 ----
    rmsnorm_kernel<<<M0, 256>>>(x0, hc0, norm1_w0, 0, D0_, S1_);
    rmsnorm_kernel<<<M1, 256>>>(x1, hc1, modin, 2 * D1_, D1_, S2_);

    // ---- fused QKV projections (column-routed, row remap into S=832 layout) ----
    { TcArgs a{hc0, wqkv0t, q, nullptr, M0, NQKV_, D0_, EPI_QKV};
      a.Ck = k; a.Cv = v;
      a.rpb = S1_; a.obatch = S_; launch_tc(a); }
    { TcArgs a{hc1, wqkv1t, q + (size_t)S1_ * H_ * HD_, nullptr, M1, NQKV_, D1_, EPI_QKV};
      a.Ck = k + (size_t)S1_ * HD_; a.Cv = v + (size_t)S1_ * HD_;
      a.rpb = S2_; a.obatch = S_; launch_tc(a); }

    // ---- RoPE (-> fp16) and V transpose (-> fp16) ----
    {
        long nq = (long)B_ * H_ * S_ * 128;
        rope_q_kernel<<<(unsigned)((nq + 255) / 256), 256>>>(q, pos, qr);
        long nk = (long)B_ * S_ * 128;
        rope_k_kernel<<<(unsigned)((nk + 255) / 256), 256>>>(k, pos, kr);
        launch_wtrans(v, vt, S_, HD_, B_, (size_t)S_ * HD_, (size_t)HD_ * S_);
    }

    // ---- scores = Q K^T * scale, masked -> fp16 ph (z = B*H) ----
    { TcArgs a{qr, kr, nullptr, ph, S_, S_, HD_, EPI_SCORES_H};
      a.zcount = B_ * H_; a.zdiv = H_;
      a.zA1 = (size_t)H_ * S_ * HD_; a.zA2 = (size_t)S_ * HD_;
      a.zB1 = (size_t)S_ * HD_;
      a.zC1 = (size_t)H_ * S_ * S_; a.zC2 = (size_t)S_ * S_;
      a.cs = cs; a.pad = pad_masks; a.maskStride = S_; a.scale = 0.0625f;
      launch_tc(a); }

    softmax_h_kernel<<<B_ * H_ * S_, 256>>>(ph);

    // ---- PV (z = B*H) -> atth [B,S,H*HD] fp16 ----
    { TcArgs a{ph, vt, nullptr, atth, S_, HD_, S_, EPI_H};
      a.ldc = H_ * HD_;
      a.zcount = B_ * H_; a.zdiv = H_;
      a.zA1 = (size_t)H_ * S_ * S_; a.zA2 = (size_t)S_ * S_;
      a.zB1 = (size_t)HD_ * S_;
      a.zC1 = (size_t)S_ * H_ * HD_; a.zC2 = (size_t)HD_;
      launch_tc(a); }

    // ---- output projections (z = B) ----
    { TcArgs a{atth, wo0t, r0, nullptr, S1_, D0_, H_ * HD_, EPI_RES};
      a.aux = x0;
      a.zcount = B_;
      a.zA1 = (size_t)S_ * H_ * HD_; a.zC1 = (size_t)S1_ * D0_; a.zAux = (size_t)S1_ * D0_;
      launch_tc(a); }
    { TcArgs a{atth + (size_t)S1_ * H_ * HD_, wo1t, r1, nullptr, S2_, D1_, H_ * HD_, EPI_RES_GATE};
      a.aux = x1;
      a.zcount = B_;
      a.zA1 = (size_t)S_ * H_ * HD_; a.zC1 = (size_t)S2_ * D1_; a.zAux = (size_t)S2_ * D1_;
      a.gvec = modin + D1_; a.zGv = (size_t)2 * D1_; a.gdiv = S2_; a.gstride = 0;
      launch_tc(a); }

    // ---- post norms -> fp16 ----
    rmsnorm_kernel<<<M0, 256>>>(r0, yc0, norm2_w0, 0, D0_, S1_);
    rmsnorm_kernel<<<M1, 256>>>(r1, yc1, modpost, 2 * D1_, D1_, S2_);

    // ---- MLP stream 0 (gate fp16 -> gelu-mul in up epilogue -> down) ----
    { TcArgs a{yc0, wg0t, nullptr, gu0hg, M0, F0_, D0_, EPI_H}; launch_tc(a); }
    { TcArgs a{yc0, wu0t, nullptr, gu0h, M0, F0_, D0_, EPI_GELUMUL_HH}; a.auxh = gu0hg; launch_tc(a); }
    { TcArgs a{gu0h, wd0t, out0, nullptr, M0, D0_, F0_, EPI_RES}; a.aux = r0; launch_tc(a); }

    // ---- MLP stream 1 (fused gate|up fp16, elementwise, down) ----
    { TcArgs a{yc1, wgu1t, nullptr, gu1h2, M1, 2 * F1_, D1_, EPI_H}; launch_tc(a); }
    {
        long n = (long)M1 * F1_;
        ew_gelumul_kernel<<<(unsigned)((n + 255) / 256), 256>>>(gu1h2, gu1h, M1, F1_);
    }
    { TcArgs a{gu1h, wd1t, out1, nullptr, M1, D1_, F1_, EPI_RES_GATE};
      a.aux = r1;
      a.gvec = modpost + D1_; a.gstride = 2 * D1_; a.gdiv = S2_;
      launch_tc(a); }
}

// round 12
// speedup vs baseline: 4.1654x; 1.0029x over previous
#include <cuda_runtime.h>
#include <cuda_fp16.h>
#include <math.h>
#include <stdint.h>

// ---------------- problem constants ----------------
#define B_   4
#define S1_  768
#define S2_  64
#define S_   832
#define D0_  2048
#define F0_  16384
#define D1_  1024
#define F1_  4096
#define H_   8
#define HD_  256
#define EPS_ 1e-6f
#define MASK_H_  -60000.0f
#define NQKV_ (H_*HD_ + 2*HD_)   // 2560

// ---------------- scratch (device globals) ----------------
__device__ float g_mod_in[B_*2*D1_];
__device__ float g_mod_post[B_*2*D1_];
__device__ float g_q[(size_t)B_*S_*H_*HD_];
__device__ float g_k[B_*S_*HD_];
__device__ float g_v[B_*S_*HD_];
__device__ float g_r0[B_*S1_*D0_];
__device__ float g_r1[B_*S2_*D1_];
__device__ int   g_pos[B_*S_];
__device__ int   g_cs[B_*S_];
// fp16 operands
__device__ __half g_hc0[(size_t)B_*S1_*D0_];
__device__ __half g_hc1[B_*S2_*D1_];
__device__ __half g_qr[(size_t)B_*H_*S_*HD_];
__device__ __half g_kr[B_*S_*HD_];
__device__ __half g_vt[B_*HD_*S_];
__device__ __half g_ph[(size_t)B_*H_*S_*S_];
__device__ __half g_atth[(size_t)B_*S_*H_*HD_];
__device__ __half g_yc0[(size_t)B_*S1_*D0_];
__device__ __half g_yc1[B_*S2_*D1_];
__device__ __half g_gu0hg[(size_t)B_*S1_*F0_];
__device__ __half g_gu0h[(size_t)B_*S1_*F0_];
__device__ __half g_gu1h2[(size_t)B_*S2_*2*F1_];
__device__ __half g_gu1h[B_*S2_*F1_];
// transposed fp16 weights [N, K]
__device__ __half g_wqkv0t[(size_t)NQKV_*2048];
__device__ __half g_wqkv1t[(size_t)NQKV_*1024];
__device__ __half g_wo0t[(size_t)2048*2048];
__device__ __half g_wg0t[(size_t)16384*2048];
__device__ __half g_wu0t[(size_t)16384*2048];
__device__ __half g_wd0t[(size_t)2048*16384];
__device__ __half g_wo1t[(size_t)1024*2048];
__device__ __half g_wgu1t[(size_t)2*4096*1024];
__device__ __half g_wd1t[(size_t)1024*4096];

// ---------------- helpers ----------------
__device__ __forceinline__ float gelu_tanh(float x) {
    float x3 = x * x * x;
    return 0.5f * x * (1.0f + tanhf(0.79788456080286535588f * (x + 0.044715f * x3)));
}
__device__ __forceinline__ uint32_t smem_u32(const void* p) {
    uint32_t a;
    asm("{ .reg .u64 t; cvta.to.shared.u64 t, %1; cvt.u32.u64 %0, t; }" : "=r"(a) : "l"(p));
    return a;
}
#define CP_ASYNC16(sm, gm) \
    asm volatile("cp.async.cg.shared.global [%0], [%1], 16;" :: "r"(sm), "l"(gm))
#define CP_COMMIT() asm volatile("cp.async.commit_group;")
#define CP_WAIT(n)  asm volatile("cp.async.wait_group %0;" :: "n"(n))

__device__ __forceinline__ void ldsm_x4(uint32_t* r, uint32_t addr) {
    asm volatile("ldmatrix.sync.aligned.m8n8.x4.shared.b16 {%0,%1,%2,%3}, [%4];"
                 : "=r"(r[0]), "=r"(r[1]), "=r"(r[2]), "=r"(r[3]) : "r"(addr));
}
__device__ __forceinline__ void mma_f16(float* c, const uint32_t* a, uint32_t b0, uint32_t b1) {
    asm volatile("mma.sync.aligned.m16n8k16.row.col.f32.f16.f16.f32 "
                 "{%0,%1,%2,%3}, {%4,%5,%6,%7}, {%8,%9}, {%0,%1,%2,%3};"
                 : "+f"(c[0]), "+f"(c[1]), "+f"(c[2]), "+f"(c[3])
                 : "r"(a[0]), "r"(a[1]), "r"(a[2]), "r"(a[3]), "r"(b0), "r"(b1));
}
__device__ __forceinline__ uint32_t sw_addr(uint32_t base, int row, int chunk) {
    return base + (uint32_t)(((row << 3) + (chunk ^ (row & 7))) << 4);
}

// ---------------- epilogue modes ----------------
#define EPI_NONE        0
#define EPI_SCORES_H    1
#define EPI_RES         2
#define EPI_RES_GATE    3
#define EPI_H           4
#define EPI_GELUMUL_HH  5
#define EPI_QKV         6

// ---------------- TC fp16 GEMM: C[M,N] = A[M,Kp] * Bt[N,Kp]^T ----------------
struct TcP {
    const __half* A; const __half* Bt;
    float* C; __half* Ch;
    float* Ck; float* Cv;
    const float* aux; const __half* auxh; const float* gvec;
    const int *cs, *pad;
    size_t zA1, zA2, zB1, zB2, zC1, zC2, zAux, zGv;
    int zdiv;
    int gstride, gdiv;
    int maskStride; float scale;
    int M, N, Kp, epi;
    int rpb, obatch, ldc;
};

#define TC_STAGES 3
#define TC_STAGE_BYTES 32768
#define TC_SMEM (TC_STAGES * TC_STAGE_BYTES)

__global__ __launch_bounds__(256) void tc_gemm_kernel(TcP p) {
    extern __shared__ char dsm[];
    uint32_t sbase = smem_u32(dsm);

    int tid  = threadIdx.x;
    int wid  = tid >> 5;
    int lane = tid & 31;
    int wm = wid >> 2;
    int wn = wid & 3;

    int m0 = blockIdx.y * 128;
    int n0 = blockIdx.x * 128;
    int z  = blockIdx.z;
    int zb = z / p.zdiv;
    int zr = z - zb * p.zdiv;

    const __half* Ab = p.A  + (size_t)zb * p.zA1 + (size_t)zr * p.zA2;
    const __half* Bb = p.Bt + (size_t)zb * p.zB1 + (size_t)zr * p.zB2;

    int kc = tid & 7;
    int rb = tid >> 3;

    float acc[4][4][4];
    #pragma unroll
    for (int i = 0; i < 4; i++)
        #pragma unroll
        for (int j = 0; j < 4; j++)
            #pragma unroll
            for (int e = 0; e < 4; e++) acc[i][j][e] = 0.f;

    int nIter = p.Kp >> 6;

    auto issue = [&](int it) {
        int st = it % TC_STAGES;
        uint32_t sa = sbase + st * TC_STAGE_BYTES;
        uint32_t sb = sa + 16384;
        int k0 = it << 6;
        #pragma unroll
        for (int i = 0; i < 4; i++) {
            int row = rb + i * 32;
            int ra = m0 + row; if (ra > p.M - 1) ra = p.M - 1;
            CP_ASYNC16(sw_addr(sa, row, kc), Ab + (size_t)ra * p.Kp + k0 + kc * 8);
            int rn = n0 + row; if (rn > p.N - 1) rn = p.N - 1;
            CP_ASYNC16(sw_addr(sb, row, kc), Bb + (size_t)rn * p.Kp + k0 + kc * 8);
        }
        CP_COMMIT();
    };

    #pragma unroll
    for (int s = 0; s < TC_STAGES - 1; s++) issue(s);

    int grp = lane >> 3;
    int lr  = lane & 7;

    for (int it = 0; it < nIter; it++) {
        if (it + TC_STAGES - 1 < nIter) {
            issue(it + TC_STAGES - 1);
            CP_WAIT(TC_STAGES - 2);
        } else {
            CP_WAIT(0);
        }
        __syncthreads();

        int st = it % TC_STAGES;
        uint32_t sa = sbase + st * TC_STAGE_BYTES;
        uint32_t sb = sa + 16384;

        #pragma unroll
        for (int kb = 0; kb < 4; kb++) {
            int chA = 2 * kb + (grp >> 1);
            uint32_t a[4][4];
            #pragma unroll
            for (int mi = 0; mi < 4; mi++) {
                int row = wm * 64 + mi * 16 + (grp & 1) * 8 + lr;
                ldsm_x4(a[mi], sw_addr(sa, row, chA));
            }
            uint32_t bf[2][4];
            #pragma unroll
            for (int bi = 0; bi < 2; bi++) {
                int row = wn * 32 + bi * 16 + (grp & 1) * 8 + lr;
                ldsm_x4(bf[bi], sw_addr(sb, row, chA));
            }
            #pragma unroll
            for (int mi = 0; mi < 4; mi++)
                #pragma unroll
                for (int ni = 0; ni < 4; ni++) {
                    int bi = ni >> 1, wh = ni & 1;
                    mma_f16(acc[mi][ni], a[mi], bf[bi][wh], bf[bi][wh + 2]);
                }
        }
        __syncthreads();
    }

    // ---- epilogue ----
    const int* csb  = p.cs  ? p.cs  + (size_t)zb * p.maskStride : nullptr;
    const int* padb = p.pad ? p.pad + (size_t)zb * p.maskStride : nullptr;
    const float* auxz = p.aux ? p.aux + (size_t)zb * p.zAux : nullptr;
    const __half* auxhz = p.auxh ? p.auxh + (size_t)zb * p.zAux : nullptr;
    const float* gvz  = p.gvec ? p.gvec + (size_t)zb * p.zGv : nullptr;
    float* Cz = p.C + (size_t)zb * p.zC1 + (size_t)zr * p.zC2;
    __half* Chz = p.Ch + (size_t)zb * p.zC1 + (size_t)zr * p.zC2;
    int qrow = lane >> 2;
    int qcol = (lane & 3) * 2;
    #pragma unroll
    for (int mi = 0; mi < 4; mi++) {
        #pragma unroll
        for (int half_ = 0; half_ < 2; half_++) {
            int r = m0 + wm * 64 + mi * 16 + half_ * 8 + qrow;
            if (r >= p.M) continue;
            int orow = (r / p.rpb) * p.obatch + (r % p.rpb);
            #pragma unroll
            for (int ni = 0; ni < 4; ni++) {
                int col = n0 + wn * 32 + ni * 8 + qcol;
                if (col >= p.N) continue;
                float v0 = acc[mi][ni][half_ * 2 + 0];
                float v1 = acc[mi][ni][half_ * 2 + 1];
                if (p.epi == EPI_QKV) {
                    float2 ov = make_float2(v0, v1);
                    if (col < H_ * HD_)
                        *(float2*)&p.C[(size_t)orow * (H_ * HD_) + col] = ov;
                    else if (col < H_ * HD_ + HD_)
                        *(float2*)&p.Ck[(size_t)orow * HD_ + (col - H_ * HD_)] = ov;
                    else
                        *(float2*)&p.Cv[(size_t)orow * HD_ + (col - H_ * HD_ - HD_)] = ov;
                    continue;
                } else if (p.epi == EPI_H) {
                    __half2 hv; hv.x = __float2half(v0); hv.y = __float2half(v1);
                    *(__half2*)&Chz[(size_t)orow * p.ldc + col] = hv;
                    continue;
                } else if (p.epi == EPI_GELUMUL_HH) {
                    __half2 ah = *(const __half2*)&auxhz[(size_t)r * p.N + col];
                    __half2 hv;
                    hv.x = __float2half(gelu_tanh(__half2float(ah.x)) * v0);
                    hv.y = __float2half(gelu_tanh(__half2float(ah.y)) * v1);
                    *(__half2*)&Chz[(size_t)orow * p.ldc + col] = hv;
                    continue;
                } else if (p.epi == EPI_SCORES_H) {
                    int csr = csb[r];
                    bool okr = padb[r] != 0;
                    bool ok0 = (csb[col] <= csr) && okr && (padb[col] != 0);
                    bool ok1 = (csb[col + 1] <= csr) && okr && (padb[col + 1] != 0);
                    __half2 hv;
                    hv.x = __float2half(ok0 ? v0 * p.scale : MASK_H_);
                    hv.y = __float2half(ok1 ? v1 * p.scale : MASK_H_);
                    *(__half2*)&Chz[(size_t)orow * p.ldc + col] = hv;
                    continue;
                } else if (p.epi == EPI_RES) {
                    float2 ax = *(const float2*)&auxz[(size_t)r * p.N + col];
                    v0 += ax.x; v1 += ax.y;
                } else if (p.epi == EPI_RES_GATE) {
                    float2 ax = *(const float2*)&auxz[(size_t)r * p.N + col];
                    float2 gx = *(const float2*)&gvz[(size_t)(r / p.gdiv) * p.gstride + col];
                    v0 = ax.x + gx.x * v0;
                    v1 = ax.y + gx.y * v1;
                }
                *(float2*)&Cz[(size_t)orow * p.ldc + col] = make_float2(v0, v1);
            }
        }
    }
}

// ---------------- transpose fp32 -> fp16 (64k x 32n tile, half2 writes) ----------------
__global__ void wtrans_kernel(const float* __restrict__ W, __half* __restrict__ out,
                              int K, int N, size_t inZ, size_t outZ) {
    W   += blockIdx.z * inZ;
    out += blockIdx.z * outZ;
    __shared__ float t[64][33];
    int k0 = blockIdx.y * 64, n0 = blockIdx.x * 32;
    int tx = threadIdx.x, ty = threadIdx.y;   // 32 x 8
    #pragma unroll
    for (int i = 0; i < 8; i++)
        t[ty + i * 8][tx] = W[(size_t)(k0 + ty + i * 8) * N + n0 + tx];
    __syncthreads();
    #pragma unroll
    for (int j = 0; j < 4; j++) {
        int nl = j * 8 + ty;
        __half2 hv;
        hv.x = __float2half(t[2 * tx][nl]);
        hv.y = __float2half(t[2 * tx + 1][nl]);
        *(__half2*)&out[(size_t)(n0 + nl) * K + k0 + 2 * tx] = hv;
    }
}

// RoPE -> fp16 for Q: q[B,S,H,HD] -> qr[B,H,S,HD]
__global__ void rope_q_kernel(const float* __restrict__ q, const int* __restrict__ pos,
                              __half* __restrict__ out) {
    long idx = blockIdx.x * (long)blockDim.x + threadIdx.x;
    if (idx >= (long)B_ * H_ * S_ * 128) return;
    int i = (int)(idx & 127);
    long t = idx >> 7;
    int s = (int)(t % S_); t /= S_;
    int h = (int)(t % H_);
    int b = (int)(t / H_);
    const float* base = q + ((size_t)(b * S_ + s) * H_ + h) * HD_;
    float x1 = base[i], x2 = base[i + 128];
    float f = (float)pos[b * S_ + s] * expf(-((float)i / 128.0f) * 9.210340371976184f);
    float sn, c; sincosf(f, &sn, &c);
    __half* ob = out + ((size_t)(b * H_ + h) * S_ + s) * HD_;
    ob[i]       = __float2half(x1 * c - x2 * sn);
    ob[i + 128] = __float2half(x2 * c + x1 * sn);
}

// RoPE -> fp16 for K
__global__ void rope_k_kernel(const float* __restrict__ k, const int* __restrict__ pos,
                              __half* __restrict__ out) {
    long idx = blockIdx.x * (long)blockDim.x + threadIdx.x;
    if (idx >= (long)B_ * S_ * 128) return;
    int i = (int)(idx & 127);
    long t = idx >> 7;
    int s = (int)(t % S_);
    int b = (int)(t / S_);
    const float* base = k + (size_t)(b * S_ + s) * HD_;
    float x1 = base[i], x2 = base[i + 128];
    float f = (float)pos[b * S_ + s] * expf(-((float)i / 128.0f) * 9.210340371976184f);
    float sn, c; sincosf(f, &sn, &c);
    __half* ob = out + (size_t)(b * S_ + s) * HD_;
    ob[i]       = __float2half(x1 * c - x2 * sn);
    ob[i + 128] = __float2half(x2 * c + x1 * sn);
}

// elementwise: out[r][j] = half(gelu(gu[r][j]) * gu[r][F+j]), gu half [M][2F]
__global__ void ew_gelumul_kernel(const __half* __restrict__ gu, __half* __restrict__ out,
                                  int M, int F) {
    long idx = blockIdx.x * (long)blockDim.x + threadIdx.x;
    if (idx >= (long)M * F) return;
    int r = (int)(idx / F), j = (int)(idx % F);
    const __half* g = gu + (size_t)r * 2 * F;
    out[(size_t)r * F + j] =
        __float2half(gelu_tanh(__half2float(g[j])) * __half2float(g[F + j]));
}

// ---------------- mod GEMV (k-split x4 + smem reduce) ----------------
__global__ void mod_kernel(const float* __restrict__ cond, const float* __restrict__ W,
                           const float* __restrict__ bias, float* __restrict__ out,
                           int D, int N) {
    __shared__ float red[256];
    int tid = threadIdx.x;
    int j = blockIdx.x * 64 + (tid & 63);
    int ks = tid >> 6;
    int b = blockIdx.y;
    const float* c = cond + (size_t)b * D;
    int kseg = D >> 2;
    int kbeg = ks * kseg;
    float s = 0.f;
    for (int kk = kbeg; kk < kbeg + kseg; kk++)
        s += c[kk] * W[(size_t)kk * N + j];
    red[tid] = s;
    __syncthreads();
    if (ks == 0)
        out[(size_t)b * N + j] = bias[j] + red[tid] + red[tid + 64] + red[tid + 128] + red[tid + 192];
}

// ---------------- prefix scans ----------------
__global__ void scan_kernel(const int* __restrict__ pad, const int* __restrict__ att,
                            int* __restrict__ pos, int* __restrict__ cs) {
    int b = threadIdx.x;
    if (b >= B_) return;
    int cp = 0, ca = 0;
    for (int s = 0; s < S_; s++) {
        cp += pad[b * S_ + s];
        ca += att[b * S_ + s];
        pos[b * S_ + s] = cp - 1;
        cs[b * S_ + s] = ca;
    }
}

// ---------------- RMSNorm -> fp16 ----------------
__global__ void rmsnorm_kernel(const float* __restrict__ x, __half* __restrict__ out,
                               const float* __restrict__ w, int wStride,
                               int D, int rowsPerBatch) {
    long row = blockIdx.x;
    int b = (int)(row / rowsPerBatch);
    const float* xp = x + row * (long)D;
    float ss = 0.f;
    for (int i = threadIdx.x; i < D; i += blockDim.x) {
        float v = xp[i];
        ss += v * v;
    }
    __shared__ float red[256];
    red[threadIdx.x] = ss;
    __syncthreads();
    for (int s = 128; s > 0; s >>= 1) {
        if (threadIdx.x < s) red[threadIdx.x] += red[threadIdx.x + s];
        __syncthreads();
    }
    float r = rsqrtf(red[0] / (float)D + EPS_);
    const float* wp = w + (size_t)b * wStride;
    __half* op = out + row * (long)D;
    for (int i = threadIdx.x; i < D; i += blockDim.x)
        op[i] = __float2half(xp[i] * r * (1.0f + wp[i]));
}

// ---------------- row softmax on fp16 in-place ----------------
__global__ void softmax_h_kernel(__half* __restrict__ probs) {
    __half* p = probs + (size_t)blockIdx.x * S_;
    __shared__ float red[256];
    int tid = threadIdx.x;
    float loc[4];
    float m = -3.4e38f;
    for (int c = 0, i = tid; i < S_; i += 256, c++) {
        loc[c] = __half2float(p[i]);
        m = fmaxf(m, loc[c]);
    }
    red[tid] = m;
    __syncthreads();
    for (int s = 128; s > 0; s >>= 1) {
        if (tid < s) red[tid] = fmaxf(red[tid], red[tid + s]);
        __syncthreads();
    }
    m = red[0];
    __syncthreads();
    float sum = 0.f;
    for (int c = 0, i = tid; i < S_; i += 256, c++) {
        float e = expf(loc[c] - m);
        loc[c] = e;
        sum += e;
    }
    red[tid] = sum;
    __syncthreads();
    for (int s = 128; s > 0; s >>= 1) {
        if (tid < s) red[tid] += red[tid + s];
        __syncthreads();
    }
    float inv = 1.0f / red[0];
    for (int c = 0, i = tid; i < S_; i += 256, c++)
        p[i] = __float2half(loc[c] * inv);
}

// ---------------- host helper ----------------
struct TcArgs {
    const __half* A; const __half* Bt;
    float* C; __half* Ch = nullptr;
    int M = 0, N = 0, Kp = 0, epi = 0;
    const float* aux = nullptr;
    int rpb = 0, obatch = 0, ldc = 0;
    int zcount = 1, zdiv = 1;
    size_t zA1 = 0, zA2 = 0, zB1 = 0, zB2 = 0, zC1 = 0, zC2 = 0, zAux = 0, zGv = 0;
    const int* cs = nullptr; const int* pad = nullptr;
    int maskStride = 0; float scale = 1.0f;
    const float* gvec = nullptr; int gstride = 0, gdiv = 1;
    float* Ck = nullptr; float* Cv = nullptr;
    const __half* auxh = nullptr;
};

static void launch_tc(const TcArgs& a) {
    cudaFuncSetAttribute(tc_gemm_kernel, cudaFuncAttributeMaxDynamicSharedMemorySize, TC_SMEM);
    TcP p;
    p.A = a.A; p.Bt = a.Bt; p.C = a.C; p.Ch = a.Ch; p.Ck = a.Ck; p.Cv = a.Cv;
    p.aux = a.aux; p.auxh = a.auxh; p.gvec = a.gvec;
    p.cs = a.cs; p.pad = a.pad;
    p.zA1 = a.zA1; p.zA2 = a.zA2; p.zB1 = a.zB1; p.zB2 = a.zB2;
    p.zC1 = a.zC1; p.zC2 = a.zC2; p.zAux = a.zAux; p.zGv = a.zGv;
    p.zdiv = a.zdiv; p.gstride = a.gstride; p.gdiv = a.gdiv;
    p.maskStride = a.maskStride; p.scale = a.scale;
    p.M = a.M; p.N = a.N; p.Kp = a.Kp; p.epi = a.epi;
    p.rpb = a.rpb ? a.rpb : a.M; p.obatch = a.obatch; p.ldc = a.ldc ? a.ldc : a.N;
    dim3 grid((a.N + 127) / 128, (a.M + 127) / 128, a.zcount);
    tc_gemm_kernel<<<grid, 256, TC_SMEM>>>(p);
}

static void launch_wtrans(const float* W, __half* out, int K, int N,
                          int z = 1, size_t inZ = 0, size_t outZ = 0,
                          cudaStream_t st = 0) {
    dim3 grid(N / 32, K / 64, z);
    wtrans_kernel<<<grid, dim3(32, 8), 0, st>>>(W, out, K, N, inZ, outZ);
}

extern "C" void kernel_launch(void* const* d_in, const int* in_sizes, int n_in,
                              void* d_out, int out_size) {
    const float* x0         = (const float*)d_in[0];
    const float* x1         = (const float*)d_in[1];
    const float* cond1      = (const float*)d_in[2];
    const float* w_q0       = (const float*)d_in[3];
    const float* w_k0       = (const float*)d_in[4];
    const float* w_v0       = (const float*)d_in[5];
    const float* w_o0       = (const float*)d_in[6];
    const float* norm1_w0   = (const float*)d_in[7];
    const float* norm2_w0   = (const float*)d_in[8];
    const float* w_gate0    = (const float*)d_in[9];
    const float* w_up0      = (const float*)d_in[10];
    const float* w_down0    = (const float*)d_in[11];
    const float* w_q1       = (const float*)d_in[12];
    const float* w_k1       = (const float*)d_in[13];
    const float* w_v1       = (const float*)d_in[14];
    const float* w_o1       = (const float*)d_in[15];
    const float* ada_in_w1  = (const float*)d_in[16];
    const float* ada_in_b1  = (const float*)d_in[17];
    const float* ada_post_w1= (const float*)d_in[18];
    const float* ada_post_b1= (const float*)d_in[19];
    const float* w_gate1    = (const float*)d_in[20];
    const float* w_up1      = (const float*)d_in[21];
    const float* w_down1    = (const float*)d_in[22];
    const int*   pad_masks  = (const int*)d_in[23];
    const int*   att_masks  = (const int*)d_in[24];

    float* out0 = (float*)d_out;
    float* out1 = out0 + (size_t)B_ * S1_ * D0_;

    float *modin, *modpost, *q, *k, *v, *r0, *r1;
    int *pos, *cs;
    __half *hc0, *hc1, *qr, *kr, *vt, *ph, *atth, *yc0, *yc1;
    __half *gu0hg, *gu0h, *gu1h2, *gu1h;
    __half *wqkv0t, *wqkv1t, *wo0t, *wg0t, *wu0t, *wd0t, *wo1t, *wgu1t, *wd1t;
    cudaGetSymbolAddress((void**)&modin, g_mod_in);
    cudaGetSymbolAddress((void**)&modpost, g_mod_post);
    cudaGetSymbolAddress((void**)&q, g_q);
    cudaGetSymbolAddress((void**)&k, g_k);
    cudaGetSymbolAddress((void**)&v, g_v);
    cudaGetSymbolAddress((void**)&r0, g_r0);
    cudaGetSymbolAddress((void**)&r1, g_r1);
    cudaGetSymbolAddress((void**)&pos, g_pos);
    cudaGetSymbolAddress((void**)&cs, g_cs);
    cudaGetSymbolAddress((void**)&hc0, g_hc0);
    cudaGetSymbolAddress((void**)&hc1, g_hc1);
    cudaGetSymbolAddress((void**)&qr, g_qr);
    cudaGetSymbolAddress((void**)&kr, g_kr);
    cudaGetSymbolAddress((void**)&vt, g_vt);
    cudaGetSymbolAddress((void**)&ph, g_ph);
    cudaGetSymbolAddress((void**)&atth, g_atth);
    cudaGetSymbolAddress((void**)&yc0, g_yc0);
    cudaGetSymbolAddress((void**)&yc1, g_yc1);
    cudaGetSymbolAddress((void**)&gu0hg, g_gu0hg);
    cudaGetSymbolAddress((void**)&gu0h, g_gu0h);
    cudaGetSymbolAddress((void**)&gu1h2, g_gu1h2);
    cudaGetSymbolAddress((void**)&gu1h, g_gu1h);
    cudaGetSymbolAddress((void**)&wqkv0t, g_wqkv0t);
    cudaGetSymbolAddress((void**)&wqkv1t, g_wqkv1t);
    cudaGetSymbolAddress((void**)&wo0t, g_wo0t);
    cudaGetSymbolAddress((void**)&wg0t, g_wg0t);
    cudaGetSymbolAddress((void**)&wu0t, g_wu0t);
    cudaGetSymbolAddress((void**)&wd0t, g_wd0t);
    cudaGetSymbolAddress((void**)&wo1t, g_wo1t);
    cudaGetSymbolAddress((void**)&wgu1t, g_wgu1t);
    cudaGetSymbolAddress((void**)&wd1t, g_wd1t);

    const int M0 = B_ * S1_;   // 3072
    const int M1 = B_ * S2_;   // 256

    // ---- side stream for weight conversion (created once, outside capture) ----
    static cudaStream_t s2 = nullptr;
    static cudaEvent_t evFork = nullptr, evJoin = nullptr;
    if (!s2) {
        cudaStreamCreate(&s2);
        cudaEventCreateWithFlags(&evFork, cudaEventDisableTiming);
        cudaEventCreateWithFlags(&evJoin, cudaEventDisableTiming);
    }

    // fork: side stream converts the late-consumed weights (o0/gate0/up0/down0/o1/gu1/d1)
    cudaEventRecord(evFork, 0);
    cudaStreamWaitEvent(s2, evFork, 0);
    launch_wtrans(w_o0,    wo0t, H_ * HD_, D0_, 1, 0, 0, s2);
    launch_wtrans(w_gate0, wg0t, D0_, F0_, 1, 0, 0, s2);
    launch_wtrans(w_up0,   wu0t, D0_, F0_, 1, 0, 0, s2);
    launch_wtrans(w_down0, wd0t, F0_, D0_, 1, 0, 0, s2);
    launch_wtrans(w_o1,    wo1t, H_ * HD_, D1_, 1, 0, 0, s2);
    launch_wtrans(w_gate1, wgu1t, D1_, F1_, 1, 0, 0, s2);
    launch_wtrans(w_up1,   wgu1t + (size_t)F1_ * D1_, D1_, F1_, 1, 0, 0, s2);
    launch_wtrans(w_down1, wd1t, F1_, D1_, 1, 0, 0, s2);
    cudaEventRecord(evJoin, s2);

    // main stream: QKV weights (needed immediately)
    launch_wtrans(w_q0, wqkv0t, D0_, H_ * HD_);
    launch_wtrans(w_k0, wqkv0t + (size_t)(H_ * HD_) * D0_, D0_, HD_);
    launch_wtrans(w_v0, wqkv0t + (size_t)(H_ * HD_ + HD_) * D0_, D0_, HD_);
    launch_wtrans(w_q1, wqkv1t, D1_, H_ * HD_);
    launch_wtrans(w_k1, wqkv1t + (size_t)(H_ * HD_) * D1_, D1_, HD_);
    launch_wtrans(w_v1, wqkv1t + (size_t)(H_ * HD_ + HD_) * D1_, D1_, HD_);

    // ---- adaLN modulation + scans ----
    {
        dim3 mg(2 * D1_ / 64, B_);
        mod_kernel<<<mg, 256>>>(cond1, ada_in_w1,   ada_in_b1,   modin,   D1_, 2 * D1_);
        mod_kernel<<<mg, 256>>>(cond1, ada_post_w1, ada_post_b1, modpost, D1_, 2 * D1_);
    }
    scan_kernel<<<1, 32>>>(pad_masks, att_masks, pos, cs);

    // ---- input norms -> fp16 ----
    rmsnorm_kernel<<<M0, 256>>>(x0, hc0, norm1_w0, 0, D0_, S1_);
    rmsnorm_kernel<<<M1, 256>>>(x1, hc1, modin, 2 * D1_, D1_, S2_);

    // ---- fused QKV projections (column-routed, row remap into S=832 layout) ----
    { TcArgs a{hc0, wqkv0t, q, nullptr, M0, NQKV_, D0_, EPI_QKV};
      a.Ck = k; a.Cv = v;
      a.rpb = S1_; a.obatch = S_; launch_tc(a); }
    { TcArgs a{hc1, wqkv1t, q + (size_t)S1_ * H_ * HD_, nullptr, M1, NQKV_, D1_, EPI_QKV};
      a.Ck = k + (size_t)S1_ * HD_; a.Cv = v + (size_t)S1_ * HD_;
      a.rpb = S2_; a.obatch = S_; launch_tc(a); }

    // ---- RoPE (-> fp16) and V transpose (-> fp16) ----
    {
        long nq = (long)B_ * H_ * S_ * 128;
        rope_q_kernel<<<(unsigned)((nq + 255) / 256), 256>>>(q, pos, qr);
        long nk = (long)B_ * S_ * 128;
        rope_k_kernel<<<(unsigned)((nk + 255) / 256), 256>>>(k, pos, kr);
        launch_wtrans(v, vt, S_, HD_, B_, (size_t)S_ * HD_, (size_t)HD_ * S_);
    }

    // ---- scores = Q K^T * scale, masked -> fp16 ph (z = B*H) ----
    { TcArgs a{qr, kr, nullptr, ph, S_, S_, HD_, EPI_SCORES_H};
      a.zcount = B_ * H_; a.zdiv = H_;
      a.zA1 = (size_t)H_ * S_ * HD_; a.zA2 = (size_t)S_ * HD_;
      a.zB1 = (size_t)S_ * HD_;
      a.zC1 = (size_t)H_ * S_ * S_; a.zC2 = (size_t)S_ * S_;
      a.cs = cs; a.pad = pad_masks; a.maskStride = S_; a.scale = 0.0625f;
      launch_tc(a); }

    softmax_h_kernel<<<B_ * H_ * S_, 256>>>(ph);

    // ---- PV (z = B*H) -> atth [B,S,H*HD] fp16 ----
    { TcArgs a{ph, vt, nullptr, atth, S_, HD_, S_, EPI_H};
      a.ldc = H_ * HD_;
      a.zcount = B_ * H_; a.zdiv = H_;
      a.zA1 = (size_t)H_ * S_ * S_; a.zA2 = (size_t)S_ * S_;
      a.zB1 = (size_t)HD_ * S_;
      a.zC1 = (size_t)S_ * H_ * HD_; a.zC2 = (size_t)HD_;
      launch_tc(a); }

    // join: side-stream weight conversions must be done before o-projections / MLPs
    cudaStreamWaitEvent(0, evJoin, 0);

    // ---- output projections (z = B) ----
    { TcArgs a{atth, wo0t, r0, nullptr, S1_, D0_, H_ * HD_, EPI_RES};
      a.aux = x0;
      a.zcount = B_;
      a.zA1 = (size_t)S_ * H_ * HD_; a.zC1 = (size_t)S1_ * D0_; a.zAux = (size_t)S1_ * D0_;
      launch_tc(a); }
    { TcArgs a{atth + (size_t)S1_ * H_ * HD_, wo1t, r1, nullptr, S2_, D1_, H_ * HD_, EPI_RES_GATE};
      a.aux = x1;
      a.zcount = B_;
      a.zA1 = (size_t)S_ * H_ * HD_; a.zC1 = (size_t)S2_ * D1_; a.zAux = (size_t)S2_ * D1_;
      a.gvec = modin + D1_; a.zGv = (size_t)2 * D1_; a.gdiv = S2_; a.gstride = 0;
      launch_tc(a); }

    // ---- post norms -> fp16 ----
    rmsnorm_kernel<<<M0, 256>>>(r0, yc0, norm2_w0, 0, D0_, S1_);
    rmsnorm_kernel<<<M1, 256>>>(r1, yc1, modpost, 2 * D1_, D1_, S2_);

    // ---- MLP stream 0 (gate fp16 -> gelu-mul in up epilogue -> down) ----
    { TcArgs a{yc0, wg0t, nullptr, gu0hg, M0, F0_, D0_, EPI_H}; launch_tc(a); }
    { TcArgs a{yc0, wu0t, nullptr, gu0h, M0, F0_, D0_, EPI_GELUMUL_HH}; a.auxh = gu0hg; launch_tc(a); }
    { TcArgs a{gu0h, wd0t, out0, nullptr, M0, D0_, F0_, EPI_RES}; a.aux = r0; launch_tc(a); }

    // ---- MLP stream 1 (fused gate|up fp16, elementwise, down) ----
    { TcArgs a{yc1, wgu1t, nullptr, gu1h2, M1, 2 * F1_, D1_, EPI_H}; launch_tc(a); }
    {
        long n = (long)M1 * F1_;
        ew_gelumul_kernel<<<(unsigned)((n + 255) / 256), 256>>>(gu1h2, gu1h, M1, F1_);
    }
    { TcArgs a{gu1h, wd1t, out1, nullptr, M1, D1_, F1_, EPI_RES_GATE};
      a.aux = r1;
      a.gvec = modpost + D1_; a.gstride = 2 * D1_; a.gdiv = S2_;
      launch_tc(a); }
}

// round 13
// speedup vs baseline: 4.2525x; 1.0209x over previous
#include <cuda_runtime.h>
#include <cuda_fp16.h>
#include <math.h>
#include <stdint.h>

// ---------------- problem constants ----------------
#define B_   4
#define S1_  768
#define S2_  64
#define S_   832
#define D0_  2048
#define F0_  16384
#define D1_  1024
#define F1_  4096
#define H_   8
#define HD_  256
#define EPS_ 1e-6f
#define MASK_H_  -60000.0f
#define NQKV_ (H_*HD_ + 2*HD_)   // 2560

// ---------------- scratch (device globals) ----------------
__device__ float g_mod_in[B_*2*D1_];
__device__ float g_mod_post[B_*2*D1_];
__device__ float g_q[(size_t)B_*S_*H_*HD_];
__device__ float g_k[B_*S_*HD_];
__device__ float g_v[B_*S_*HD_];
__device__ float g_r0[B_*S1_*D0_];
__device__ float g_r1[B_*S2_*D1_];
__device__ int   g_pos[B_*S_];
__device__ int   g_cs[B_*S_];
// fp16 operands
__device__ __half g_hc0[(size_t)B_*S1_*D0_];
__device__ __half g_hc1[B_*S2_*D1_];
__device__ __half g_qr[(size_t)B_*H_*S_*HD_];
__device__ __half g_kr[B_*S_*HD_];
__device__ __half g_vt[B_*HD_*S_];
__device__ __half g_ph[(size_t)B_*H_*S_*S_];
__device__ __half g_atth[(size_t)B_*S_*H_*HD_];
__device__ __half g_yc0[(size_t)B_*S1_*D0_];
__device__ __half g_yc1[B_*S2_*D1_];
__device__ __half g_gu0hg[(size_t)B_*S1_*F0_];
__device__ __half g_gu0h[(size_t)B_*S1_*F0_];
__device__ __half g_gu1h2[(size_t)B_*S2_*2*F1_];
__device__ __half g_gu1h[B_*S2_*F1_];
// transposed fp16 weights [N, K]
__device__ __half g_wqkv0t[(size_t)NQKV_*2048];
__device__ __half g_wqkv1t[(size_t)NQKV_*1024];
__device__ __half g_wo0t[(size_t)2048*2048];
__device__ __half g_wg0t[(size_t)16384*2048];
__device__ __half g_wu0t[(size_t)16384*2048];
__device__ __half g_wd0t[(size_t)2048*16384];
__device__ __half g_wo1t[(size_t)1024*2048];
__device__ __half g_wgu1t[(size_t)2*4096*1024];
__device__ __half g_wd1t[(size_t)1024*4096];

// ---------------- helpers ----------------
__device__ __forceinline__ float gelu_tanh(float x) {
    float x3 = x * x * x;
    return 0.5f * x * (1.0f + tanhf(0.79788456080286535588f * (x + 0.044715f * x3)));
}
__device__ __forceinline__ uint32_t smem_u32(const void* p) {
    uint32_t a;
    asm("{ .reg .u64 t; cvta.to.shared.u64 t, %1; cvt.u32.u64 %0, t; }" : "=r"(a) : "l"(p));
    return a;
}
#define CP_ASYNC16(sm, gm) \
    asm volatile("cp.async.cg.shared.global [%0], [%1], 16;" :: "r"(sm), "l"(gm))
#define CP_COMMIT() asm volatile("cp.async.commit_group;")
#define CP_WAIT(n)  asm volatile("cp.async.wait_group %0;" :: "n"(n))

__device__ __forceinline__ void ldsm_x4(uint32_t* r, uint32_t addr) {
    asm volatile("ldmatrix.sync.aligned.m8n8.x4.shared.b16 {%0,%1,%2,%3}, [%4];"
                 : "=r"(r[0]), "=r"(r[1]), "=r"(r[2]), "=r"(r[3]) : "r"(addr));
}
__device__ __forceinline__ void mma_f16(float* c, const uint32_t* a, uint32_t b0, uint32_t b1) {
    asm volatile("mma.sync.aligned.m16n8k16.row.col.f32.f16.f16.f32 "
                 "{%0,%1,%2,%3}, {%4,%5,%6,%7}, {%8,%9}, {%0,%1,%2,%3};"
                 : "+f"(c[0]), "+f"(c[1]), "+f"(c[2]), "+f"(c[3])
                 : "r"(a[0]), "r"(a[1]), "r"(a[2]), "r"(a[3]), "r"(b0), "r"(b1));
}
__device__ __forceinline__ uint32_t sw_addr(uint32_t base, int row, int chunk) {
    return base + (uint32_t)(((row << 3) + (chunk ^ (row & 7))) << 4);
}

// ---------------- epilogue modes ----------------
#define EPI_NONE        0
#define EPI_SCORES_H    1
#define EPI_RES         2
#define EPI_RES_GATE    3
#define EPI_H           4
#define EPI_GELUMUL_HH  5
#define EPI_QKV         6

// ---------------- TC fp16 GEMM: C[M,N] = A[M,Kp] * Bt[N,Kp]^T ----------------
struct TcP {
    const __half* A; const __half* Bt;
    float* C; __half* Ch;
    float* Ck; float* Cv;
    const float* aux; const __half* auxh; const float* gvec;
    const int *cs, *pad;
    size_t zA1, zA2, zB1, zB2, zC1, zC2, zAux, zGv;
    int zdiv;
    int gstride, gdiv;
    int maskStride; float scale;
    int M, N, Kp, epi;
    int rpb, obatch, ldc;
};

#define TC_STAGES 3
#define TC_STAGE_BYTES 32768
#define TC_SMEM (TC_STAGES * TC_STAGE_BYTES)

__global__ __launch_bounds__(256) void tc_gemm_kernel(TcP p) {
    extern __shared__ char dsm[];
    uint32_t sbase = smem_u32(dsm);

    int tid  = threadIdx.x;
    int wid  = tid >> 5;
    int lane = tid & 31;
    int wm = wid >> 2;
    int wn = wid & 3;

    int m0 = blockIdx.y * 128;
    int n0 = blockIdx.x * 128;
    int z  = blockIdx.z;
    int zb = z / p.zdiv;
    int zr = z - zb * p.zdiv;

    const __half* Ab = p.A  + (size_t)zb * p.zA1 + (size_t)zr * p.zA2;
    const __half* Bb = p.Bt + (size_t)zb * p.zB1 + (size_t)zr * p.zB2;

    int kc = tid & 7;
    int rb = tid >> 3;

    float acc[4][4][4];
    #pragma unroll
    for (int i = 0; i < 4; i++)
        #pragma unroll
        for (int j = 0; j < 4; j++)
            #pragma unroll
            for (int e = 0; e < 4; e++) acc[i][j][e] = 0.f;

    int nIter = p.Kp >> 6;

    auto issue = [&](int it) {
        int st = it % TC_STAGES;
        uint32_t sa = sbase + st * TC_STAGE_BYTES;
        uint32_t sb = sa + 16384;
        int k0 = it << 6;
        #pragma unroll
        for (int i = 0; i < 4; i++) {
            int row = rb + i * 32;
            int ra = m0 + row; if (ra > p.M - 1) ra = p.M - 1;
            CP_ASYNC16(sw_addr(sa, row, kc), Ab + (size_t)ra * p.Kp + k0 + kc * 8);
            int rn = n0 + row; if (rn > p.N - 1) rn = p.N - 1;
            CP_ASYNC16(sw_addr(sb, row, kc), Bb + (size_t)rn * p.Kp + k0 + kc * 8);
        }
        CP_COMMIT();
    };

    #pragma unroll
    for (int s = 0; s < TC_STAGES - 1; s++) issue(s);

    int grp = lane >> 3;
    int lr  = lane & 7;

    for (int it = 0; it < nIter; it++) {
        if (it + TC_STAGES - 1 < nIter) {
            issue(it + TC_STAGES - 1);
            CP_WAIT(TC_STAGES - 2);
        } else {
            CP_WAIT(0);
        }
        __syncthreads();

        int st = it % TC_STAGES;
        uint32_t sa = sbase + st * TC_STAGE_BYTES;
        uint32_t sb = sa + 16384;

        #pragma unroll
        for (int kb = 0; kb < 4; kb++) {
            int chA = 2 * kb + (grp >> 1);
            uint32_t a[4][4];
            #pragma unroll
            for (int mi = 0; mi < 4; mi++) {
                int row = wm * 64 + mi * 16 + (grp & 1) * 8 + lr;
                ldsm_x4(a[mi], sw_addr(sa, row, chA));
            }
            uint32_t bf[2][4];
            #pragma unroll
            for (int bi = 0; bi < 2; bi++) {
                int row = wn * 32 + bi * 16 + (grp & 1) * 8 + lr;
                ldsm_x4(bf[bi], sw_addr(sb, row, chA));
            }
            #pragma unroll
            for (int mi = 0; mi < 4; mi++)
                #pragma unroll
                for (int ni = 0; ni < 4; ni++) {
                    int bi = ni >> 1, wh = ni & 1;
                    mma_f16(acc[mi][ni], a[mi], bf[bi][wh], bf[bi][wh + 2]);
                }
        }
        __syncthreads();
    }

    // ---- epilogue ----
    const int* csb  = p.cs  ? p.cs  + (size_t)zb * p.maskStride : nullptr;
    const int* padb = p.pad ? p.pad + (size_t)zb * p.maskStride : nullptr;
    const float* auxz = p.aux ? p.aux + (size_t)zb * p.zAux : nullptr;
    const __half* auxhz = p.auxh ? p.auxh + (size_t)zb * p.zAux : nullptr;
    const float* gvz  = p.gvec ? p.gvec + (size_t)zb * p.zGv : nullptr;
    float* Cz = p.C + (size_t)zb * p.zC1 + (size_t)zr * p.zC2;
    __half* Chz = p.Ch + (size_t)zb * p.zC1 + (size_t)zr * p.zC2;
    int qrow = lane >> 2;
    int qcol = (lane & 3) * 2;
    #pragma unroll
    for (int mi = 0; mi < 4; mi++) {
        #pragma unroll
        for (int half_ = 0; half_ < 2; half_++) {
            int r = m0 + wm * 64 + mi * 16 + half_ * 8 + qrow;
            if (r >= p.M) continue;
            int orow = (r / p.rpb) * p.obatch + (r % p.rpb);
            #pragma unroll
            for (int ni = 0; ni < 4; ni++) {
                int col = n0 + wn * 32 + ni * 8 + qcol;
                if (col >= p.N) continue;
                float v0 = acc[mi][ni][half_ * 2 + 0];
                float v1 = acc[mi][ni][half_ * 2 + 1];
                if (p.epi == EPI_QKV) {
                    float2 ov = make_float2(v0, v1);
                    if (col < H_ * HD_)
                        *(float2*)&p.C[(size_t)orow * (H_ * HD_) + col] = ov;
                    else if (col < H_ * HD_ + HD_)
                        *(float2*)&p.Ck[(size_t)orow * HD_ + (col - H_ * HD_)] = ov;
                    else
                        *(float2*)&p.Cv[(size_t)orow * HD_ + (col - H_ * HD_ - HD_)] = ov;
                    continue;
                } else if (p.epi == EPI_H) {
                    __half2 hv; hv.x = __float2half(v0); hv.y = __float2half(v1);
                    *(__half2*)&Chz[(size_t)orow * p.ldc + col] = hv;
                    continue;
                } else if (p.epi == EPI_GELUMUL_HH) {
                    __half2 ah = *(const __half2*)&auxhz[(size_t)r * p.N + col];
                    __half2 hv;
                    hv.x = __float2half(gelu_tanh(__half2float(ah.x)) * v0);
                    hv.y = __float2half(gelu_tanh(__half2float(ah.y)) * v1);
                    *(__half2*)&Chz[(size_t)orow * p.ldc + col] = hv;
                    continue;
                } else if (p.epi == EPI_SCORES_H) {
                    int csr = csb[r];
                    bool okr = padb[r] != 0;
                    bool ok0 = (csb[col] <= csr) && okr && (padb[col] != 0);
                    bool ok1 = (csb[col + 1] <= csr) && okr && (padb[col + 1] != 0);
                    __half2 hv;
                    hv.x = __float2half(ok0 ? v0 * p.scale : MASK_H_);
                    hv.y = __float2half(ok1 ? v1 * p.scale : MASK_H_);
                    *(__half2*)&Chz[(size_t)orow * p.ldc + col] = hv;
                    continue;
                } else if (p.epi == EPI_RES) {
                    float2 ax = *(const float2*)&auxz[(size_t)r * p.N + col];
                    v0 += ax.x; v1 += ax.y;
                } else if (p.epi == EPI_RES_GATE) {
                    float2 ax = *(const float2*)&auxz[(size_t)r * p.N + col];
                    float2 gx = *(const float2*)&gvz[(size_t)(r / p.gdiv) * p.gstride + col];
                    v0 = ax.x + gx.x * v0;
                    v1 = ax.y + gx.y * v1;
                }
                *(float2*)&Cz[(size_t)orow * p.ldc + col] = make_float2(v0, v1);
            }
        }
    }
}

// ---------------- multi-weight transpose fp32 -> fp16 ----------------
#define WT_MAX 8
struct WtEntry { const float* src; __half* dst; int K, N, nx, blkOff; };
struct WtP { WtEntry e[WT_MAX]; int cnt; };

__global__ void wtrans_multi_kernel(WtP p) {
    int bx = blockIdx.x;
    int i = p.cnt - 1;
    while (i > 0 && bx < p.e[i].blkOff) i--;
    WtEntry e = p.e[i];
    int local = bx - e.blkOff;
    int n0 = (local % e.nx) * 32;
    int k0 = (local / e.nx) * 64;

    __shared__ float t[64][33];
    int tx = threadIdx.x, ty = threadIdx.y;   // 32 x 8
    #pragma unroll
    for (int j = 0; j < 8; j++)
        t[ty + j * 8][tx] = e.src[(size_t)(k0 + ty + j * 8) * e.N + n0 + tx];
    __syncthreads();
    #pragma unroll
    for (int j = 0; j < 4; j++) {
        int nl = j * 8 + ty;
        __half2 hv;
        hv.x = __float2half(t[2 * tx][nl]);
        hv.y = __float2half(t[2 * tx + 1][nl]);
        *(__half2*)&e.dst[(size_t)(n0 + nl) * e.K + k0 + 2 * tx] = hv;
    }
}

// batched V transpose (z over B)
__global__ void wtrans_kernel(const float* __restrict__ W, __half* __restrict__ out,
                              int K, int N, size_t inZ, size_t outZ) {
    W   += blockIdx.z * inZ;
    out += blockIdx.z * outZ;
    __shared__ float t[64][33];
    int k0 = blockIdx.y * 64, n0 = blockIdx.x * 32;
    int tx = threadIdx.x, ty = threadIdx.y;
    #pragma unroll
    for (int i = 0; i < 8; i++)
        t[ty + i * 8][tx] = W[(size_t)(k0 + ty + i * 8) * N + n0 + tx];
    __syncthreads();
    #pragma unroll
    for (int j = 0; j < 4; j++) {
        int nl = j * 8 + ty;
        __half2 hv;
        hv.x = __float2half(t[2 * tx][nl]);
        hv.y = __float2half(t[2 * tx + 1][nl]);
        *(__half2*)&out[(size_t)(n0 + nl) * K + k0 + 2 * tx] = hv;
    }
}

// merged RoPE (Q then K ranges) -> fp16
__global__ void rope_qk_kernel(const float* __restrict__ q, const float* __restrict__ k,
                               const int* __restrict__ pos,
                               __half* __restrict__ qr, __half* __restrict__ kr) {
    const long NQ = (long)B_ * H_ * S_ * 128;
    const long NK = (long)B_ * S_ * 128;
    long idx = blockIdx.x * (long)blockDim.x + threadIdx.x;
    if (idx >= NQ + NK) return;
    if (idx < NQ) {
        int i = (int)(idx & 127);
        long t = idx >> 7;
        int s = (int)(t % S_); t /= S_;
        int h = (int)(t % H_);
        int b = (int)(t / H_);
        const float* base = q + ((size_t)(b * S_ + s) * H_ + h) * HD_;
        float x1 = base[i], x2 = base[i + 128];
        float f = (float)pos[b * S_ + s] * expf(-((float)i / 128.0f) * 9.210340371976184f);
        float sn, c; sincosf(f, &sn, &c);
        __half* ob = qr + ((size_t)(b * H_ + h) * S_ + s) * HD_;
        ob[i]       = __float2half(x1 * c - x2 * sn);
        ob[i + 128] = __float2half(x2 * c + x1 * sn);
    } else {
        idx -= NQ;
        int i = (int)(idx & 127);
        long t = idx >> 7;
        int s = (int)(t % S_);
        int b = (int)(t / S_);
        const float* base = k + (size_t)(b * S_ + s) * HD_;
        float x1 = base[i], x2 = base[i + 128];
        float f = (float)pos[b * S_ + s] * expf(-((float)i / 128.0f) * 9.210340371976184f);
        float sn, c; sincosf(f, &sn, &c);
        __half* ob = kr + (size_t)(b * S_ + s) * HD_;
        ob[i]       = __float2half(x1 * c - x2 * sn);
        ob[i + 128] = __float2half(x2 * c + x1 * sn);
    }
}

// elementwise gelu-mul (stream-1 fused gate|up)
__global__ void ew_gelumul_kernel(const __half* __restrict__ gu, __half* __restrict__ out,
                                  int M, int F) {
    long idx = blockIdx.x * (long)blockDim.x + threadIdx.x;
    if (idx >= (long)M * F) return;
    int r = (int)(idx / F), j = (int)(idx % F);
    const __half* g = gu + (size_t)r * 2 * F;
    out[(size_t)r * F + j] =
        __float2half(gelu_tanh(__half2float(g[j])) * __half2float(g[F + j]));
}

// merged mod GEMV: z=0 -> (W0,b0,out0), z=1 -> (W1,b1,out1); k-split x4
__global__ void mod2_kernel(const float* __restrict__ cond,
                            const float* __restrict__ W0, const float* __restrict__ b0, float* __restrict__ o0,
                            const float* __restrict__ W1, const float* __restrict__ b1, float* __restrict__ o1,
                            int D, int N) {
    const float* W = blockIdx.z ? W1 : W0;
    const float* bias = blockIdx.z ? b1 : b0;
    float* out = blockIdx.z ? o1 : o0;
    __shared__ float red[256];
    int tid = threadIdx.x;
    int j = blockIdx.x * 64 + (tid & 63);
    int ks = tid >> 6;
    int b = blockIdx.y;
    const float* c = cond + (size_t)b * D;
    int kseg = D >> 2;
    int kbeg = ks * kseg;
    float s = 0.f;
    for (int kk = kbeg; kk < kbeg + kseg; kk++)
        s += c[kk] * W[(size_t)kk * N + j];
    red[tid] = s;
    __syncthreads();
    if (ks == 0)
        out[(size_t)b * N + j] = bias[j] + red[tid] + red[tid + 64] + red[tid + 128] + red[tid + 192];
}

// ---------------- prefix scans ----------------
__global__ void scan_kernel(const int* __restrict__ pad, const int* __restrict__ att,
                            int* __restrict__ pos, int* __restrict__ cs) {
    int b = threadIdx.x;
    if (b >= B_) return;
    int cp = 0, ca = 0;
    for (int s = 0; s < S_; s++) {
        cp += pad[b * S_ + s];
        ca += att[b * S_ + s];
        pos[b * S_ + s] = cp - 1;
        cs[b * S_ + s] = ca;
    }
}

// ---------------- merged RMSNorm (two tensors, row-routed) -> fp16 ----------------
__global__ void rmsnorm2_kernel(const float* __restrict__ xA, __half* __restrict__ oA,
                                const float* __restrict__ wA, int wsA, int DA, int rpbA, int MA,
                                const float* __restrict__ xB, __half* __restrict__ oB,
                                const float* __restrict__ wB, int wsB, int DB, int rpbB) {
    long row = blockIdx.x;
    const float* xp; __half* op; const float* wp; int D;
    if (row < MA) {
        xp = xA + row * (long)DA; op = oA + row * (long)DA;
        wp = wA + (size_t)(row / rpbA) * wsA; D = DA;
    } else {
        long r2 = row - MA;
        xp = xB + r2 * (long)DB; op = oB + r2 * (long)DB;
        wp = wB + (size_t)(r2 / rpbB) * wsB; D = DB;
    }
    float ss = 0.f;
    for (int i = threadIdx.x; i < D; i += blockDim.x) {
        float v = xp[i];
        ss += v * v;
    }
    __shared__ float red[256];
    red[threadIdx.x] = ss;
    __syncthreads();
    for (int s = 128; s > 0; s >>= 1) {
        if (threadIdx.x < s) red[threadIdx.x] += red[threadIdx.x + s];
        __syncthreads();
    }
    float r = rsqrtf(red[0] / (float)D + EPS_);
    for (int i = threadIdx.x; i < D; i += blockDim.x)
        op[i] = __float2half(xp[i] * r * (1.0f + wp[i]));
}

// ---------------- row softmax on fp16 in-place ----------------
__global__ void softmax_h_kernel(__half* __restrict__ probs) {
    __half* p = probs + (size_t)blockIdx.x * S_;
    __shared__ float red[256];
    int tid = threadIdx.x;
    float loc[4];
    float m = -3.4e38f;
    for (int c = 0, i = tid; i < S_; i += 256, c++) {
        loc[c] = __half2float(p[i]);
        m = fmaxf(m, loc[c]);
    }
    red[tid] = m;
    __syncthreads();
    for (int s = 128; s > 0; s >>= 1) {
        if (tid < s) red[tid] = fmaxf(red[tid], red[tid + s]);
        __syncthreads();
    }
    m = red[0];
    __syncthreads();
    float sum = 0.f;
    for (int c = 0, i = tid; i < S_; i += 256, c++) {
        float e = expf(loc[c] - m);
        loc[c] = e;
        sum += e;
    }
    red[tid] = sum;
    __syncthreads();
    for (int s = 128; s > 0; s >>= 1) {
        if (tid < s) red[tid] += red[tid + s];
        __syncthreads();
    }
    float inv = 1.0f / red[0];
    for (int c = 0, i = tid; i < S_; i += 256, c++)
        p[i] = __float2half(loc[c] * inv);
}

// ---------------- host helper ----------------
struct TcArgs {
    const __half* A; const __half* Bt;
    float* C; __half* Ch = nullptr;
    int M = 0, N = 0, Kp = 0, epi = 0;
    const float* aux = nullptr;
    int rpb = 0, obatch = 0, ldc = 0;
    int zcount = 1, zdiv = 1;
    size_t zA1 = 0, zA2 = 0, zB1 = 0, zB2 = 0, zC1 = 0, zC2 = 0, zAux = 0, zGv = 0;
    const int* cs = nullptr; const int* pad = nullptr;
    int maskStride = 0; float scale = 1.0f;
    const float* gvec = nullptr; int gstride = 0, gdiv = 1;
    float* Ck = nullptr; float* Cv = nullptr;
    const __half* auxh = nullptr;
};

static void launch_tc(const TcArgs& a) {
    cudaFuncSetAttribute(tc_gemm_kernel, cudaFuncAttributeMaxDynamicSharedMemorySize, TC_SMEM);
    TcP p;
    p.A = a.A; p.Bt = a.Bt; p.C = a.C; p.Ch = a.Ch; p.Ck = a.Ck; p.Cv = a.Cv;
    p.aux = a.aux; p.auxh = a.auxh; p.gvec = a.gvec;
    p.cs = a.cs; p.pad = a.pad;
    p.zA1 = a.zA1; p.zA2 = a.zA2; p.zB1 = a.zB1; p.zB2 = a.zB2;
    p.zC1 = a.zC1; p.zC2 = a.zC2; p.zAux = a.zAux; p.zGv = a.zGv;
    p.zdiv = a.zdiv; p.gstride = a.gstride; p.gdiv = a.gdiv;
    p.maskStride = a.maskStride; p.scale = a.scale;
    p.M = a.M; p.N = a.N; p.Kp = a.Kp; p.epi = a.epi;
    p.rpb = a.rpb ? a.rpb : a.M; p.obatch = a.obatch; p.ldc = a.ldc ? a.ldc : a.N;
    dim3 grid((a.N + 127) / 128, (a.M + 127) / 128, a.zcount);
    tc_gemm_kernel<<<grid, 256, TC_SMEM>>>(p);
}

struct WtBuild {
    WtP p;
    int total = 0;
    WtBuild() { p.cnt = 0; }
    void add(const float* src, __half* dst, int K, int N) {
        WtEntry& e = p.e[p.cnt++];
        e.src = src; e.dst = dst; e.K = K; e.N = N;
        e.nx = N / 32;
        e.blkOff = total;
        total += (N / 32) * (K / 64);
    }
    void launch(cudaStream_t st) {
        wtrans_multi_kernel<<<total, dim3(32, 8), 0, st>>>(p);
    }
};

extern "C" void kernel_launch(void* const* d_in, const int* in_sizes, int n_in,
                              void* d_out, int out_size) {
    const float* x0         = (const float*)d_in[0];
    const float* x1         = (const float*)d_in[1];
    const float* cond1      = (const float*)d_in[2];
    const float* w_q0       = (const float*)d_in[3];
    const float* w_k0       = (const float*)d_in[4];
    const float* w_v0       = (const float*)d_in[5];
    const float* w_o0       = (const float*)d_in[6];
    const float* norm1_w0   = (const float*)d_in[7];
    const float* norm2_w0   = (const float*)d_in[8];
    const float* w_gate0    = (const float*)d_in[9];
    const float* w_up0      = (const float*)d_in[10];
    const float* w_down0    = (const float*)d_in[11];
    const float* w_q1       = (const float*)d_in[12];
    const float* w_k1       = (const float*)d_in[13];
    const float* w_v1       = (const float*)d_in[14];
    const float* w_o1       = (const float*)d_in[15];
    const float* ada_in_w1  = (const float*)d_in[16];
    const float* ada_in_b1  = (const float*)d_in[17];
    const float* ada_post_w1= (const float*)d_in[18];
    const float* ada_post_b1= (const float*)d_in[19];
    const float* w_gate1    = (const float*)d_in[20];
    const float* w_up1      = (const float*)d_in[21];
    const float* w_down1    = (const float*)d_in[22];
    const int*   pad_masks  = (const int*)d_in[23];
    const int*   att_masks  = (const int*)d_in[24];

    float* out0 = (float*)d_out;
    float* out1 = out0 + (size_t)B_ * S1_ * D0_;

    float *modin, *modpost, *q, *k, *v, *r0, *r1;
    int *pos, *cs;
    __half *hc0, *hc1, *qr, *kr, *vt, *ph, *atth, *yc0, *yc1;
    __half *gu0hg, *gu0h, *gu1h2, *gu1h;
    __half *wqkv0t, *wqkv1t, *wo0t, *wg0t, *wu0t, *wd0t, *wo1t, *wgu1t, *wd1t;
    cudaGetSymbolAddress((void**)&modin, g_mod_in);
    cudaGetSymbolAddress((void**)&modpost, g_mod_post);
    cudaGetSymbolAddress((void**)&q, g_q);
    cudaGetSymbolAddress((void**)&k, g_k);
    cudaGetSymbolAddress((void**)&v, g_v);
    cudaGetSymbolAddress((void**)&r0, g_r0);
    cudaGetSymbolAddress((void**)&r1, g_r1);
    cudaGetSymbolAddress((void**)&pos, g_pos);
    cudaGetSymbolAddress((void**)&cs, g_cs);
    cudaGetSymbolAddress((void**)&hc0, g_hc0);
    cudaGetSymbolAddress((void**)&hc1, g_hc1);
    cudaGetSymbolAddress((void**)&qr, g_qr);
    cudaGetSymbolAddress((void**)&kr, g_kr);
    cudaGetSymbolAddress((void**)&vt, g_vt);
    cudaGetSymbolAddress((void**)&ph, g_ph);
    cudaGetSymbolAddress((void**)&atth, g_atth);
    cudaGetSymbolAddress((void**)&yc0, g_yc0);
    cudaGetSymbolAddress((void**)&yc1, g_yc1);
    cudaGetSymbolAddress((void**)&gu0hg, g_gu0hg);
    cudaGetSymbolAddress((void**)&gu0h, g_gu0h);
    cudaGetSymbolAddress((void**)&gu1h2, g_gu1h2);
    cudaGetSymbolAddress((void**)&gu1h, g_gu1h);
    cudaGetSymbolAddress((void**)&wqkv0t, g_wqkv0t);
    cudaGetSymbolAddress((void**)&wqkv1t, g_wqkv1t);
    cudaGetSymbolAddress((void**)&wo0t, g_wo0t);
    cudaGetSymbolAddress((void**)&wg0t, g_wg0t);
    cudaGetSymbolAddress((void**)&wu0t, g_wu0t);
    cudaGetSymbolAddress((void**)&wd0t, g_wd0t);
    cudaGetSymbolAddress((void**)&wo1t, g_wo1t);
    cudaGetSymbolAddress((void**)&wgu1t, g_wgu1t);
    cudaGetSymbolAddress((void**)&wd1t, g_wd1t);

    const int M0 = B_ * S1_;   // 3072
    const int M1 = B_ * S2_;   // 256

    // ---- side stream (created once, outside capture) ----
    static cudaStream_t s2 = nullptr;
    static cudaEvent_t evFork = nullptr, evJoin = nullptr;
    if (!s2) {
        cudaStreamCreate(&s2);
        cudaEventCreateWithFlags(&evFork, cudaEventDisableTiming);
        cudaEventCreateWithFlags(&evJoin, cudaEventDisableTiming);
    }

    // fork: ONE merged kernel converts the 8 late-consumed weights on the side stream
    cudaEventRecord(evFork, 0);
    cudaStreamWaitEvent(s2, evFork, 0);
    {
        WtBuild wb;
        wb.add(w_o0,    wo0t, H_ * HD_, D0_);
        wb.add(w_gate0, wg0t, D0_, F0_);
        wb.add(w_up0,   wu0t, D0_, F0_);
        wb.add(w_down0, wd0t, F0_, D0_);
        wb.add(w_o1,    wo1t, H_ * HD_, D1_);
        wb.add(w_gate1, wgu1t, D1_, F1_);
        wb.add(w_up1,   wgu1t + (size_t)F1_ * D1_, D1_, F1_);
        wb.add(w_down1, wd1t, F1_, D1_);
        wb.launch(s2);
    }
    cudaEventRecord(evJoin, s2);

    // main stream: ONE merged kernel for the 6 QKV weights
    {
        WtBuild wb;
        wb.add(w_q0, wqkv0t, D0_, H_ * HD_);
        wb.add(w_k0, wqkv0t + (size_t)(H_ * HD_) * D0_, D0_, HD_);
        wb.add(w_v0, wqkv0t + (size_t)(H_ * HD_ + HD_) * D0_, D0_, HD_);
        wb.add(w_q1, wqkv1t, D1_, H_ * HD_);
        wb.add(w_k1, wqkv1t + (size_t)(H_ * HD_) * D1_, D1_, HD_);
        wb.add(w_v1, wqkv1t + (size_t)(H_ * HD_ + HD_) * D1_, D1_, HD_);
        wb.launch(0);
    }

    // ---- adaLN modulation (merged) + scans ----
    {
        dim3 mg(2 * D1_ / 64, B_, 2);
        mod2_kernel<<<mg, 256>>>(cond1, ada_in_w1, ada_in_b1, modin,
                                 ada_post_w1, ada_post_b1, modpost, D1_, 2 * D1_);
    }
    scan_kernel<<<1, 32>>>(pad_masks, att_masks, pos, cs);

    // ---- input norms (merged) -> fp16 ----
    rmsnorm2_kernel<<<M0 + M1, 256>>>(x0, hc0, norm1_w0, 0, D0_, S1_, M0,
                                      x1, hc1, modin, 2 * D1_, D1_, S2_);

    // ---- fused QKV projections ----
    { TcArgs a{hc0, wqkv0t, q, nullptr, M0, NQKV_, D0_, EPI_QKV};
      a.Ck = k; a.Cv = v;
      a.rpb = S1_; a.obatch = S_; launch_tc(a); }
    { TcArgs a{hc1, wqkv1t, q + (size_t)S1_ * H_ * HD_, nullptr, M1, NQKV_, D1_, EPI_QKV};
      a.Ck = k + (size_t)S1_ * HD_; a.Cv = v + (size_t)S1_ * HD_;
      a.rpb = S2_; a.obatch = S_; launch_tc(a); }

    // ---- merged RoPE + V transpose ----
    {
        long ntot = (long)B_ * H_ * S_ * 128 + (long)B_ * S_ * 128;
        rope_qk_kernel<<<(unsigned)((ntot + 255) / 256), 256>>>(q, k, pos, qr, kr);
        dim3 vg(HD_ / 32, S_ / 64, B_);
        wtrans_kernel<<<vg, dim3(32, 8)>>>(v, vt, S_, HD_, (size_t)S_ * HD_, (size_t)HD_ * S_);
    }

    // ---- scores = Q K^T * scale, masked -> fp16 ph (z = B*H) ----
    { TcArgs a{qr, kr, nullptr, ph, S_, S_, HD_, EPI_SCORES_H};
      a.zcount = B_ * H_; a.zdiv = H_;
      a.zA1 = (size_t)H_ * S_ * HD_; a.zA2 = (size_t)S_ * HD_;
      a.zB1 = (size_t)S_ * HD_;
      a.zC1 = (size_t)H_ * S_ * S_; a.zC2 = (size_t)S_ * S_;
      a.cs = cs; a.pad = pad_masks; a.maskStride = S_; a.scale = 0.0625f;
      launch_tc(a); }

    softmax_h_kernel<<<B_ * H_ * S_, 256>>>(ph);

    // ---- PV (z = B*H) -> atth [B,S,H*HD] fp16 ----
    { TcArgs a{ph, vt, nullptr, atth, S_, HD_, S_, EPI_H};
      a.ldc = H_ * HD_;
      a.zcount = B_ * H_; a.zdiv = H_;
      a.zA1 = (size_t)H_ * S_ * S_; a.zA2 = (size_t)S_ * S_;
      a.zB1 = (size_t)HD_ * S_;
      a.zC1 = (size_t)S_ * H_ * HD_; a.zC2 = (size_t)HD_;
      launch_tc(a); }

    // join: side-stream weight conversions before o-projections / MLPs
    cudaStreamWaitEvent(0, evJoin, 0);

    // ---- output projections (z = B) ----
    { TcArgs a{atth, wo0t, r0, nullptr, S1_, D0_, H_ * HD_, EPI_RES};
      a.aux = x0;
      a.zcount = B_;
      a.zA1 = (size_t)S_ * H_ * HD_; a.zC1 = (size_t)S1_ * D0_; a.zAux = (size_t)S1_ * D0_;
      launch_tc(a); }
    { TcArgs a{atth + (size_t)S1_ * H_ * HD_, wo1t, r1, nullptr, S2_, D1_, H_ * HD_, EPI_RES_GATE};
      a.aux = x1;
      a.zcount = B_;
      a.zA1 = (size_t)S_ * H_ * HD_; a.zC1 = (size_t)S2_ * D1_; a.zAux = (size_t)S2_ * D1_;
      a.gvec = modin + D1_; a.zGv = (size_t)2 * D1_; a.gdiv = S2_; a.gstride = 0;
      launch_tc(a); }

    // ---- post norms (merged) -> fp16 ----
    rmsnorm2_kernel<<<M0 + M1, 256>>>(r0, yc0, norm2_w0, 0, D0_, S1_, M0,
                                      r1, yc1, modpost, 2 * D1_, D1_, S2_);

    // ---- MLP stream 0 ----
    { TcArgs a{yc0, wg0t, nullptr, gu0hg, M0, F0_, D0_, EPI_H}; launch_tc(a); }
    { TcArgs a{yc0, wu0t, nullptr, gu0h, M0, F0_, D0_, EPI_GELUMUL_HH}; a.auxh = gu0hg; launch_tc(a); }
    { TcArgs a{gu0h, wd0t, out0, nullptr, M0, D0_, F0_, EPI_RES}; a.aux = r0; launch_tc(a); }

    // ---- MLP stream 1 ----
    { TcArgs a{yc1, wgu1t, nullptr, gu1h2, M1, 2 * F1_, D1_, EPI_H}; launch_tc(a); }
    {
        long n = (long)M1 * F1_;
        ew_gelumul_kernel<<<(unsigned)((n + 255) / 256), 256>>>(gu1h2, gu1h, M1, F1_);
    }
    { TcArgs a{gu1h, wd1t, out1, nullptr, M1, D1_, F1_, EPI_RES_GATE};
      a.aux = r1;
      a.gvec = modpost + D1_; a.gstride = 2 * D1_; a.gdiv = S2_;
      launch_tc(a); }
}

// round 14
// speedup vs baseline: 4.3198x; 1.0158x over previous
#include <cuda_runtime.h>
#include <cuda_fp16.h>
#include <math.h>
#include <stdint.h>

// ---------------- problem constants ----------------
#define B_   4
#define S1_  768
#define S2_  64
#define S_   832
#define D0_  2048
#define F0_  16384
#define D1_  1024
#define F1_  4096
#define H_   8
#define HD_  256
#define EPS_ 1e-6f
#define MASK_H_  -60000.0f
#define NQKV_ (H_*HD_ + 2*HD_)   // 2560

// ---------------- scratch (device globals) ----------------
__device__ float g_mod_in[B_*2*D1_];
__device__ float g_mod_post[B_*2*D1_];
__device__ float g_q[(size_t)B_*S_*H_*HD_];
__device__ float g_k[B_*S_*HD_];
__device__ float g_v[B_*S_*HD_];
__device__ float g_r0[B_*S1_*D0_];
__device__ float g_r1[B_*S2_*D1_];
__device__ int   g_pos[B_*S_];
__device__ int   g_cs[B_*S_];
// fp16 operands
__device__ __half g_hc0[(size_t)B_*S1_*D0_];
__device__ __half g_hc1[B_*S2_*D1_];
__device__ __half g_qr[(size_t)B_*H_*S_*HD_];
__device__ __half g_kr[B_*S_*HD_];
__device__ __half g_vt[B_*HD_*S_];
__device__ __half g_ph[(size_t)B_*H_*S_*S_];
__device__ __half g_atth[(size_t)B_*S_*H_*HD_];
__device__ __half g_yc0[(size_t)B_*S1_*D0_];
__device__ __half g_yc1[B_*S2_*D1_];
__device__ __half g_gu0hg[(size_t)B_*S1_*F0_];
__device__ __half g_gu0h[(size_t)B_*S1_*F0_];
__device__ __half g_gu1h2[(size_t)B_*S2_*2*F1_];
__device__ __half g_gu1h[B_*S2_*F1_];
// transposed fp16 weights [N, K]
__device__ __half g_wqkv0t[(size_t)NQKV_*2048];
__device__ __half g_wqkv1t[(size_t)NQKV_*1024];
__device__ __half g_wo0t[(size_t)2048*2048];
__device__ __half g_wg0t[(size_t)16384*2048];
__device__ __half g_wu0t[(size_t)16384*2048];
__device__ __half g_wd0t[(size_t)2048*16384];
__device__ __half g_wo1t[(size_t)1024*2048];
__device__ __half g_wgu1t[(size_t)2*4096*1024];
__device__ __half g_wd1t[(size_t)1024*4096];

// ---------------- helpers ----------------
__device__ __forceinline__ float gelu_tanh(float x) {
    float x3 = x * x * x;
    return 0.5f * x * (1.0f + tanhf(0.79788456080286535588f * (x + 0.044715f * x3)));
}
__device__ __forceinline__ uint32_t smem_u32(const void* p) {
    uint32_t a;
    asm("{ .reg .u64 t; cvta.to.shared.u64 t, %1; cvt.u32.u64 %0, t; }" : "=r"(a) : "l"(p));
    return a;
}
#define CP_ASYNC16(sm, gm) \
    asm volatile("cp.async.cg.shared.global [%0], [%1], 16;" :: "r"(sm), "l"(gm))
#define CP_COMMIT() asm volatile("cp.async.commit_group;")
#define CP_WAIT(n)  asm volatile("cp.async.wait_group %0;" :: "n"(n))

__device__ __forceinline__ void ldsm_x4(uint32_t* r, uint32_t addr) {
    asm volatile("ldmatrix.sync.aligned.m8n8.x4.shared.b16 {%0,%1,%2,%3}, [%4];"
                 : "=r"(r[0]), "=r"(r[1]), "=r"(r[2]), "=r"(r[3]) : "r"(addr));
}
__device__ __forceinline__ void mma_f16(float* c, const uint32_t* a, uint32_t b0, uint32_t b1) {
    asm volatile("mma.sync.aligned.m16n8k16.row.col.f32.f16.f16.f32 "
                 "{%0,%1,%2,%3}, {%4,%5,%6,%7}, {%8,%9}, {%0,%1,%2,%3};"
                 : "+f"(c[0]), "+f"(c[1]), "+f"(c[2]), "+f"(c[3])
                 : "r"(a[0]), "r"(a[1]), "r"(a[2]), "r"(a[3]), "r"(b0), "r"(b1));
}
__device__ __forceinline__ uint32_t sw_addr(uint32_t base, int row, int chunk) {
    return base + (uint32_t)(((row << 3) + (chunk ^ (row & 7))) << 4);
}

// ---------------- epilogue modes ----------------
#define EPI_NONE        0
#define EPI_SCORES_H    1
#define EPI_RES         2
#define EPI_RES_GATE    3
#define EPI_H           4
#define EPI_GELUMUL_HH  5
#define EPI_QKV         6

// ---------------- TC fp16 GEMM: C[M,N] = A[M,Kp] * Bt[N,Kp]^T ----------------
struct TcP {
    const __half* A; const __half* Bt;
    float* C; __half* Ch;
    float* Ck; float* Cv;
    const float* aux; const __half* auxh; const float* gvec;
    const int *cs, *pad;
    size_t zA1, zA2, zB1, zB2, zC1, zC2, zAux, zGv;
    int zdiv;
    int gstride, gdiv;
    int maskStride; float scale;
    int M, N, Kp, epi;
    int rpb, obatch, ldc;
};

#define TC_STAGES 3
#define TC_STAGE_BYTES 32768
#define TC_SMEM (TC_STAGES * TC_STAGE_BYTES)

__global__ __launch_bounds__(256) void tc_gemm_kernel(TcP p) {
    extern __shared__ char dsm[];
    uint32_t sbase = smem_u32(dsm);

    int tid  = threadIdx.x;
    int wid  = tid >> 5;
    int lane = tid & 31;
    int wm = wid >> 2;
    int wn = wid & 3;

    int m0 = blockIdx.y * 128;
    int n0 = blockIdx.x * 128;
    int z  = blockIdx.z;
    int zb = z / p.zdiv;
    int zr = z - zb * p.zdiv;

    const __half* Ab = p.A  + (size_t)zb * p.zA1 + (size_t)zr * p.zA2;
    const __half* Bb = p.Bt + (size_t)zb * p.zB1 + (size_t)zr * p.zB2;

    int kc = tid & 7;
    int rb = tid >> 3;

    float acc[4][4][4];
    #pragma unroll
    for (int i = 0; i < 4; i++)
        #pragma unroll
        for (int j = 0; j < 4; j++)
            #pragma unroll
            for (int e = 0; e < 4; e++) acc[i][j][e] = 0.f;

    int nIter = p.Kp >> 6;

    auto issue = [&](int it) {
        int st = it % TC_STAGES;
        uint32_t sa = sbase + st * TC_STAGE_BYTES;
        uint32_t sb = sa + 16384;
        int k0 = it << 6;
        #pragma unroll
        for (int i = 0; i < 4; i++) {
            int row = rb + i * 32;
            int ra = m0 + row; if (ra > p.M - 1) ra = p.M - 1;
            CP_ASYNC16(sw_addr(sa, row, kc), Ab + (size_t)ra * p.Kp + k0 + kc * 8);
            int rn = n0 + row; if (rn > p.N - 1) rn = p.N - 1;
            CP_ASYNC16(sw_addr(sb, row, kc), Bb + (size_t)rn * p.Kp + k0 + kc * 8);
        }
        CP_COMMIT();
    };

    #pragma unroll
    for (int s = 0; s < TC_STAGES - 1; s++) issue(s);

    int grp = lane >> 3;
    int lr  = lane & 7;

    for (int it = 0; it < nIter; it++) {
        if (it + TC_STAGES - 1 < nIter) {
            issue(it + TC_STAGES - 1);
            CP_WAIT(TC_STAGES - 2);
        } else {
            CP_WAIT(0);
        }
        __syncthreads();

        int st = it % TC_STAGES;
        uint32_t sa = sbase + st * TC_STAGE_BYTES;
        uint32_t sb = sa + 16384;

        #pragma unroll
        for (int kb = 0; kb < 4; kb++) {
            int chA = 2 * kb + (grp >> 1);
            uint32_t a[4][4];
            #pragma unroll
            for (int mi = 0; mi < 4; mi++) {
                int row = wm * 64 + mi * 16 + (grp & 1) * 8 + lr;
                ldsm_x4(a[mi], sw_addr(sa, row, chA));
            }
            uint32_t bf[2][4];
            #pragma unroll
            for (int bi = 0; bi < 2; bi++) {
                int row = wn * 32 + bi * 16 + (grp & 1) * 8 + lr;
                ldsm_x4(bf[bi], sw_addr(sb, row, chA));
            }
            #pragma unroll
            for (int mi = 0; mi < 4; mi++)
                #pragma unroll
                for (int ni = 0; ni < 4; ni++) {
                    int bi = ni >> 1, wh = ni & 1;
                    mma_f16(acc[mi][ni], a[mi], bf[bi][wh], bf[bi][wh + 2]);
                }
        }
        __syncthreads();
    }

    // ---- epilogue ----
    const int* csb  = p.cs  ? p.cs  + (size_t)zb * p.maskStride : nullptr;
    const int* padb = p.pad ? p.pad + (size_t)zb * p.maskStride : nullptr;
    const float* auxz = p.aux ? p.aux + (size_t)zb * p.zAux : nullptr;
    const __half* auxhz = p.auxh ? p.auxh + (size_t)zb * p.zAux : nullptr;
    const float* gvz  = p.gvec ? p.gvec + (size_t)zb * p.zGv : nullptr;
    float* Cz = p.C + (size_t)zb * p.zC1 + (size_t)zr * p.zC2;
    __half* Chz = p.Ch + (size_t)zb * p.zC1 + (size_t)zr * p.zC2;
    int qrow = lane >> 2;
    int qcol = (lane & 3) * 2;
    #pragma unroll
    for (int mi = 0; mi < 4; mi++) {
        #pragma unroll
        for (int half_ = 0; half_ < 2; half_++) {
            int r = m0 + wm * 64 + mi * 16 + half_ * 8 + qrow;
            if (r >= p.M) continue;
            int orow = (r / p.rpb) * p.obatch + (r % p.rpb);
            #pragma unroll
            for (int ni = 0; ni < 4; ni++) {
                int col = n0 + wn * 32 + ni * 8 + qcol;
                if (col >= p.N) continue;
                float v0 = acc[mi][ni][half_ * 2 + 0];
                float v1 = acc[mi][ni][half_ * 2 + 1];
                if (p.epi == EPI_QKV) {
                    float2 ov = make_float2(v0, v1);
                    if (col < H_ * HD_)
                        *(float2*)&p.C[(size_t)orow * (H_ * HD_) + col] = ov;
                    else if (col < H_ * HD_ + HD_)
                        *(float2*)&p.Ck[(size_t)orow * HD_ + (col - H_ * HD_)] = ov;
                    else
                        *(float2*)&p.Cv[(size_t)orow * HD_ + (col - H_ * HD_ - HD_)] = ov;
                    continue;
                } else if (p.epi == EPI_H) {
                    __half2 hv; hv.x = __float2half(v0); hv.y = __float2half(v1);
                    *(__half2*)&Chz[(size_t)orow * p.ldc + col] = hv;
                    continue;
                } else if (p.epi == EPI_GELUMUL_HH) {
                    __half2 ah = *(const __half2*)&auxhz[(size_t)r * p.N + col];
                    __half2 hv;
                    hv.x = __float2half(gelu_tanh(__half2float(ah.x)) * v0);
                    hv.y = __float2half(gelu_tanh(__half2float(ah.y)) * v1);
                    *(__half2*)&Chz[(size_t)orow * p.ldc + col] = hv;
                    continue;
                } else if (p.epi == EPI_SCORES_H) {
                    int csr = csb[r];
                    bool okr = padb[r] != 0;
                    bool ok0 = (csb[col] <= csr) && okr && (padb[col] != 0);
                    bool ok1 = (csb[col + 1] <= csr) && okr && (padb[col + 1] != 0);
                    __half2 hv;
                    hv.x = __float2half(ok0 ? v0 * p.scale : MASK_H_);
                    hv.y = __float2half(ok1 ? v1 * p.scale : MASK_H_);
                    *(__half2*)&Chz[(size_t)orow * p.ldc + col] = hv;
                    continue;
                } else if (p.epi == EPI_RES) {
                    float2 ax = *(const float2*)&auxz[(size_t)r * p.N + col];
                    v0 += ax.x; v1 += ax.y;
                } else if (p.epi == EPI_RES_GATE) {
                    float2 ax = *(const float2*)&auxz[(size_t)r * p.N + col];
                    float2 gx = *(const float2*)&gvz[(size_t)(r / p.gdiv) * p.gstride + col];
                    v0 = ax.x + gx.x * v0;
                    v1 = ax.y + gx.y * v1;
                }
                *(float2*)&Cz[(size_t)orow * p.ldc + col] = make_float2(v0, v1);
            }
        }
    }
}

// ---------------- multi-weight transpose fp32 -> fp16 ----------------
#define WT_MAX 8
struct WtEntry { const float* src; __half* dst; int K, N, nx, blkOff; };
struct WtP { WtEntry e[WT_MAX]; int cnt; };

__global__ void wtrans_multi_kernel(WtP p) {
    int bx = blockIdx.x;
    int i = p.cnt - 1;
    while (i > 0 && bx < p.e[i].blkOff) i--;
    WtEntry e = p.e[i];
    int local = bx - e.blkOff;
    int n0 = (local % e.nx) * 32;
    int k0 = (local / e.nx) * 64;

    __shared__ float t[64][33];
    int tx = threadIdx.x, ty = threadIdx.y;   // 32 x 8
    #pragma unroll
    for (int j = 0; j < 8; j++)
        t[ty + j * 8][tx] = e.src[(size_t)(k0 + ty + j * 8) * e.N + n0 + tx];
    __syncthreads();
    #pragma unroll
    for (int j = 0; j < 4; j++) {
        int nl = j * 8 + ty;
        __half2 hv;
        hv.x = __float2half(t[2 * tx][nl]);
        hv.y = __float2half(t[2 * tx + 1][nl]);
        *(__half2*)&e.dst[(size_t)(n0 + nl) * e.K + k0 + 2 * tx] = hv;
    }
}

// batched V transpose (z over B)
__global__ void wtrans_kernel(const float* __restrict__ W, __half* __restrict__ out,
                              int K, int N, size_t inZ, size_t outZ) {
    W   += blockIdx.z * inZ;
    out += blockIdx.z * outZ;
    __shared__ float t[64][33];
    int k0 = blockIdx.y * 64, n0 = blockIdx.x * 32;
    int tx = threadIdx.x, ty = threadIdx.y;
    #pragma unroll
    for (int i = 0; i < 8; i++)
        t[ty + i * 8][tx] = W[(size_t)(k0 + ty + i * 8) * N + n0 + tx];
    __syncthreads();
    #pragma unroll
    for (int j = 0; j < 4; j++) {
        int nl = j * 8 + ty;
        __half2 hv;
        hv.x = __float2half(t[2 * tx][nl]);
        hv.y = __float2half(t[2 * tx + 1][nl]);
        *(__half2*)&out[(size_t)(n0 + nl) * K + k0 + 2 * tx] = hv;
    }
}

// merged RoPE (Q then K ranges) -> fp16
__global__ void rope_qk_kernel(const float* __restrict__ q, const float* __restrict__ k,
                               const int* __restrict__ pos,
                               __half* __restrict__ qr, __half* __restrict__ kr) {
    const long NQ = (long)B_ * H_ * S_ * 128;
    const long NK = (long)B_ * S_ * 128;
    long idx = blockIdx.x * (long)blockDim.x + threadIdx.x;
    if (idx >= NQ + NK) return;
    if (idx < NQ) {
        int i = (int)(idx & 127);
        long t = idx >> 7;
        int s = (int)(t % S_); t /= S_;
        int h = (int)(t % H_);
        int b = (int)(t / H_);
        const float* base = q + ((size_t)(b * S_ + s) * H_ + h) * HD_;
        float x1 = base[i], x2 = base[i + 128];
        float f = (float)pos[b * S_ + s] * expf(-((float)i / 128.0f) * 9.210340371976184f);
        float sn, c; sincosf(f, &sn, &c);
        __half* ob = qr + ((size_t)(b * H_ + h) * S_ + s) * HD_;
        ob[i]       = __float2half(x1 * c - x2 * sn);
        ob[i + 128] = __float2half(x2 * c + x1 * sn);
    } else {
        idx -= NQ;
        int i = (int)(idx & 127);
        long t = idx >> 7;
        int s = (int)(t % S_);
        int b = (int)(t / S_);
        const float* base = k + (size_t)(b * S_ + s) * HD_;
        float x1 = base[i], x2 = base[i + 128];
        float f = (float)pos[b * S_ + s] * expf(-((float)i / 128.0f) * 9.210340371976184f);
        float sn, c; sincosf(f, &sn, &c);
        __half* ob = kr + (size_t)(b * S_ + s) * HD_;
        ob[i]       = __float2half(x1 * c - x2 * sn);
        ob[i + 128] = __float2half(x2 * c + x1 * sn);
    }
}

// elementwise gelu-mul (stream-1 fused gate|up)
__global__ void ew_gelumul_kernel(const __half* __restrict__ gu, __half* __restrict__ out,
                                  int M, int F) {
    long idx = blockIdx.x * (long)blockDim.x + threadIdx.x;
    if (idx >= (long)M * F) return;
    int r = (int)(idx / F), j = (int)(idx % F);
    const __half* g = gu + (size_t)r * 2 * F;
    out[(size_t)r * F + j] =
        __float2half(gelu_tanh(__half2float(g[j])) * __half2float(g[F + j]));
}

// merged mod GEMV: z=0 -> (W0,b0,out0), z=1 -> (W1,b1,out1); k-split x4
__global__ void mod2_kernel(const float* __restrict__ cond,
                            const float* __restrict__ W0, const float* __restrict__ b0, float* __restrict__ o0,
                            const float* __restrict__ W1, const float* __restrict__ b1, float* __restrict__ o1,
                            int D, int N) {
    const float* W = blockIdx.z ? W1 : W0;
    const float* bias = blockIdx.z ? b1 : b0;
    float* out = blockIdx.z ? o1 : o0;
    __shared__ float red[256];
    int tid = threadIdx.x;
    int j = blockIdx.x * 64 + (tid & 63);
    int ks = tid >> 6;
    int b = blockIdx.y;
    const float* c = cond + (size_t)b * D;
    int kseg = D >> 2;
    int kbeg = ks * kseg;
    float s = 0.f;
    for (int kk = kbeg; kk < kbeg + kseg; kk++)
        s += c[kk] * W[(size_t)kk * N + j];
    red[tid] = s;
    __syncthreads();
    if (ks == 0)
        out[(size_t)b * N + j] = bias[j] + red[tid] + red[tid + 64] + red[tid + 128] + red[tid + 192];
}

// ---------------- parallel prefix scan (block per batch, Hillis-Steele) ----------------
__global__ void scan_par_kernel(const int* __restrict__ pad, const int* __restrict__ att,
                                int* __restrict__ pos, int* __restrict__ cs) {
    __shared__ int sp[1024];
    __shared__ int sa[1024];
    int b = blockIdx.x;
    int t = threadIdx.x;
    int vp = 0, va = 0;
    if (t < S_) {
        vp = pad[b * S_ + t];
        va = att[b * S_ + t];
    }
    sp[t] = vp; sa[t] = va;
    __syncthreads();
    #pragma unroll
    for (int off = 1; off < 1024; off <<= 1) {
        int ap = 0, aa = 0;
        if (t >= off) { ap = sp[t - off]; aa = sa[t - off]; }
        __syncthreads();
        sp[t] += ap; sa[t] += aa;
        __syncthreads();
    }
    if (t < S_) {
        pos[b * S_ + t] = sp[t] - 1;
        cs[b * S_ + t] = sa[t];
    }
}

// ---------------- merged RMSNorm (two tensors, row-routed) -> fp16 ----------------
__global__ void rmsnorm2_kernel(const float* __restrict__ xA, __half* __restrict__ oA,
                                const float* __restrict__ wA, int wsA, int DA, int rpbA, int MA,
                                const float* __restrict__ xB, __half* __restrict__ oB,
                                const float* __restrict__ wB, int wsB, int DB, int rpbB) {
    long row = blockIdx.x;
    const float* xp; __half* op; const float* wp; int D;
    if (row < MA) {
        xp = xA + row * (long)DA; op = oA + row * (long)DA;
        wp = wA + (size_t)(row / rpbA) * wsA; D = DA;
    } else {
        long r2 = row - MA;
        xp = xB + r2 * (long)DB; op = oB + r2 * (long)DB;
        wp = wB + (size_t)(r2 / rpbB) * wsB; D = DB;
    }
    float ss = 0.f;
    for (int i = threadIdx.x; i < D; i += blockDim.x) {
        float v = xp[i];
        ss += v * v;
    }
    __shared__ float red[256];
    red[threadIdx.x] = ss;
    __syncthreads();
    for (int s = 128; s > 0; s >>= 1) {
        if (threadIdx.x < s) red[threadIdx.x] += red[threadIdx.x + s];
        __syncthreads();
    }
    float r = rsqrtf(red[0] / (float)D + EPS_);
    for (int i = threadIdx.x; i < D; i += blockDim.x)
        op[i] = __float2half(xp[i] * r * (1.0f + wp[i]));
}

// ---------------- row softmax on fp16 in-place ----------------
__global__ void softmax_h_kernel(__half* __restrict__ probs) {
    __half* p = probs + (size_t)blockIdx.x * S_;
    __shared__ float red[256];
    int tid = threadIdx.x;
    float loc[4];
    float m = -3.4e38f;
    for (int c = 0, i = tid; i < S_; i += 256, c++) {
        loc[c] = __half2float(p[i]);
        m = fmaxf(m, loc[c]);
    }
    red[tid] = m;
    __syncthreads();
    for (int s = 128; s > 0; s >>= 1) {
        if (tid < s) red[tid] = fmaxf(red[tid], red[tid + s]);
        __syncthreads();
    }
    m = red[0];
    __syncthreads();
    float sum = 0.f;
    for (int c = 0, i = tid; i < S_; i += 256, c++) {
        float e = expf(loc[c] - m);
        loc[c] = e;
        sum += e;
    }
    red[tid] = sum;
    __syncthreads();
    for (int s = 128; s > 0; s >>= 1) {
        if (tid < s) red[tid] += red[tid + s];
        __syncthreads();
    }
    float inv = 1.0f / red[0];
    for (int c = 0, i = tid; i < S_; i += 256, c++)
        p[i] = __float2half(loc[c] * inv);
}

// ---------------- host helper ----------------
struct TcArgs {
    const __half* A; const __half* Bt;
    float* C; __half* Ch = nullptr;
    int M = 0, N = 0, Kp = 0, epi = 0;
    const float* aux = nullptr;
    int rpb = 0, obatch = 0, ldc = 0;
    int zcount = 1, zdiv = 1;
    size_t zA1 = 0, zA2 = 0, zB1 = 0, zB2 = 0, zC1 = 0, zC2 = 0, zAux = 0, zGv = 0;
    const int* cs = nullptr; const int* pad = nullptr;
    int maskStride = 0; float scale = 1.0f;
    const float* gvec = nullptr; int gstride = 0, gdiv = 1;
    float* Ck = nullptr; float* Cv = nullptr;
    const __half* auxh = nullptr;
};

static void launch_tc(const TcArgs& a) {
    cudaFuncSetAttribute(tc_gemm_kernel, cudaFuncAttributeMaxDynamicSharedMemorySize, TC_SMEM);
    TcP p;
    p.A = a.A; p.Bt = a.Bt; p.C = a.C; p.Ch = a.Ch; p.Ck = a.Ck; p.Cv = a.Cv;
    p.aux = a.aux; p.auxh = a.auxh; p.gvec = a.gvec;
    p.cs = a.cs; p.pad = a.pad;
    p.zA1 = a.zA1; p.zA2 = a.zA2; p.zB1 = a.zB1; p.zB2 = a.zB2;
    p.zC1 = a.zC1; p.zC2 = a.zC2; p.zAux = a.zAux; p.zGv = a.zGv;
    p.zdiv = a.zdiv; p.gstride = a.gstride; p.gdiv = a.gdiv;
    p.maskStride = a.maskStride; p.scale = a.scale;
    p.M = a.M; p.N = a.N; p.Kp = a.Kp; p.epi = a.epi;
    p.rpb = a.rpb ? a.rpb : a.M; p.obatch = a.obatch; p.ldc = a.ldc ? a.ldc : a.N;
    dim3 grid((a.N + 127) / 128, (a.M + 127) / 128, a.zcount);
    tc_gemm_kernel<<<grid, 256, TC_SMEM>>>(p);
}

struct WtBuild {
    WtP p;
    int total = 0;
    WtBuild() { p.cnt = 0; }
    void add(const float* src, __half* dst, int K, int N) {
        WtEntry& e = p.e[p.cnt++];
        e.src = src; e.dst = dst; e.K = K; e.N = N;
        e.nx = N / 32;
        e.blkOff = total;
        total += (N / 32) * (K / 64);
    }
    void launch(cudaStream_t st) {
        wtrans_multi_kernel<<<total, dim3(32, 8), 0, st>>>(p);
    }
};

extern "C" void kernel_launch(void* const* d_in, const int* in_sizes, int n_in,
                              void* d_out, int out_size) {
    const float* x0         = (const float*)d_in[0];
    const float* x1         = (const float*)d_in[1];
    const float* cond1      = (const float*)d_in[2];
    const float* w_q0       = (const float*)d_in[3];
    const float* w_k0       = (const float*)d_in[4];
    const float* w_v0       = (const float*)d_in[5];
    const float* w_o0       = (const float*)d_in[6];
    const float* norm1_w0   = (const float*)d_in[7];
    const float* norm2_w0   = (const float*)d_in[8];
    const float* w_gate0    = (const float*)d_in[9];
    const float* w_up0      = (const float*)d_in[10];
    const float* w_down0    = (const float*)d_in[11];
    const float* w_q1       = (const float*)d_in[12];
    const float* w_k1       = (const float*)d_in[13];
    const float* w_v1       = (const float*)d_in[14];
    const float* w_o1       = (const float*)d_in[15];
    const float* ada_in_w1  = (const float*)d_in[16];
    const float* ada_in_b1  = (const float*)d_in[17];
    const float* ada_post_w1= (const float*)d_in[18];
    const float* ada_post_b1= (const float*)d_in[19];
    const float* w_gate1    = (const float*)d_in[20];
    const float* w_up1      = (const float*)d_in[21];
    const float* w_down1    = (const float*)d_in[22];
    const int*   pad_masks  = (const int*)d_in[23];
    const int*   att_masks  = (const int*)d_in[24];

    float* out0 = (float*)d_out;
    float* out1 = out0 + (size_t)B_ * S1_ * D0_;

    float *modin, *modpost, *q, *k, *v, *r0, *r1;
    int *pos, *cs;
    __half *hc0, *hc1, *qr, *kr, *vt, *ph, *atth, *yc0, *yc1;
    __half *gu0hg, *gu0h, *gu1h2, *gu1h;
    __half *wqkv0t, *wqkv1t, *wo0t, *wg0t, *wu0t, *wd0t, *wo1t, *wgu1t, *wd1t;
    cudaGetSymbolAddress((void**)&modin, g_mod_in);
    cudaGetSymbolAddress((void**)&modpost, g_mod_post);
    cudaGetSymbolAddress((void**)&q, g_q);
    cudaGetSymbolAddress((void**)&k, g_k);
    cudaGetSymbolAddress((void**)&v, g_v);
    cudaGetSymbolAddress((void**)&r0, g_r0);
    cudaGetSymbolAddress((void**)&r1, g_r1);
    cudaGetSymbolAddress((void**)&pos, g_pos);
    cudaGetSymbolAddress((void**)&cs, g_cs);
    cudaGetSymbolAddress((void**)&hc0, g_hc0);
    cudaGetSymbolAddress((void**)&hc1, g_hc1);
    cudaGetSymbolAddress((void**)&qr, g_qr);
    cudaGetSymbolAddress((void**)&kr, g_kr);
    cudaGetSymbolAddress((void**)&vt, g_vt);
    cudaGetSymbolAddress((void**)&ph, g_ph);
    cudaGetSymbolAddress((void**)&atth, g_atth);
    cudaGetSymbolAddress((void**)&yc0, g_yc0);
    cudaGetSymbolAddress((void**)&yc1, g_yc1);
    cudaGetSymbolAddress((void**)&gu0hg, g_gu0hg);
    cudaGetSymbolAddress((void**)&gu0h, g_gu0h);
    cudaGetSymbolAddress((void**)&gu1h2, g_gu1h2);
    cudaGetSymbolAddress((void**)&gu1h, g_gu1h);
    cudaGetSymbolAddress((void**)&wqkv0t, g_wqkv0t);
    cudaGetSymbolAddress((void**)&wqkv1t, g_wqkv1t);
    cudaGetSymbolAddress((void**)&wo0t, g_wo0t);
    cudaGetSymbolAddress((void**)&wg0t, g_wg0t);
    cudaGetSymbolAddress((void**)&wu0t, g_wu0t);
    cudaGetSymbolAddress((void**)&wd0t, g_wd0t);
    cudaGetSymbolAddress((void**)&wo1t, g_wo1t);
    cudaGetSymbolAddress((void**)&wgu1t, g_wgu1t);
    cudaGetSymbolAddress((void**)&wd1t, g_wd1t);

    const int M0 = B_ * S1_;   // 3072
    const int M1 = B_ * S2_;   // 256

    // ---- side stream (created once, outside capture) ----
    static cudaStream_t s2 = nullptr;
    static cudaEvent_t evFork = nullptr, evJoin = nullptr;
    if (!s2) {
        cudaStreamCreate(&s2);
        cudaEventCreateWithFlags(&evFork, cudaEventDisableTiming);
        cudaEventCreateWithFlags(&evJoin, cudaEventDisableTiming);
    }

    // fork: ONE merged kernel converts the 8 late-consumed weights on the side stream
    cudaEventRecord(evFork, 0);
    cudaStreamWaitEvent(s2, evFork, 0);
    {
        WtBuild wb;
        wb.add(w_o0,    wo0t, H_ * HD_, D0_);
        wb.add(w_gate0, wg0t, D0_, F0_);
        wb.add(w_up0,   wu0t, D0_, F0_);
        wb.add(w_down0, wd0t, F0_, D0_);
        wb.add(w_o1,    wo1t, H_ * HD_, D1_);
        wb.add(w_gate1, wgu1t, D1_, F1_);
        wb.add(w_up1,   wgu1t + (size_t)F1_ * D1_, D1_, F1_);
        wb.add(w_down1, wd1t, F1_, D1_);
        wb.launch(s2);
    }
    cudaEventRecord(evJoin, s2);

    // main stream: ONE merged kernel for the 6 QKV weights
    {
        WtBuild wb;
        wb.add(w_q0, wqkv0t, D0_, H_ * HD_);
        wb.add(w_k0, wqkv0t + (size_t)(H_ * HD_) * D0_, D0_, HD_);
        wb.add(w_v0, wqkv0t + (size_t)(H_ * HD_ + HD_) * D0_, D0_, HD_);
        wb.add(w_q1, wqkv1t, D1_, H_ * HD_);
        wb.add(w_k1, wqkv1t + (size_t)(H_ * HD_) * D1_, D1_, HD_);
        wb.add(w_v1, wqkv1t + (size_t)(H_ * HD_ + HD_) * D1_, D1_, HD_);
        wb.launch(0);
    }

    // ---- adaLN modulation (merged) + parallel scans ----
    {
        dim3 mg(2 * D1_ / 64, B_, 2);
        mod2_kernel<<<mg, 256>>>(cond1, ada_in_w1, ada_in_b1, modin,
                                 ada_post_w1, ada_post_b1, modpost, D1_, 2 * D1_);
    }
    scan_par_kernel<<<B_, 1024>>>(pad_masks, att_masks, pos, cs);

    // ---- input norms (merged) -> fp16 ----
    rmsnorm2_kernel<<<M0 + M1, 256>>>(x0, hc0, norm1_w0, 0, D0_, S1_, M0,
                                      x1, hc1, modin, 2 * D1_, D1_, S2_);

    // ---- fused QKV projections ----
    { TcArgs a{hc0, wqkv0t, q, nullptr, M0, NQKV_, D0_, EPI_QKV};
      a.Ck = k; a.Cv = v;
      a.rpb = S1_; a.obatch = S_; launch_tc(a); }
    { TcArgs a{hc1, wqkv1t, q + (size_t)S1_ * H_ * HD_, nullptr, M1, NQKV_, D1_, EPI_QKV};
      a.Ck = k + (size_t)S1_ * HD_; a.Cv = v + (size_t)S1_ * HD_;
      a.rpb = S2_; a.obatch = S_; launch_tc(a); }

    // ---- merged RoPE + V transpose ----
    {
        long ntot = (long)B_ * H_ * S_ * 128 + (long)B_ * S_ * 128;
        rope_qk_kernel<<<(unsigned)((ntot + 255) / 256), 256>>>(q, k, pos, qr, kr);
        dim3 vg(HD_ / 32, S_ / 64, B_);
        wtrans_kernel<<<vg, dim3(32, 8)>>>(v, vt, S_, HD_, (size_t)S_ * HD_, (size_t)HD_ * S_);
    }

    // ---- scores = Q K^T * scale, masked -> fp16 ph (z = B*H) ----
    { TcArgs a{qr, kr, nullptr, ph, S_, S_, HD_, EPI_SCORES_H};
      a.zcount = B_ * H_; a.zdiv = H_;
      a.zA1 = (size_t)H_ * S_ * HD_; a.zA2 = (size_t)S_ * HD_;
      a.zB1 = (size_t)S_ * HD_;
      a.zC1 = (size_t)H_ * S_ * S_; a.zC2 = (size_t)S_ * S_;
      a.cs = cs; a.pad = pad_masks; a.maskStride = S_; a.scale = 0.0625f;
      launch_tc(a); }

    softmax_h_kernel<<<B_ * H_ * S_, 256>>>(ph);

    // ---- PV (z = B*H) -> atth [B,S,H*HD] fp16 ----
    { TcArgs a{ph, vt, nullptr, atth, S_, HD_, S_, EPI_H};
      a.ldc = H_ * HD_;
      a.zcount = B_ * H_; a.zdiv = H_;
      a.zA1 = (size_t)H_ * S_ * S_; a.zA2 = (size_t)S_ * S_;
      a.zB1 = (size_t)HD_ * S_;
      a.zC1 = (size_t)S_ * H_ * HD_; a.zC2 = (size_t)HD_;
      launch_tc(a); }

    // join: side-stream weight conversions before o-projections / MLPs
    cudaStreamWaitEvent(0, evJoin, 0);

    // ---- output projections (z = B) ----
    { TcArgs a{atth, wo0t, r0, nullptr, S1_, D0_, H_ * HD_, EPI_RES};
      a.aux = x0;
      a.zcount = B_;
      a.zA1 = (size_t)S_ * H_ * HD_; a.zC1 = (size_t)S1_ * D0_; a.zAux = (size_t)S1_ * D0_;
      launch_tc(a); }
    { TcArgs a{atth + (size_t)S1_ * H_ * HD_, wo1t, r1, nullptr, S2_, D1_, H_ * HD_, EPI_RES_GATE};
      a.aux = x1;
      a.zcount = B_;
      a.zA1 = (size_t)S_ * H_ * HD_; a.zC1 = (size_t)S2_ * D1_; a.zAux = (size_t)S2_ * D1_;
      a.gvec = modin + D1_; a.zGv = (size_t)2 * D1_; a.gdiv = S2_; a.gstride = 0;
      launch_tc(a); }

    // ---- post norms (merged) -> fp16 ----
    rmsnorm2_kernel<<<M0 + M1, 256>>>(r0, yc0, norm2_w0, 0, D0_, S1_, M0,
                                      r1, yc1, modpost, 2 * D1_, D1_, S2_);

    // ---- MLP stream 0 ----
    { TcArgs a{yc0, wg0t, nullptr, gu0hg, M0, F0_, D0_, EPI_H}; launch_tc(a); }
    { TcArgs a{yc0, wu0t, nullptr, gu0h, M0, F0_, D0_, EPI_GELUMUL_HH}; a.auxh = gu0hg; launch_tc(a); }
    { TcArgs a{gu0h, wd0t, out0, nullptr, M0, D0_, F0_, EPI_RES}; a.aux = r0; launch_tc(a); }

    // ---- MLP stream 1 ----
    { TcArgs a{yc1, wgu1t, nullptr, gu1h2, M1, 2 * F1_, D1_, EPI_H}; launch_tc(a); }
    {
        long n = (long)M1 * F1_;
        ew_gelumul_kernel<<<(unsigned)((n + 255) / 256), 256>>>(gu1h2, gu1h, M1, F1_);
    }
    { TcArgs a{gu1h, wd1t, out1, nullptr, M1, D1_, F1_, EPI_RES_GATE};
      a.aux = r1;
      a.gvec = modpost + D1_; a.gstride = 2 * D1_; a.gdiv = S2_;
      launch_tc(a); }
}